// round 9
// baseline (speedup 1.0000x reference)
#include <cuda_runtime.h>
#include <math.h>

#define HH 384
#define WW 384
#define NPIX (HH*WW)          // 147456
#define BB 2
#define BN (BB*NPIX)          // 294912
#define NDIR 128
#define EMB 32
#define SELG 16
#define GTY 24

// ======================= scratch buffers =======================
__device__ float g_E[BN];
__device__ float g_S[BN];
__device__ float g_Lp[BN];
__device__ float g_zb[BN];
__device__ float g_Ra[2*BN];     // [(b*2+k)*NPIX+n]
__device__ float g_DM[BN];
__device__ float g_t0[2*BN], g_t1[2*BN], g_t2[2*BN];
__device__ float g_lla[2*BN];
__device__ float g_den[2*BN];
__device__ float g_gld[2*BN];
__device__ float g_La[BN];
__device__ unsigned char g_idxb[BN];
__device__ unsigned g_jh[8*6*2048];     // cooperative select histograms

// ======================= small state =======================
__device__ float    g_sv[64];
__device__ unsigned g_mm[BB][2] = {{0xFFFFFFFFu,0u},{0xFFFFFFFFu,0u}};
__device__ double   g_reg[BB][5];
__device__ double   g_beta[BB][2];
__device__ double   g_cacc[BB][9];
__device__ double   g_mean3[BB][3];
__device__ double   g_wwh[BB][9];
__device__ float    g_cdir[BB*NDIR*3];
__device__ float    g_cbest[BB][3];
__device__ double   g_dirm[BB][NDIR][4];
__device__ double   g_emacc2[9][BB][6];
__device__ double   g_clacc[BB][2][10];
__device__ double   g_clmu[BB][2][3];
__device__ double   g_clinv[BB][2][9];
__device__ double   g_ghist[BB][2][32];
__device__ float    g_gcdf[BB][2][32];
__device__ double   g_esinv[BB][6];

// grid-wide barrier (monotonic generation; arrive self-resets)
__device__ int g_barArrive = 0;
__device__ int g_barGen = 0;

static __device__ __forceinline__ void gridBarrier(int nb){
    __threadfence();
    __syncthreads();
    if(threadIdx.x==0){
        int gen = *(volatile int*)&g_barGen;
        if(atomicAdd(&g_barArrive,1)==nb-1){
            g_barArrive = 0;
            __threadfence();
            *(volatile int*)&g_barGen = gen+1;
        } else {
            while(*(volatile int*)&g_barGen == gen) { }
        }
    }
    __syncthreads();
}

static __device__ __forceinline__ double vloadd(const double* p){ return *(volatile const double*)p; }
static __device__ __forceinline__ float  vloadf(const float* p){ return *(volatile const float*)p; }

// ======================= helpers =======================
static __device__ __forceinline__ unsigned f2u(float f){
    unsigned u = __float_as_uint(f);
    return (u & 0x80000000u) ? ~u : (u | 0x80000000u);
}
static __device__ __forceinline__ float u2f(unsigned u){
    unsigned v = (u & 0x80000000u) ? (u & 0x7FFFFFFFu) : ~u;
    return __uint_as_float(v);
}
static __device__ __forceinline__ float softplusf(float x){
    float t = log1pf(expf(-fabsf(x)));
    return x >= 0.f ? x + t : t;
}
static __device__ double blockReduceD(double v){
    __shared__ double sh[32];
    int lane = threadIdx.x & 31, wid = threadIdx.x >> 5;
    for (int o=16;o;o>>=1) v += __shfl_down_sync(0xffffffffu, v, o);
    if (lane==0) sh[wid] = v;
    __syncthreads();
    int nw = (blockDim.x + 31) >> 5;
    v = (threadIdx.x < nw) ? sh[threadIdx.x] : 0.0;
    if (wid==0) for (int o=16;o;o>>=1) v += __shfl_down_sync(0xffffffffu, v, o);
    __syncthreads();
    return v;
}
static __device__ void eigh3(const double* A, double* e, double* V){
    double a[9]; for(int i=0;i<9;i++) a[i]=A[i];
    for(int i=0;i<9;i++) V[i] = (i%4==0)?1.0:0.0;
    for(int sweep=0;sweep<40;sweep++){
        double off = fabs(a[1])+fabs(a[2])+fabs(a[5]);
        if(off < 1e-300) break;
        for(int p=0;p<2;p++) for(int q=p+1;q<3;q++){
            double apq=a[p*3+q];
            if(fabs(apq) < 1e-300) continue;
            double app=a[p*3+p], aqq=a[q*3+q];
            double th=(aqq-app)/(2.0*apq);
            double t=(th>=0?1.0:-1.0)/(fabs(th)+sqrt(th*th+1.0));
            double c=1.0/sqrt(t*t+1.0), s=t*c;
            for(int i=0;i<3;i++){ double x=a[i*3+p],y=a[i*3+q]; a[i*3+p]=c*x-s*y; a[i*3+q]=s*x+c*y; }
            for(int i=0;i<3;i++){ double x=a[p*3+i],y=a[q*3+i]; a[p*3+i]=c*x-s*y; a[q*3+i]=s*x+c*y; }
            for(int i=0;i<3;i++){ double x=V[i*3+p],y=V[i*3+q]; V[i*3+p]=c*x-s*y; V[i*3+q]=s*x+c*y; }
        }
    }
    e[0]=a[0]; e[1]=a[4]; e[2]=a[8];
}
static __device__ void inv3(const double* m, double* inv){
    double a=m[0],b=m[1],c=m[2],d=m[3],e=m[4],f=m[5],g=m[6],h=m[7],i=m[8];
    double A=e*i-f*h, B=c*h-b*i, C=b*f-c*e;
    double D=f*g-d*i, E=a*i-c*g, F=c*d-a*f;
    double G=d*h-e*g, Hh=b*g-a*h, I=a*e-b*d;
    double det=a*A+b*D+c*G, id=1.0/det;
    inv[0]=A*id; inv[1]=B*id; inv[2]=C*id;
    inv[3]=D*id; inv[4]=E*id; inv[5]=F*id;
    inv[6]=G*id; inv[7]=Hh*id; inv[8]=I*id;
}

// ======================= cooperative radix select =======================
// jobs: {kind, type, b, rank, slotA, slotB}
__device__ const int g_seljobs[22*6] = {
 0,0,0,73727,0,6,   0,1,0,73727,1,7,   0,2,0,73727,2,8,
 0,0,1,73727,3,9,   0,1,1,73727,4,10,  0,2,1,73727,5,11,
 1,3,0,36863,12,13,  1,3,0,110591,14,15,  1,3,1,36863,16,17,  1,3,1,110591,18,19,
 0,4,0,73727,20,24,  0,5,0,73727,21,25,  0,4,1,73727,22,26,  0,5,1,73727,23,27,
 0,6,0,73727,28,32,  0,7,0,73727,29,33,  0,6,1,73727,30,34,  0,7,1,73727,31,35,
 1,8,0,1474,36,37,  1,8,0,145980,38,39,  1,8,1,1474,40,41,  1,8,1,145980,42,43
};

static __device__ const float* selSrc(int type, int b){
    switch(type){
        case 0: return g_Lp + b*NPIX;
        case 1: return g_E  + b*NPIX;
        case 2: return g_S  + b*NPIX;
        case 3: return g_zb + b*NPIX;
        case 4: return g_lla + (b*2+0)*NPIX;
        case 5: return g_lla + (b*2+1)*NPIX;
        case 6: return g_gld + (b*2+0)*NPIX;
        case 7: return g_gld + (b*2+1)*NPIX;
        default: return g_La + b*NPIX;
    }
}

static __device__ void coopZero(int njobs, int nbTot){
    int total = njobs*6*2048;
    for(int i=blockIdx.x*blockDim.x+threadIdx.x; i<total; i+=nbTot*blockDim.x)
        g_jh[i]=0u;
}

// 3-pass (11/11/10 bit) cooperative select across SELG blocks per job.
static __device__ float coopSel(const float4* __restrict__ src4, float ref, int useAbs, unsigned rank,
                                int jobLocal, int passBase, int chunk, int nbTot){
    __shared__ unsigned sh[2048];
    __shared__ unsigned sres[2];
    unsigned pref=0, rk=rank;
    for(int pass=0; pass<3; pass++){
        unsigned* hist = g_jh + (jobLocal*6+passBase+pass)*2048;
        int nbin = (pass==2)?1024:2048;
        for(int i=threadIdx.x;i<nbin;i+=blockDim.x) sh[i]=0u;
        __syncthreads();
        int per = (NPIX/4)/SELG;      // 2304
        int lo = chunk*per;
        for(int i=lo+threadIdx.x;i<lo+per;i+=blockDim.x){
            float4 v4 = src4[i];
            float vv[4]={v4.x,v4.y,v4.z,v4.w};
            #pragma unroll
            for(int c=0;c<4;c++){
                float v=vv[c]; if(useAbs) v=fabsf(v-ref);
                unsigned key=f2u(v);
                if(pass==0) atomicAdd(&sh[key>>21],1u);
                else if(pass==1){ if((key>>21)==(pref>>21)) atomicAdd(&sh[(key>>10)&2047u],1u); }
                else { if((key>>10)==(pref>>10)) atomicAdd(&sh[key&1023u],1u); }
            }
        }
        __syncthreads();
        for(int i=threadIdx.x;i<nbin;i+=blockDim.x) if(sh[i]) atomicAdd(&hist[i],sh[i]);
        gridBarrier(nbTot);
        if(threadIdx.x<32){
            int lane=threadIdx.x, perl=nbin>>5;
            unsigned s=0;
            for(int i=0;i<perl;i++) s+=hist[lane*perl+i];
            unsigned cum=s;
            #pragma unroll
            for(int o=1;o<32;o<<=1){ unsigned t=__shfl_up_sync(0xffffffffu,cum,o); if(lane>=o) cum+=t; }
            unsigned prev=cum-s;
            if(prev<=rk && rk<cum){
                unsigned rr=rk-prev; int bin=lane*perl;
                for(int i=0;i<perl;i++){ unsigned c=hist[lane*perl+i]; if(rr<c){ bin=lane*perl+i; break;} rr-=c; }
                sres[0]=(pass==0)? ((unsigned)bin<<21) : (pass==1)? (pref|((unsigned)bin<<10)) : (pref|(unsigned)bin);
                sres[1]=rr;
            }
        }
        __syncthreads();
        pref=sres[0]; rk=sres[1];
        __syncthreads();
    }
    return u2f(pref);
}

__global__ void __launch_bounds__(1024,1) selCoop(int jobBase, int njobs){
    int nbTot = njobs*SELG;
    int job = blockIdx.x/SELG, chunk = blockIdx.x%SELG;
    coopZero(njobs, nbTot);
    gridBarrier(nbTot);
    const int* jb = &g_seljobs[(jobBase+job)*6];
    const float4* src = (const float4*)selSrc(jb[1], jb[2]);
    if(jb[0]==0){
        float med = coopSel(src,0.f,0,(unsigned)jb[3],job,0,chunk,nbTot);
        if(chunk==0&&threadIdx.x==0) g_sv[jb[4]]=med;
        float mad = coopSel(src,med,1,(unsigned)jb[3],job,3,chunk,nbTot);
        if(chunk==0&&threadIdx.x==0) g_sv[jb[5]]=mad;
    } else {
        float v0 = coopSel(src,0.f,0,(unsigned)jb[3],job,0,chunk,nbTot);
        if(chunk==0&&threadIdx.x==0) g_sv[jb[4]]=v0;
        float v1 = coopSel(src,0.f,0,(unsigned)jb[3]+1u,job,3,chunk,nbTot);
        if(chunk==0&&threadIdx.x==0) g_sv[jb[5]]=v1;
    }
}

// ======================= pipeline kernels =======================
// fused Sobel + avg3 + regression accumulation, tiled in shared memory
__global__ void __launch_bounds__(256) kSobelE(const float* __restrict__ lab){
    __shared__ float sL[20][20];
    __shared__ float sP[18][18];
    int b = blockIdx.z;
    int x0 = blockIdx.x*16, y0 = blockIdx.y*16;
    int tid = threadIdx.x;
    int tx = tid & 15, ty = tid >> 4;
    const float* L = lab + (size_t)b*3*NPIX;
    for(int i=tid;i<400;i+=256){
        int jj=i/20, ii=i%20;
        int yy=y0-2+jj, xx=x0-2+ii;
        sL[jj][ii] = (yy>=0&&yy<HH&&xx>=0&&xx<WW) ? L[yy*WW+xx] : 0.f;
    }
    __syncthreads();
    for(int i=tid;i<324;i+=256){
        int jj=i/18, ii=i%18;
        int py=y0-1+jj, px=x0-1+ii;
        float v=0.f;
        if(py>=0&&py<HH&&px>=0&&px<WW){
            float l00=sL[jj][ii],   l01=sL[jj][ii+1],   l02=sL[jj][ii+2];
            float l10=sL[jj+1][ii],                     l12=sL[jj+1][ii+2];
            float l20=sL[jj+2][ii], l21=sL[jj+2][ii+1], l22=sL[jj+2][ii+2];
            float gx = -l00 + l02 - 2.f*l10 + 2.f*l12 - l20 + l22;
            float gy = -l00 - 2.f*l01 - l02 + l20 + 2.f*l21 + l22;
            v = gx*gx + gy*gy;
        }
        sP[jj][ii]=v;
    }
    __syncthreads();
    int y=y0+ty, x=x0+tx;
    int p = y*WW+x, idx = b*NPIX+p;
    float s = sP[ty][tx]  +sP[ty][tx+1]  +sP[ty][tx+2]
            + sP[ty+1][tx]+sP[ty+1][tx+1]+sP[ty+1][tx+2]
            + sP[ty+2][tx]+sP[ty+2][tx+1]+sP[ty+2][tx+2];
    float E = s/9.f;
    float av = L[NPIX+p], bv = L[2*NPIX+p];
    float S = sqrtf(av*av+bv*bv+1e-8f);
    g_E[idx]=E; g_S[idx]=S;
    double e=E, sv=S, l=L[p];
    double r;
    r=blockReduceD(e*e);  if(tid==0) atomicAdd(&g_reg[b][0],r);
    r=blockReduceD(e*sv); if(tid==0) atomicAdd(&g_reg[b][1],r);
    r=blockReduceD(sv*sv);if(tid==0) atomicAdd(&g_reg[b][2],r);
    r=blockReduceD(e*l);  if(tid==0) atomicAdd(&g_reg[b][3],r);
    r=blockReduceD(sv*l); if(tid==0) atomicAdd(&g_reg[b][4],r);
}

__global__ void kSolve(){
    int b = threadIdx.x; if(b>=BB) return;
    double ee=g_reg[b][0]+1e-6, es=g_reg[b][1], ss=g_reg[b][2]+1e-6;
    double el=g_reg[b][3], sl=g_reg[b][4];
    double det = ee*ss - es*es;
    g_beta[b][0] = (ss*el - es*sl)/det;
    g_beta[b][1] = (ee*sl - es*el)/det;
    for(int i=0;i<5;i++) g_reg[b][i]=0.0;
}

__global__ void kLperp(const float* __restrict__ lab, float* __restrict__ out){
    int idx = blockIdx.x*blockDim.x + threadIdx.x;
    int b = idx / NPIX, p = idx % NPIX;
    float v = lab[(size_t)b*3*NPIX+p] - (float)g_beta[b][0]*g_E[idx] - (float)g_beta[b][1]*g_S[idx];
    g_Lp[idx] = v;
    out[idx] = v;   // output #1
    unsigned k = f2u(v);
    __shared__ unsigned smn[256], smx[256];
    smn[threadIdx.x]=k; smx[threadIdx.x]=k;
    __syncthreads();
    for(int o=128;o>0;o>>=1){
        if(threadIdx.x<o){ smn[threadIdx.x]=min(smn[threadIdx.x],smn[threadIdx.x+o]);
                           smx[threadIdx.x]=max(smx[threadIdx.x],smx[threadIdx.x+o]); }
        __syncthreads();
    }
    if(threadIdx.x==0){ atomicMin(&g_mm[b][0],smn[0]); atomicMax(&g_mm[b][1],smx[0]); }
}

// robust-z cov + eigh + whitening + ES inverse + whitened directions
__global__ void kCovEighCdir(const float* __restrict__ arand){
    int b = blockIdx.x >> 5, chunk = blockIdx.x & 31;
    float md[3], sd[3];
    for(int f=0;f<3;f++){ md[f]=g_sv[b*3+f]; sd[f]=g_sv[6+b*3+f]*1.4826f+1e-8f; }
    double a[9]={0,0,0,0,0,0,0,0,0};
    int per = NPIX/32;
    int lo = chunk*per, hi = lo+per;
    for(int p=lo+threadIdx.x;p<hi;p+=blockDim.x){
        float z0=(g_Lp[b*NPIX+p]-md[0])/sd[0];
        float z1=(g_E [b*NPIX+p]-md[1])/sd[1];
        float z2=(g_S [b*NPIX+p]-md[2])/sd[2];
        a[0]+=z0; a[1]+=z1; a[2]+=z2;
        a[3]+=(double)z0*z0; a[4]+=(double)z0*z1; a[5]+=(double)z0*z2;
        a[6]+=(double)z1*z1; a[7]+=(double)z1*z2; a[8]+=(double)z2*z2;
    }
    for(int m=0;m<9;m++){ double r=blockReduceD(a[m]); if(threadIdx.x==0) atomicAdd(&g_cacc[b][m],r); }
    gridBarrier(64);
    if(blockIdx.x==0){
        int t = threadIdx.x;
        if(t<BB){
            int bb = t;
            double N = (double)NPIX;
            double mu[3]; for(int i=0;i<3;i++){ mu[i]=vloadd(&g_cacc[bb][i])/N; g_mean3[bb][i]=mu[i]; }
            double C[9];
            C[0]=vloadd(&g_cacc[bb][3])/N-mu[0]*mu[0]; C[1]=vloadd(&g_cacc[bb][4])/N-mu[0]*mu[1]; C[2]=vloadd(&g_cacc[bb][5])/N-mu[0]*mu[2];
            C[4]=vloadd(&g_cacc[bb][6])/N-mu[1]*mu[1]; C[5]=vloadd(&g_cacc[bb][7])/N-mu[1]*mu[2]; C[8]=vloadd(&g_cacc[bb][8])/N-mu[2]*mu[2];
            C[3]=C[1]; C[6]=C[2]; C[7]=C[5];
            {
                double c00=C[4]+1e-6, c01=C[5], c11=C[8]+1e-6;
                double det=c00*c11-c01*c01;
                g_esinv[bb][0]=c11/det; g_esinv[bb][1]=-c01/det; g_esinv[bb][2]=c00/det;
                g_esinv[bb][3]=mu[1]; g_esinv[bb][4]=mu[2];
            }
            for(int i=0;i<9;i++) C[i] = C[i] > 1e-8 ? C[i] : 1e-8;
            double e[3], V[9];
            eigh3(C, e, V);
            for(int i=0;i<3;i++) for(int j=0;j<3;j++){
                double ssum=0; for(int k2=0;k2<3;k2++) ssum += V[i*3+k2]*(1.0/sqrt(e[k2]))*V[j*3+k2];
                g_wwh[bb][i*3+j]=ssum;
            }
            for(int i=0;i<9;i++) g_cacc[bb][i]=0.0;
        }
        __syncthreads();
        if(t < BB*NDIR){
            int bb = t / NDIR, d = t % NDIR;
            float a0=arand[(bb*NDIR+d)*3+0], a1=arand[(bb*NDIR+d)*3+1], a2=arand[(bb*NDIR+d)*3+2];
            float nr = sqrtf(a0*a0+a1*a1+a2*a2) + 1e-12f;
            double an[3]={a0/nr,a1/nr,a2/nr};
            for(int jj=0;jj<3;jj++){
                double ssum=0; for(int i=0;i<3;i++) ssum += g_wwh[bb][jj*3+i]*an[i];
                g_cdir[(bb*NDIR+d)*3+jj]=(float)ssum;
            }
        }
    }
}

// kurtosis moments: pixels in registers, all 128 dirs per block
__global__ void __launch_bounds__(256) kKurtAcc(){
    int b = blockIdx.y, chunk = blockIdx.x;
    __shared__ float scd[NDIR*3];
    __shared__ float sacc[NDIR*4];
    for(int i=threadIdx.x;i<NDIR*3;i+=256) scd[i]=g_cdir[b*NDIR*3+i];
    for(int i=threadIdx.x;i<NDIR*4;i+=256) sacc[i]=0.f;
    float md[3], sd[3], mn[3];
    for(int f=0;f<3;f++){ md[f]=g_sv[b*3+f]; sd[f]=g_sv[6+b*3+f]*1.4826f+1e-8f; mn[f]=(float)g_mean3[b][f]; }
    int base = b*NPIX + chunk*(NPIX/64);
    float d0[9], d1[9], d2[9];
    #pragma unroll
    for(int i=0;i<9;i++){
        int p = base + i*256 + threadIdx.x;
        d0[i]=(g_Lp[p]-md[0])/sd[0]-mn[0];
        d1[i]=(g_E [p]-md[1])/sd[1]-mn[1];
        d2[i]=(g_S [p]-md[2])/sd[2]-mn[2];
    }
    __syncthreads();
    int lane = threadIdx.x & 31;
    for(int d=0;d<NDIR;d++){
        float c0=scd[d*3], c1=scd[d*3+1], c2=scd[d*3+2];
        float s1=0,s2=0,s3=0,s4=0;
        #pragma unroll
        for(int i=0;i<9;i++){
            float z=d0[i]*c0+d1[i]*c1+d2[i]*c2;
            float z2=z*z;
            s1+=z; s2+=z2; s3+=z2*z; s4+=z2*z2;
        }
        for(int o=16;o;o>>=1){
            s1+=__shfl_down_sync(0xffffffffu,s1,o); s2+=__shfl_down_sync(0xffffffffu,s2,o);
            s3+=__shfl_down_sync(0xffffffffu,s3,o); s4+=__shfl_down_sync(0xffffffffu,s4,o);
        }
        if(lane==0){
            atomicAdd(&sacc[d*4+0],s1); atomicAdd(&sacc[d*4+1],s2);
            atomicAdd(&sacc[d*4+2],s3); atomicAdd(&sacc[d*4+3],s4);
        }
    }
    __syncthreads();
    for(int i=threadIdx.x;i<NDIR*4;i+=256)
        atomicAdd(&((double*)g_dirm)[b*NDIR*4+i], (double)sacc[i]);
}

__global__ void kKurtPick(){
    int b = threadIdx.x; if(b>=BB) return;
    double N=(double)NPIX, bestv=-1.0; int best=0;
    for(int d=0;d<NDIR;d++){
        double m1=g_dirm[b][d][0]/N, s2=g_dirm[b][d][1]/N, s3=g_dirm[b][d][2]/N, s4=g_dirm[b][d][3]/N;
        double m2=(s2-m1*m1)+1e-12;
        double m4=s4-4.0*m1*s3+6.0*m1*m1*s2-3.0*m1*m1*m1*m1;
        double kurt=fabs(m4/(m2*m2)-3.0);
        if(kurt>bestv){bestv=kurt;best=d;}
    }
    for(int j=0;j<3;j++) g_cbest[b][j]=g_cdir[(b*NDIR+best)*3+j];
    for(int d=0;d<NDIR;d++) for(int m=0;m<4;m++) g_dirm[b][d][m]=0.0;
}

// phase Z: compute zb inline, then cooperative quartile-bracket selects
__global__ void __launch_bounds__(1024,1) kPhaseZ(){
    int nbTot = 4*SELG;   // 64
    int job = blockIdx.x/SELG, chunk = blockIdx.x%SELG;
    int per = BN/64;      // 4608
    int lo = blockIdx.x*per;
    for(int idx=lo+threadIdx.x; idx<lo+per; idx+=blockDim.x){
        int b = idx / NPIX;
        float md0=g_sv[b*3+0], md1=g_sv[b*3+1], md2=g_sv[b*3+2];
        float sd0=g_sv[6+b*3+0]*1.4826f+1e-8f, sd1=g_sv[6+b*3+1]*1.4826f+1e-8f, sd2=g_sv[6+b*3+2]*1.4826f+1e-8f;
        float d0=(g_Lp[idx]-md0)/sd0-(float)g_mean3[b][0];
        float d1=(g_E [idx]-md1)/sd1-(float)g_mean3[b][1];
        float d2=(g_S [idx]-md2)/sd2-(float)g_mean3[b][2];
        g_zb[idx] = d0*g_cbest[b][0]+d1*g_cbest[b][1]+d2*g_cbest[b][2];
    }
    coopZero(4, nbTot);
    gridBarrier(nbTot);
    const int* jb = &g_seljobs[(6+job)*6];
    const float4* src = (const float4*)selSrc(jb[1], jb[2]);
    float v0 = coopSel(src,0.f,0,(unsigned)jb[3],job,0,chunk,nbTot);
    if(chunk==0&&threadIdx.x==0) g_sv[jb[4]]=v0;
    float v1 = coopSel(src,0.f,0,(unsigned)jb[3]+1u,job,3,chunk,nbTot);
    if(chunk==0&&threadIdx.x==0) g_sv[jb[5]]=v1;
}

// persistent EM: per-iteration accumulator slots (1 barrier/iter), zb in registers
__global__ void __launch_bounds__(1024,1) kEM(){
    int blk = blockIdx.x;
    int b = blk >> 4, sub = blk & 15;
    const float* zb = g_zb + b*NPIX;
    float x[9];
    int base = sub*(NPIX/16) + threadIdx.x;
    #pragma unroll
    for(int i=0;i<9;i++) x[i] = zb[base + i*1024];
    {
        double* acc = (double*)g_emacc2;
        int tot = 9*BB*6;
        for(int i=blk*blockDim.x+threadIdx.x; i<tot; i+=EMB*blockDim.x) acc[i]=0.0;
    }
    float q25 = g_sv[12+4*b] + 0.75f*(g_sv[13+4*b]-g_sv[12+4*b]);
    float q75 = g_sv[14+4*b] + 0.25f*(g_sv[15+4*b]-g_sv[14+4*b]);
    double mu0=q25, mu1=q75, var0=1.0, var1=1.0, pi0=0.5, pi1=0.5;
    gridBarrier(EMB);
    for(int it=0; it<9; it++){
        float m0=(float)mu0, m1=(float)mu1;
        float v0=(float)var0+1e-6f, v1=(float)var1+1e-6f;
        float lw0=-0.5f*logf(v0)+logf((float)pi0+1e-8f);
        float lw1=-0.5f*logf(v1)+logf((float)pi1+1e-8f);
        float iv0=0.5f/v0, iv1=0.5f/v1;
        float a0=0,a1=0,a2=0,a3=0,a4=0,a5=0;
        #pragma unroll
        for(int i=0;i<9;i++){
            float xx=x[i];
            float lp0=-(xx-m0)*(xx-m0)*iv0+lw0;
            float lp1=-(xx-m1)*(xx-m1)*iv1+lw1;
            float R0=1.f/(1.f+expf(lp1-lp0));
            float R1=1.f/(1.f+expf(lp0-lp1));
            a0+=R0; a1+=R0*xx; a2+=R0*xx*xx;
            a3+=R1; a4+=R1*xx; a5+=R1*xx*xx;
        }
        double s[6]={a0,a1,a2,a3,a4,a5};
        for(int m=0;m<6;m++){
            double r=blockReduceD(s[m]);
            if(threadIdx.x==0) atomicAdd(&g_emacc2[it][b][m],r);
        }
        gridBarrier(EMB);
        {
            double Sr0=vloadd(&g_emacc2[it][b][0]), Sx0=vloadd(&g_emacc2[it][b][1]), Sxx0=vloadd(&g_emacc2[it][b][2]);
            double Sr1=vloadd(&g_emacc2[it][b][3]), Sx1=vloadd(&g_emacc2[it][b][4]), Sxx1=vloadd(&g_emacc2[it][b][5]);
            double den0=Sr0+1e-8; mu0=Sx0/den0;
            var0=(Sxx0-2.0*mu0*Sx0+mu0*mu0*Sr0)/den0+1e-6; pi0=Sr0/(double)NPIX;
            double den1=Sr1+1e-8; mu1=Sx1/den1;
            var1=(Sxx1-2.0*mu1*Sx1+mu1*mu1*Sr1)/den1+1e-6; pi1=Sr1/(double)NPIX;
        }
    }
    float m0=(float)mu0, m1=(float)mu1;
    float v0=(float)var0+1e-6f, v1=(float)var1+1e-6f;
    float lw0=-0.5f*logf(v0)+logf((float)pi0+1e-8f);
    float lw1=-0.5f*logf(v1)+logf((float)pi1+1e-8f);
    float iv0=0.5f/v0, iv1=0.5f/v1;
    #pragma unroll
    for(int i=0;i<9;i++){
        float xx=x[i];
        float lp0=-(xx-m0)*(xx-m0)*iv0+lw0;
        float lp1=-(xx-m1)*(xx-m1)*iv1+lw1;
        float R0=1.f/(1.f+expf(lp1-lp0));
        float R1=1.f/(1.f+expf(lp0-lp1));
        float r0=powf(R0,0.9f), r1=powf(R1,0.9f);
        float ssum=r0+r1+1e-8f;
        int p = base + i*1024;
        g_Ra[(b*2+0)*NPIX+p]=r0/ssum;
        g_Ra[(b*2+1)*NPIX+p]=r1/ssum;
    }
}

// cluster moments + bin index + global hist -> inverses + gcdf
__global__ void kClusterBin(){
    int b = blockIdx.y;
    __shared__ float sh[64];
    if(threadIdx.x<64) sh[threadIdx.x]=0.f;
    __syncthreads();
    float mn = u2f(g_mm[b][0]), mx = u2f(g_mm[b][1]);
    float inv_rng = 1.f/(mx-mn+1e-8f);
    double a[20];
    for(int i=0;i<20;i++) a[i]=0.0;
    int per = NPIX/64;
    int lo = blockIdx.x*per, hi = lo+per;
    for(int p=lo+threadIdx.x;p<hi;p+=blockDim.x){
        float w0=g_Ra[(b*2+0)*NPIX+p], w1=g_Ra[(b*2+1)*NPIX+p];
        float lpv=g_Lp[b*NPIX+p];
        double x0=lpv, x1=g_E[b*NPIX+p], x2=g_S[b*NPIX+p];
        a[0]+=w0; a[1]+=w0*x0; a[2]+=w0*x1; a[3]+=w0*x2;
        a[4]+=w0*x0*x0; a[5]+=w0*x0*x1; a[6]+=w0*x0*x2;
        a[7]+=w0*x1*x1; a[8]+=w0*x1*x2; a[9]+=w0*x2*x2;
        a[10]+=w1; a[11]+=w1*x0; a[12]+=w1*x1; a[13]+=w1*x2;
        a[14]+=w1*x0*x0; a[15]+=w1*x0*x1; a[16]+=w1*x0*x2;
        a[17]+=w1*x1*x1; a[18]+=w1*x1*x2; a[19]+=w1*x2*x2;
        float ln = (lpv-mn)*inv_rng;
        ln = fminf(fmaxf(ln,0.f),1.f);
        int c = (int)(ln*32.f); c = c<0?0:(c>31?31:c);
        g_idxb[b*NPIX+p] = (unsigned char)c;
        atomicAdd(&sh[c],    w0);
        atomicAdd(&sh[32+c], w1);
    }
    for(int m=0;m<20;m++){
        double r=blockReduceD(a[m]);
        if(threadIdx.x==0) atomicAdd(&g_clacc[b][m/10][m%10],r);
    }
    __syncthreads();
    if(threadIdx.x<64 && sh[threadIdx.x]!=0.f)
        atomicAdd(&g_ghist[b][threadIdx.x>>5][threadIdx.x&31],(double)sh[threadIdx.x]);
    gridBarrier(64*BB);
    if(blockIdx.x==0 && blockIdx.y==0 && threadIdx.x<4){
        int t = threadIdx.x;
        int bb=t>>1, k=t&1;
        double A[10];
        for(int i=0;i<10;i++) A[i]=vloadd(&g_clacc[bb][k][i]);
        double Ws = A[0] + 1e-8;
        double mu[3] = {A[1]/Ws, A[2]/Ws, A[3]/Ws};
        double Sx[3] = {A[1], A[2], A[3]};
        double Sxx[9] = {A[4],A[5],A[6], A[5],A[7],A[8], A[6],A[8],A[9]};
        double C[9];
        for(int i=0;i<3;i++) for(int j2=0;j2<3;j2++)
            C[i*3+j2] = (Sxx[i*3+j2] - mu[i]*Sx[j2] - mu[j2]*Sx[i] + A[0]*mu[i]*mu[j2])/Ws + ((i==j2)?1e-6:0.0);
        double I[9]; inv3(C, I);
        for(int i=0;i<9;i++) g_clinv[bb][k][i]=I[i];
        for(int i=0;i<3;i++) g_clmu[bb][k][i]=mu[i];
        for(int i=0;i<10;i++) g_clacc[bb][k][i]=0.0;
        double tot=0; for(int c=0;c<32;c++) tot += vloadd(&g_ghist[bb][k][c]);
        double cum=0;
        for(int c=0;c<32;c++){ cum += vloadd(&g_ghist[bb][k][c])/(tot+1e-8); g_gcdf[bb][k][c]=(float)cum; g_ghist[bb][k][c]=0.0; }
        if(k==0){ g_mm[bb][0]=0xFFFFFFFFu; g_mm[bb][1]=0u; }
    }
}

// DM (k==0 threads) fused with horizontal box pass
__global__ void kDMBoxH(){
    int bk = blockIdx.y; int b=bk>>1, k=bk&1;
    int p = blockIdx.x*blockDim.x + threadIdx.x;
    int y = p / WW, x = p % WW;
    float s0=0.f,s1=0.f,s2=0.f;
    int lo = max(x-7,0), hi = min(x+7,WW-1);
    for(int xx=lo;xx<=hi;xx++){
        float r = g_Ra[bk*NPIX + y*WW + xx];
        float l = g_Lp[b*NPIX + y*WW + xx];
        s0+=r; s1+=r*l; s2+=r*l*l;
    }
    g_t0[bk*NPIX+p]=s0; g_t1[bk*NPIX+p]=s1; g_t2[bk*NPIX+p]=s2;
    if(k==0){
        int idx = b*NPIX + p;
        float X0=g_Lp[idx], X1=g_E[idx], X2=g_S[idx];
        float ra0=g_Ra[(b*2+0)*NPIX+p], ra1=g_Ra[(b*2+1)*NPIX+p];
        float ssum = ra0+ra1+2e-8f;
        float DM=0.f;
        for(int kk=0;kk<2;kk++){
            float xm0=X0-(float)g_clmu[b][kk][0];
            float xm1=X1-(float)g_clmu[b][kk][1];
            float xm2=X2-(float)g_clmu[b][kk][2];
            const double* I=g_clinv[b][kk];
            float q = xm0*xm0*(float)I[0] + xm1*xm1*(float)I[4] + xm2*xm2*(float)I[8]
                    + 2.f*xm0*xm1*(float)I[1] + 2.f*xm0*xm2*(float)I[2] + 2.f*xm1*xm2*(float)I[5];
            float Dk = sqrtf(q + 1e-8f);
            float Rt = ((kk==0?ra0:ra1)+1e-8f)/ssum;
            DM += Rt*Dk;
        }
        g_DM[idx]=DM;
    }
}

__global__ void kBoxV(){
    int bk = blockIdx.y; int b=bk>>1;
    int p = blockIdx.x*blockDim.x + threadIdx.x;
    int y = p / WW, x = p % WW;
    float s0=0.f,s1=0.f,s2=0.f;
    int lo = max(y-7,0), hi = min(y+7,HH-1);
    for(int yy=lo;yy<=hi;yy++){
        s0+=g_t0[bk*NPIX+yy*WW+x]; s1+=g_t1[bk*NPIX+yy*WW+x]; s2+=g_t2[bk*NPIX+yy*WW+x];
    }
    float cy = (float)(min(y+8,HH)-max(y-7,0));
    float cx = (float)(min(x+8,WW)-max(x-7,0));
    float c = cy*cx;
    float a0=s0/c, a1=s1/c, a2=s2/c;
    float den = a0 + 1e-8f;
    float mu = a1/den;
    float vb = fmaxf(a2/den - mu*mu, 1e-8f);
    g_lla[bk*NPIX+p] = fabsf(g_Lp[b*NPIX+p]-mu)/(sqrtf(vb)+1e-8f);
    g_den[bk*NPIX+p] = a0;
}

// fused GLD: tiled column histograms in shared (bin-prefix form), vertical+horizontal sliding
__global__ void __launch_bounds__(128,8) kGLDTile(){
    int bk = blockIdx.z; int b=bk>>1, k=bk&1;
    int strip = blockIdx.x;            // 8 strips of 48 cols
    int y0 = blockIdx.y*GTY;           // 16 segs of 24 rows
    int warp = threadIdx.x>>5, lane = threadIdx.x&31;
    __shared__ float ch[62][32];
    const float* rk = g_Ra + bk*NPIX;
    const unsigned char* bi = g_idxb + b*NPIX;
    int xbase = strip*48 - 7;
    for(int i=threadIdx.x;i<62*32;i+=128) ((float*)ch)[i]=0.f;
    __syncthreads();
    for(int c=warp;c<62;c+=4){
        int x = xbase+c;
        if(x<0||x>=WW) continue;
        float P=0.f;
        for(int r=y0-7;r<=y0+6;r++){
            if(r<0||r>=HH) continue;
            float v=rk[r*WW+x]; int bn=bi[r*WW+x];
            if(lane>=bn) P+=v;
        }
        ch[c][lane]=P;
    }
    float gc = g_gcdf[b][k][lane];
    __syncthreads();
    for(int y=y0;y<y0+GTY;y++){
        int ra=y+7;
        if(ra<HH){
            for(int c=warp;c<62;c+=4){
                int x=xbase+c; if(x<0||x>=WW) continue;
                float v=rk[ra*WW+x]; int bn=bi[ra*WW+x];
                if(lane>=bn) ch[c][lane]+=v;
            }
        }
        __syncthreads();
        {
            int xo0 = warp*12;
            float S=0.f;
            #pragma unroll
            for(int c=0;c<14;c++) S += ch[xo0+c][lane];
            float cy = (float)(min(y+8,HH)-max(y-7,0));
            for(int j=0;j<12;j++){
                int xo = xo0+j;
                S += ch[xo+14][lane];
                int x = strip*48 + xo;
                float cx = (float)(min(x+8,WW)-max(x-7,0));
                float den = g_den[bk*NPIX + y*WW+x] + 1e-8f;
                float diff = fabsf(S/(cy*cx)/den - gc);
                for(int o=16;o;o>>=1) diff += __shfl_down_sync(0xffffffffu,diff,o);
                if(lane==0) g_gld[bk*NPIX + y*WW+x] = diff*(1.f/32.f);
                S -= ch[xo][lane];
            }
        }
        __syncthreads();
        int rs=y-7;
        if(rs>=0){
            for(int c=warp;c<62;c+=4){
                int x=xbase+c; if(x<0||x>=WW) continue;
                float v=rk[rs*WW+x]; int bn=bi[rs*WW+x];
                if(lane>=bn) ch[c][lane]-=v;
            }
        }
        __syncthreads();
    }
}

// final phase: gamma/La inline, cooperative 1%/99% selects, final normalize
__global__ void __launch_bounds__(1024,1) kFinalPhase(float* __restrict__ out){
    int nbTot = 4*SELG;   // 64
    int job = blockIdx.x/SELG, chunk = blockIdx.x%SELG;
    int per = BN/64;
    int lo = blockIdx.x*per;
    for(int idx=lo+threadIdx.x; idx<lo+per; idx+=blockDim.x){
        int b = idx / NPIX, p = idx % NPIX;
        float gamma = 1.f;
        for(int k=0;k<2;k++){
            int s = b*2+k;
            float zl = (g_lla[s*NPIX+p]-g_sv[20+s])/(g_sv[24+s]*1.4826f+1e-8f);
            float zg = (g_gld[s*NPIX+p]-g_sv[28+s])/(g_sv[32+s]*1.4826f+1e-8f);
            gamma += g_Ra[s*NPIX+p]*(0.5f*softplusf(zl)+0.5f*softplusf(zg));
        }
        float mdE=g_sv[b*3+1], mdS=g_sv[b*3+2];
        float sdE=g_sv[6+b*3+1]*1.4826f+1e-8f, sdS=g_sv[6+b*3+2]*1.4826f+1e-8f;
        float dE=(g_E[idx]-mdE)/sdE-(float)g_esinv[b][3];
        float dS=(g_S[idx]-mdS)/sdS-(float)g_esinv[b][4];
        float d2 = dE*dE*(float)g_esinv[b][0] + 2.f*dE*dS*(float)g_esinv[b][1] + dS*dS*(float)g_esinv[b][2];
        float Rs = expf(-0.5f*d2);
        g_La[idx] = fmaxf(g_DM[idx]*gamma*(1.f-Rs), 0.f);
    }
    coopZero(4, nbTot);
    gridBarrier(nbTot);
    const int* jb = &g_seljobs[(18+job)*6];
    const float4* src = (const float4*)selSrc(jb[1], jb[2]);
    float v0 = coopSel(src,0.f,0,(unsigned)jb[3],job,0,chunk,nbTot);
    if(chunk==0&&threadIdx.x==0) g_sv[jb[4]]=v0;
    float v1 = coopSel(src,0.f,0,(unsigned)jb[3]+1u,job,3,chunk,nbTot);
    if(chunk==0&&threadIdx.x==0) g_sv[jb[5]]=v1;
    gridBarrier(nbTot);
    for(int idx=lo+threadIdx.x; idx<lo+per; idx+=blockDim.x){
        int b = idx / NPIX;
        float q1 = vloadf(&g_sv[36+4*b]) + 0.55f*(vloadf(&g_sv[37+4*b])-vloadf(&g_sv[36+4*b]));
        float q9 = vloadf(&g_sv[38+4*b]) + 0.45f*(vloadf(&g_sv[39+4*b])-vloadf(&g_sv[38+4*b]));
        float v = (g_La[idx]-q1)/(q9-q1+1e-8f);
        out[BN + idx] = fminf(fmaxf(v,0.f),1.f);   // output #2
    }
}

// ======================= host =======================
extern "C" void kernel_launch(void* const* d_in, const int* in_sizes, int n_in,
                              void* d_out, int out_size){
    const float* lab   = (const float*)d_in[0];
    const float* arand = (const float*)d_in[1];
    float* out = (float*)d_out;
    const int EB = (BN+255)/256;      // 1152 (exact)

    kSobelE<<<dim3(24,24,BB),256>>>(lab);
    kSolve<<<1,32>>>();
    kLperp<<<EB,256>>>(lab,out);

    selCoop<<<6*SELG,1024>>>(0,6);        // med+MAD of Lp,E,S
    kCovEighCdir<<<64,256>>>(arand);
    kKurtAcc<<<dim3(64,BB),256>>>();
    kKurtPick<<<1,32>>>();

    kPhaseZ<<<4*SELG,1024>>>();           // zb + quartile brackets
    kEM<<<EMB,1024>>>();                  // persistent EM -> Ra

    kClusterBin<<<dim3(64,BB),256>>>();
    kDMBoxH<<<dim3(576,4),256>>>();
    kBoxV<<<dim3(576,4),256>>>();
    kGLDTile<<<dim3(8,16,4),128>>>();

    selCoop<<<8*SELG,1024>>>(10,8);       // LLA + GLD med+MAD (merged)

    kFinalPhase<<<4*SELG,1024>>>(out);    // gamma/La + quantiles + normalize
}

// round 11
// speedup vs baseline: 1.1514x; 1.1514x over previous
#include <cuda_runtime.h>
#include <math.h>

#define HH 384
#define WW 384
#define NPIX (HH*WW)          // 147456
#define BB 2
#define BN (BB*NPIX)          // 294912
#define NDIR 128
#define GTY 24

// ======================= scratch buffers =======================
__device__ float g_E[BN];
__device__ float g_S[BN];
__device__ float g_Lp[BN];
__device__ float g_zb[BN];
__device__ float g_Ra[2*BN];     // [(b*2+k)*NPIX+n]
__device__ float g_DM[BN];
__device__ float g_t0[2*BN], g_t1[2*BN], g_t2[2*BN];
__device__ float g_lla[2*BN];
__device__ float g_den[2*BN];
__device__ float g_gld[2*BN];
__device__ float g_La[BN];
__device__ unsigned char g_idxb[BN];
__device__ unsigned g_jh[8*6*2048];     // cooperative select histograms

// ======================= small state =======================
__device__ float    g_sv[64];
__device__ unsigned g_mm[BB][2] = {{0xFFFFFFFFu,0u},{0xFFFFFFFFu,0u}};
__device__ double   g_reg[BB][5];
__device__ double   g_cacc[BB][9];
__device__ double   g_mean3[BB][3];
__device__ double   g_wwh[BB][9];
__device__ float    g_cdir[BB*NDIR*3];
__device__ float    g_cbest[BB][3];
__device__ double   g_dirm[BB][NDIR][4];
__device__ double   g_emacc2[9][BB][6];
__device__ double   g_clacc[BB][2][10];
__device__ double   g_clmu[BB][2][3];
__device__ double   g_clinv[BB][2][9];
__device__ double   g_ghist[BB][2][32];
__device__ float    g_gcdf[BB][2][32];
__device__ double   g_esinv[BB][6];

// grid-wide barrier (monotonic generation; arrive self-resets)
__device__ int g_barArrive = 0;
__device__ int g_barGen = 0;

static __device__ __forceinline__ void gridBarrier(int nb){
    __threadfence();
    __syncthreads();
    if(threadIdx.x==0){
        int gen = *(volatile int*)&g_barGen;
        if(atomicAdd(&g_barArrive,1)==nb-1){
            g_barArrive = 0;
            __threadfence();
            *(volatile int*)&g_barGen = gen+1;
        } else {
            while(*(volatile int*)&g_barGen == gen) { }
        }
    }
    __syncthreads();
}

static __device__ __forceinline__ double vloadd(const double* p){ return *(volatile const double*)p; }
static __device__ __forceinline__ float  vloadf(const float* p){ return *(volatile const float*)p; }

// ======================= helpers =======================
static __device__ __forceinline__ unsigned f2u(float f){
    unsigned u = __float_as_uint(f);
    return (u & 0x80000000u) ? ~u : (u | 0x80000000u);
}
static __device__ __forceinline__ float u2f(unsigned u){
    unsigned v = (u & 0x80000000u) ? (u & 0x7FFFFFFFu) : ~u;
    return __uint_as_float(v);
}
static __device__ __forceinline__ float softplusf(float x){
    float t = log1pf(expf(-fabsf(x)));
    return x >= 0.f ? x + t : t;
}
static __device__ double blockReduceD(double v){
    __shared__ double sh[32];
    int lane = threadIdx.x & 31, wid = threadIdx.x >> 5;
    for (int o=16;o;o>>=1) v += __shfl_down_sync(0xffffffffu, v, o);
    if (lane==0) sh[wid] = v;
    __syncthreads();
    int nw = (blockDim.x + 31) >> 5;
    v = (threadIdx.x < nw) ? sh[threadIdx.x] : 0.0;
    if (wid==0) for (int o=16;o;o>>=1) v += __shfl_down_sync(0xffffffffu, v, o);
    __syncthreads();
    return v;
}
static __device__ void eigh3(const double* A, double* e, double* V){
    double a[9]; for(int i=0;i<9;i++) a[i]=A[i];
    for(int i=0;i<9;i++) V[i] = (i%4==0)?1.0:0.0;
    for(int sweep=0;sweep<40;sweep++){
        double off = fabs(a[1])+fabs(a[2])+fabs(a[5]);
        if(off < 1e-300) break;
        for(int p=0;p<2;p++) for(int q=p+1;q<3;q++){
            double apq=a[p*3+q];
            if(fabs(apq) < 1e-300) continue;
            double app=a[p*3+p], aqq=a[q*3+q];
            double th=(aqq-app)/(2.0*apq);
            double t=(th>=0?1.0:-1.0)/(fabs(th)+sqrt(th*th+1.0));
            double c=1.0/sqrt(t*t+1.0), s=t*c;
            for(int i=0;i<3;i++){ double x=a[i*3+p],y=a[i*3+q]; a[i*3+p]=c*x-s*y; a[i*3+q]=s*x+c*y; }
            for(int i=0;i<3;i++){ double x=a[p*3+i],y=a[q*3+i]; a[p*3+i]=c*x-s*y; a[q*3+i]=s*x+c*y; }
            for(int i=0;i<3;i++){ double x=V[i*3+p],y=V[i*3+q]; V[i*3+p]=c*x-s*y; V[i*3+q]=s*x+c*y; }
        }
    }
    e[0]=a[0]; e[1]=a[4]; e[2]=a[8];
}
static __device__ void inv3(const double* m, double* inv){
    double a=m[0],b=m[1],c=m[2],d=m[3],e=m[4],f=m[5],g=m[6],h=m[7],i=m[8];
    double A=e*i-f*h, B=c*h-b*i, C=b*f-c*e;
    double D=f*g-d*i, E=a*i-c*g, F=c*d-a*f;
    double G=d*h-e*g, Hh=b*g-a*h, I=a*e-b*d;
    double det=a*A+b*D+c*G, id=1.0/det;
    inv[0]=A*id; inv[1]=B*id; inv[2]=C*id;
    inv[3]=D*id; inv[4]=E*id; inv[5]=F*id;
    inv[6]=G*id; inv[7]=Hh*id; inv[8]=I*id;
}

// ======================= cooperative radix select =======================
// jobs: {kind, type, b, rank, slotA, slotB}
__device__ const int g_seljobs[22*6] = {
 0,0,0,73727,0,6,   0,1,0,73727,1,7,   0,2,0,73727,2,8,
 0,0,1,73727,3,9,   0,1,1,73727,4,10,  0,2,1,73727,5,11,
 1,3,0,36863,12,13,  1,3,0,110591,14,15,  1,3,1,36863,16,17,  1,3,1,110591,18,19,
 0,4,0,73727,20,24,  0,5,0,73727,21,25,  0,4,1,73727,22,26,  0,5,1,73727,23,27,
 0,6,0,73727,28,32,  0,7,0,73727,29,33,  0,6,1,73727,30,34,  0,7,1,73727,31,35,
 1,8,0,1474,36,37,  1,8,0,145980,38,39,  1,8,1,1474,40,41,  1,8,1,145980,42,43
};

static __device__ const float* selSrc(int type, int b){
    switch(type){
        case 0: return g_Lp + b*NPIX;
        case 1: return g_E  + b*NPIX;
        case 2: return g_S  + b*NPIX;
        case 3: return g_zb + b*NPIX;
        case 4: return g_lla + (b*2+0)*NPIX;
        case 5: return g_lla + (b*2+1)*NPIX;
        case 6: return g_gld + (b*2+0)*NPIX;
        case 7: return g_gld + (b*2+1)*NPIX;
        default: return g_La + b*NPIX;
    }
}

static __device__ void coopZero(int nbTot){
    int total = 8*6*2048;
    for(int i=blockIdx.x*blockDim.x+threadIdx.x; i<total; i+=nbTot*blockDim.x)
        g_jh[i]=0u;
}

// 3-pass (11/11/10 bit) cooperative select across ncs blocks per job.
static __device__ float coopSel(const float4* __restrict__ src4, float ref, int useAbs, unsigned rank,
                                int jobLocal, int passBase, int chunk, int ncs, int nbTot){
    __shared__ unsigned sh[2048];
    __shared__ unsigned sres[2];
    unsigned pref=0, rk=rank;
    for(int pass=0; pass<3; pass++){
        unsigned* hist = g_jh + (jobLocal*6+passBase+pass)*2048;
        int nbin = (pass==2)?1024:2048;
        for(int i=threadIdx.x;i<nbin;i+=blockDim.x) sh[i]=0u;
        __syncthreads();
        int per = (NPIX/4)/ncs;
        int lo = chunk*per;
        for(int i=lo+threadIdx.x;i<lo+per;i+=blockDim.x){
            float4 v4 = src4[i];
            float vv[4]={v4.x,v4.y,v4.z,v4.w};
            #pragma unroll
            for(int c=0;c<4;c++){
                float v=vv[c]; if(useAbs) v=fabsf(v-ref);
                unsigned key=f2u(v);
                if(pass==0) atomicAdd(&sh[key>>21],1u);
                else if(pass==1){ if((key>>21)==(pref>>21)) atomicAdd(&sh[(key>>10)&2047u],1u); }
                else { if((key>>10)==(pref>>10)) atomicAdd(&sh[key&1023u],1u); }
            }
        }
        __syncthreads();
        for(int i=threadIdx.x;i<nbin;i+=blockDim.x) if(sh[i]) atomicAdd(&hist[i],sh[i]);
        gridBarrier(nbTot);
        if(threadIdx.x<32){
            int lane=threadIdx.x, perl=nbin>>5;
            unsigned s=0;
            for(int i=0;i<perl;i++) s+=hist[lane*perl+i];
            unsigned cum=s;
            #pragma unroll
            for(int o=1;o<32;o<<=1){ unsigned t=__shfl_up_sync(0xffffffffu,cum,o); if(lane>=o) cum+=t; }
            unsigned prev=cum-s;
            if(prev<=rk && rk<cum){
                unsigned rr=rk-prev; int bin=lane*perl;
                for(int i=0;i<perl;i++){ unsigned c=hist[lane*perl+i]; if(rr<c){ bin=lane*perl+i; break;} rr-=c; }
                sres[0]=(pass==0)? ((unsigned)bin<<21) : (pass==1)? (pref|((unsigned)bin<<10)) : (pref|(unsigned)bin);
                sres[1]=rr;
            }
        }
        __syncthreads();
        pref=sres[0]; rk=sres[1];
        __syncthreads();
    }
    return u2f(pref);
}

// ======================= pipeline kernels =======================
// fused Sobel + avg3 + regression accumulation, tiled in shared memory
__global__ void __launch_bounds__(256) kSobelE(const float* __restrict__ lab){
    __shared__ float sL[20][20];
    __shared__ float sP[18][18];
    int b = blockIdx.z;
    int x0 = blockIdx.x*16, y0 = blockIdx.y*16;
    int tid = threadIdx.x;
    int tx = tid & 15, ty = tid >> 4;
    const float* L = lab + (size_t)b*3*NPIX;
    for(int i=tid;i<400;i+=256){
        int jj=i/20, ii=i%20;
        int yy=y0-2+jj, xx=x0-2+ii;
        sL[jj][ii] = (yy>=0&&yy<HH&&xx>=0&&xx<WW) ? L[yy*WW+xx] : 0.f;
    }
    __syncthreads();
    for(int i=tid;i<324;i+=256){
        int jj=i/18, ii=i%18;
        int py=y0-1+jj, px=x0-1+ii;
        float v=0.f;
        if(py>=0&&py<HH&&px>=0&&px<WW){
            float l00=sL[jj][ii],   l01=sL[jj][ii+1],   l02=sL[jj][ii+2];
            float l10=sL[jj+1][ii],                     l12=sL[jj+1][ii+2];
            float l20=sL[jj+2][ii], l21=sL[jj+2][ii+1], l22=sL[jj+2][ii+2];
            float gx = -l00 + l02 - 2.f*l10 + 2.f*l12 - l20 + l22;
            float gy = -l00 - 2.f*l01 - l02 + l20 + 2.f*l21 + l22;
            v = gx*gx + gy*gy;
        }
        sP[jj][ii]=v;
    }
    __syncthreads();
    int y=y0+ty, x=x0+tx;
    int p = y*WW+x, idx = b*NPIX+p;
    float s = sP[ty][tx]  +sP[ty][tx+1]  +sP[ty][tx+2]
            + sP[ty+1][tx]+sP[ty+1][tx+1]+sP[ty+1][tx+2]
            + sP[ty+2][tx]+sP[ty+2][tx+1]+sP[ty+2][tx+2];
    float E = s/9.f;
    float av = L[NPIX+p], bv = L[2*NPIX+p];
    float S = sqrtf(av*av+bv*bv+1e-8f);
    g_E[idx]=E; g_S[idx]=S;
    double e=E, sv=S, l=L[p];
    double r;
    r=blockReduceD(e*e);  if(tid==0) atomicAdd(&g_reg[b][0],r);
    r=blockReduceD(e*sv); if(tid==0) atomicAdd(&g_reg[b][1],r);
    r=blockReduceD(sv*sv);if(tid==0) atomicAdd(&g_reg[b][2],r);
    r=blockReduceD(e*l);  if(tid==0) atomicAdd(&g_reg[b][3],r);
    r=blockReduceD(sv*l); if(tid==0) atomicAdd(&g_reg[b][4],r);
}

// L_perp (per-block inline 2x2 solve) + fused global min/max
__global__ void __launch_bounds__(256) kLperp(const float* __restrict__ lab, float* __restrict__ out){
    __shared__ float sb0, sb1;
    int idx = blockIdx.x*blockDim.x + threadIdx.x;
    int b = idx / NPIX, p = idx % NPIX;
    if(threadIdx.x==0){
        double ee=g_reg[b][0]+1e-6, es=g_reg[b][1], ss=g_reg[b][2]+1e-6;
        double el=g_reg[b][3], sl=g_reg[b][4];
        double det = ee*ss - es*es;
        sb0 = (float)((ss*el - es*sl)/det);
        sb1 = (float)((ee*sl - es*el)/det);
    }
    __syncthreads();
    float v = lab[(size_t)b*3*NPIX+p] - sb0*g_E[idx] - sb1*g_S[idx];
    g_Lp[idx] = v;
    out[idx] = v;   // output #1
    unsigned k = f2u(v);
    __shared__ unsigned smn[256], smx[256];
    smn[threadIdx.x]=k; smx[threadIdx.x]=k;
    __syncthreads();
    for(int o=128;o>0;o>>=1){
        if(threadIdx.x<o){ smn[threadIdx.x]=min(smn[threadIdx.x],smn[threadIdx.x+o]);
                           smx[threadIdx.x]=max(smx[threadIdx.x],smx[threadIdx.x+o]); }
        __syncthreads();
    }
    if(threadIdx.x==0){ atomicMin(&g_mm[b][0],smn[0]); atomicMax(&g_mm[b][1],smx[0]); }
}

// phase A: med+MAD of Lp,E,S for both batches; 6 jobs x 24 chunks = 144 blocks
__global__ void __launch_bounds__(1024,1) kSelA(){
    const int NB = 144;
    int job = blockIdx.x/24, chunk = blockIdx.x%24;
    coopZero(NB);
    gridBarrier(NB);
    const int* jb = &g_seljobs[job*6];
    const float4* src = (const float4*)selSrc(jb[1], jb[2]);
    float med = coopSel(src,0.f,0,(unsigned)jb[3],job,0,chunk,24,NB);
    if(chunk==0&&threadIdx.x==0) g_sv[jb[4]]=med;
    float mad = coopSel(src,med,1,(unsigned)jb[3],job,3,chunk,24,NB);
    if(chunk==0&&threadIdx.x==0) g_sv[jb[5]]=mad;
}

// cov-acc + eigh/ESinv/cdir + kurt-acc + parallel pick : ONE kernel, 128 blocks x 256
__global__ void __launch_bounds__(256) kWhiten(const float* __restrict__ arand){
    int blk = blockIdx.x;
    int b = blk>>6, chunk = blk&63;
    float md[3], sd[3];
    for(int f=0;f<3;f++){ md[f]=g_sv[b*3+f]; sd[f]=g_sv[6+b*3+f]*1.4826f+1e-8f; }
    int base = b*NPIX + chunk*2304;
    float z0[9], z1[9], z2[9];
    double a[9]={0,0,0,0,0,0,0,0,0};
    #pragma unroll
    for(int i=0;i<9;i++){
        int p = base + i*256 + threadIdx.x;
        float u0=(g_Lp[p]-md[0])/sd[0];
        float u1=(g_E [p]-md[1])/sd[1];
        float u2=(g_S [p]-md[2])/sd[2];
        z0[i]=u0; z1[i]=u1; z2[i]=u2;
        a[0]+=u0; a[1]+=u1; a[2]+=u2;
        a[3]+=(double)u0*u0; a[4]+=(double)u0*u1; a[5]+=(double)u0*u2;
        a[6]+=(double)u1*u1; a[7]+=(double)u1*u2; a[8]+=(double)u2*u2;
    }
    for(int m=0;m<9;m++){ double r=blockReduceD(a[m]); if(threadIdx.x==0) atomicAdd(&g_cacc[b][m],r); }
    gridBarrier(128);
    if(blk==0){
        int t = threadIdx.x;
        if(t<BB){
            int bb = t;
            double N = (double)NPIX;
            double mu[3]; for(int i=0;i<3;i++){ mu[i]=vloadd(&g_cacc[bb][i])/N; g_mean3[bb][i]=mu[i]; }
            double C[9];
            C[0]=vloadd(&g_cacc[bb][3])/N-mu[0]*mu[0]; C[1]=vloadd(&g_cacc[bb][4])/N-mu[0]*mu[1]; C[2]=vloadd(&g_cacc[bb][5])/N-mu[0]*mu[2];
            C[4]=vloadd(&g_cacc[bb][6])/N-mu[1]*mu[1]; C[5]=vloadd(&g_cacc[bb][7])/N-mu[1]*mu[2]; C[8]=vloadd(&g_cacc[bb][8])/N-mu[2]*mu[2];
            C[3]=C[1]; C[6]=C[2]; C[7]=C[5];
            {
                double c00=C[4]+1e-6, c01=C[5], c11=C[8]+1e-6;
                double det=c00*c11-c01*c01;
                g_esinv[bb][0]=c11/det; g_esinv[bb][1]=-c01/det; g_esinv[bb][2]=c00/det;
                g_esinv[bb][3]=mu[1]; g_esinv[bb][4]=mu[2];
            }
            for(int i=0;i<9;i++) C[i] = C[i] > 1e-8 ? C[i] : 1e-8;   // elementwise max (matches ref)
            double e[3], V[9];
            eigh3(C, e, V);
            for(int i=0;i<3;i++) for(int j=0;j<3;j++){
                double ssum=0; for(int k2=0;k2<3;k2++) ssum += V[i*3+k2]*(1.0/sqrt(e[k2]))*V[j*3+k2];
                g_wwh[bb][i*3+j]=ssum;
            }
            for(int i=0;i<9;i++) g_cacc[bb][i]=0.0;
        }
        __syncthreads();
        {
            int t2 = threadIdx.x;       // 256 threads = BB*NDIR
            int bb = t2 / NDIR, d = t2 % NDIR;
            float a0=arand[(bb*NDIR+d)*3+0], a1=arand[(bb*NDIR+d)*3+1], a2=arand[(bb*NDIR+d)*3+2];
            float nr = sqrtf(a0*a0+a1*a1+a2*a2) + 1e-12f;
            double an[3]={a0/nr,a1/nr,a2/nr};
            for(int jj=0;jj<3;jj++){
                double ssum=0; for(int i=0;i<3;i++) ssum += g_wwh[bb][jj*3+i]*an[i];
                g_cdir[(bb*NDIR+d)*3+jj]=(float)ssum;
            }
        }
    }
    gridBarrier(128);
    // kurt phase: reuse cached z arrays
    __shared__ float scd[NDIR*3];
    __shared__ float sacc[NDIR*4];
    for(int i=threadIdx.x;i<NDIR*3;i+=256) scd[i]=vloadf(&g_cdir[b*NDIR*3+i]);
    for(int i=threadIdx.x;i<NDIR*4;i+=256) sacc[i]=0.f;
    float mn0=(float)vloadd(&g_mean3[b][0]), mn1=(float)vloadd(&g_mean3[b][1]), mn2=(float)vloadd(&g_mean3[b][2]);
    #pragma unroll
    for(int i=0;i<9;i++){ z0[i]-=mn0; z1[i]-=mn1; z2[i]-=mn2; }
    __syncthreads();
    int lane = threadIdx.x & 31;
    for(int d=0;d<NDIR;d++){
        float c0=scd[d*3], c1=scd[d*3+1], c2=scd[d*3+2];
        float s1=0,s2=0,s3=0,s4=0;
        #pragma unroll
        for(int i=0;i<9;i++){
            float z=z0[i]*c0+z1[i]*c1+z2[i]*c2;
            float zz=z*z;
            s1+=z; s2+=zz; s3+=zz*z; s4+=zz*zz;
        }
        for(int o=16;o;o>>=1){
            s1+=__shfl_down_sync(0xffffffffu,s1,o); s2+=__shfl_down_sync(0xffffffffu,s2,o);
            s3+=__shfl_down_sync(0xffffffffu,s3,o); s4+=__shfl_down_sync(0xffffffffu,s4,o);
        }
        if(lane==0){
            atomicAdd(&sacc[d*4+0],s1); atomicAdd(&sacc[d*4+1],s2);
            atomicAdd(&sacc[d*4+2],s3); atomicAdd(&sacc[d*4+3],s4);
        }
    }
    __syncthreads();
    for(int i=threadIdx.x;i<NDIR*4;i+=256)
        atomicAdd(&((double*)g_dirm)[b*NDIR*4+i], (double)sacc[i]);
    gridBarrier(128);
    if(blk==0){
        __shared__ double skv[256];
        __shared__ int sdi[256];
        int t = threadIdx.x;
        int bb = t>>7, d = t&127;
        double N=(double)NPIX;
        double m1=vloadd(&g_dirm[bb][d][0])/N, s2=vloadd(&g_dirm[bb][d][1])/N;
        double s3=vloadd(&g_dirm[bb][d][2])/N, s4=vloadd(&g_dirm[bb][d][3])/N;
        double m2=(s2-m1*m1)+1e-12;
        double m4=s4-4.0*m1*s3+6.0*m1*m1*s2-3.0*m1*m1*m1*m1;
        skv[t]=fabs(m4/(m2*m2)-3.0); sdi[t]=d;
        __syncthreads();
        for(int o=64;o;o>>=1){
            if((t&127)<o){
                if(skv[t+o]>skv[t] || (skv[t+o]==skv[t] && sdi[t+o]<sdi[t])){ skv[t]=skv[t+o]; sdi[t]=sdi[t+o]; }
            }
            __syncthreads();
        }
        if((t&127)==0){
            int best=sdi[t];
            for(int j=0;j<3;j++) g_cbest[t>>7][j]=vloadf(&g_cdir[((t>>7)*NDIR+best)*3+j]);
        }
        __syncthreads();
        // reset dirm (1024 doubles)
        for(int i=t;i<BB*NDIR*4;i+=256) ((double*)g_dirm)[i]=0.0;
    }
}

// phase Z + EM fused: zb compute, quartile-bracket selects, 9 EM iters, Ra.  144 x 1024
__global__ void __launch_bounds__(1024,1) kPhaseZEM(){
    const int NB = 144;
    int gtid = blockIdx.x*1024 + threadIdx.x;     // < 147456
    // zb for both batches
    #pragma unroll
    for(int h=0;h<2;h++){
        int idx = gtid + h*NPIX;
        int b = h;
        float md0=g_sv[b*3+0], md1=g_sv[b*3+1], md2=g_sv[b*3+2];
        float sd0=g_sv[6+b*3+0]*1.4826f+1e-8f, sd1=g_sv[6+b*3+1]*1.4826f+1e-8f, sd2=g_sv[6+b*3+2]*1.4826f+1e-8f;
        float d0=(g_Lp[idx]-md0)/sd0-(float)g_mean3[b][0];
        float d1=(g_E [idx]-md1)/sd1-(float)g_mean3[b][1];
        float d2=(g_S [idx]-md2)/sd2-(float)g_mean3[b][2];
        g_zb[idx] = d0*g_cbest[b][0]+d1*g_cbest[b][1]+d2*g_cbest[b][2];
    }
    coopZero(NB);
    {   // zero EM accumulators for this replay
        double* acc = (double*)g_emacc2;
        int tot = 9*BB*6;
        for(int i=blockIdx.x*1024+threadIdx.x; i<tot; i+=NB*1024) acc[i]=0.0;
    }
    gridBarrier(NB);
    // quartile-bracket selects: 4 jobs x 36 chunks
    {
        int job = blockIdx.x/36, chunk = blockIdx.x%36;
        const int* jb = &g_seljobs[(6+job)*6];
        const float4* src = (const float4*)selSrc(jb[1], jb[2]);
        float v0 = coopSel(src,0.f,0,(unsigned)jb[3],job,0,chunk,36,NB);
        if(chunk==0&&threadIdx.x==0) g_sv[jb[4]]=v0;
        float v1 = coopSel(src,0.f,0,(unsigned)jb[3]+1u,job,3,chunk,36,NB);
        if(chunk==0&&threadIdx.x==0) g_sv[jb[5]]=v1;
    }
    gridBarrier(NB);
    // EM: blocks 0..71 -> batch0, 72..143 -> batch1; 2 elems per thread
    // NOTE: baseRel is batch-RELATIVE (R9 bug: absolute base reused as plane offset -> OOB)
    int b = blockIdx.x/72, sub = blockIdx.x%72;
    int baseRel = sub*2048 + threadIdx.x;
    float x0 = g_zb[b*NPIX + baseRel], x1 = g_zb[b*NPIX + baseRel + 1024];
    float q25 = vloadf(&g_sv[12+4*b]) + 0.75f*(vloadf(&g_sv[13+4*b])-vloadf(&g_sv[12+4*b]));
    float q75 = vloadf(&g_sv[14+4*b]) + 0.25f*(vloadf(&g_sv[15+4*b])-vloadf(&g_sv[14+4*b]));
    double mu0=q25, mu1=q75, var0=1.0, var1=1.0, pi0=0.5, pi1=0.5;
    for(int it=0; it<9; it++){
        float m0=(float)mu0, m1=(float)mu1;
        float v0=(float)var0+1e-6f, v1=(float)var1+1e-6f;
        float lw0=-0.5f*logf(v0)+logf((float)pi0+1e-8f);
        float lw1=-0.5f*logf(v1)+logf((float)pi1+1e-8f);
        float iv0=0.5f/v0, iv1=0.5f/v1;
        float a0=0,a1=0,a2=0,a3=0,a4=0,a5=0;
        #pragma unroll
        for(int i=0;i<2;i++){
            float xx = (i==0)?x0:x1;
            float lp0=-(xx-m0)*(xx-m0)*iv0+lw0;
            float lp1=-(xx-m1)*(xx-m1)*iv1+lw1;
            float R0=1.f/(1.f+expf(lp1-lp0));
            float R1=1.f/(1.f+expf(lp0-lp1));
            a0+=R0; a1+=R0*xx; a2+=R0*xx*xx;
            a3+=R1; a4+=R1*xx; a5+=R1*xx*xx;
        }
        double s[6]={a0,a1,a2,a3,a4,a5};
        for(int m=0;m<6;m++){
            double r=blockReduceD(s[m]);
            if(threadIdx.x==0) atomicAdd(&g_emacc2[it][b][m],r);
        }
        gridBarrier(NB);
        {
            double Sr0=vloadd(&g_emacc2[it][b][0]), Sx0=vloadd(&g_emacc2[it][b][1]), Sxx0=vloadd(&g_emacc2[it][b][2]);
            double Sr1=vloadd(&g_emacc2[it][b][3]), Sx1=vloadd(&g_emacc2[it][b][4]), Sxx1=vloadd(&g_emacc2[it][b][5]);
            double den0=Sr0+1e-8; mu0=Sx0/den0;
            var0=(Sxx0-2.0*mu0*Sx0+mu0*mu0*Sr0)/den0+1e-6; pi0=Sr0/(double)NPIX;
            double den1=Sr1+1e-8; mu1=Sx1/den1;
            var1=(Sxx1-2.0*mu1*Sx1+mu1*mu1*Sr1)/den1+1e-6; pi1=Sr1/(double)NPIX;
        }
    }
    {
        float m0=(float)mu0, m1=(float)mu1;
        float v0=(float)var0+1e-6f, v1=(float)var1+1e-6f;
        float lw0=-0.5f*logf(v0)+logf((float)pi0+1e-8f);
        float lw1=-0.5f*logf(v1)+logf((float)pi1+1e-8f);
        float iv0=0.5f/v0, iv1=0.5f/v1;
        #pragma unroll
        for(int i=0;i<2;i++){
            float xx = (i==0)?x0:x1;
            int p = baseRel + i*1024;          // batch-relative plane offset
            float lp0=-(xx-m0)*(xx-m0)*iv0+lw0;
            float lp1=-(xx-m1)*(xx-m1)*iv1+lw1;
            float R0=1.f/(1.f+expf(lp1-lp0));
            float R1=1.f/(1.f+expf(lp0-lp1));
            float r0=powf(R0,0.9f), r1=powf(R1,0.9f);
            float ssum=r0+r1+1e-8f;
            g_Ra[(b*2+0)*NPIX+p]=r0/ssum;
            g_Ra[(b*2+1)*NPIX+p]=r1/ssum;
        }
    }
}

// cluster moments + binidx + ghist -> inverses+gcdf -> DM + boxH(shared rows) -> boxV(sliding)
__global__ void __launch_bounds__(256) kClusterDM(){
    int blk = blockIdx.x;              // 128
    int b = blk>>6, chunk = blk&63;
    __shared__ float sh64[64];
    if(threadIdx.x<64) sh64[threadIdx.x]=0.f;
    __syncthreads();
    float mn = u2f(g_mm[b][0]), mx = u2f(g_mm[b][1]);
    float inv_rng = 1.f/(mx-mn+1e-8f);
    double a[20];
    for(int i=0;i<20;i++) a[i]=0.0;
    int lo = chunk*2304, hi = lo+2304;
    for(int p=lo+threadIdx.x;p<hi;p+=256){
        float w0=g_Ra[(b*2+0)*NPIX+p], w1=g_Ra[(b*2+1)*NPIX+p];
        float lpv=g_Lp[b*NPIX+p];
        double x0=lpv, x1=g_E[b*NPIX+p], x2=g_S[b*NPIX+p];
        a[0]+=w0; a[1]+=w0*x0; a[2]+=w0*x1; a[3]+=w0*x2;
        a[4]+=w0*x0*x0; a[5]+=w0*x0*x1; a[6]+=w0*x0*x2;
        a[7]+=w0*x1*x1; a[8]+=w0*x1*x2; a[9]+=w0*x2*x2;
        a[10]+=w1; a[11]+=w1*x0; a[12]+=w1*x1; a[13]+=w1*x2;
        a[14]+=w1*x0*x0; a[15]+=w1*x0*x1; a[16]+=w1*x0*x2;
        a[17]+=w1*x1*x1; a[18]+=w1*x1*x2; a[19]+=w1*x2*x2;
        float ln = (lpv-mn)*inv_rng;
        ln = fminf(fmaxf(ln,0.f),1.f);
        int c = (int)(ln*32.f); c = c<0?0:(c>31?31:c);
        g_idxb[b*NPIX+p] = (unsigned char)c;
        atomicAdd(&sh64[c],    w0);
        atomicAdd(&sh64[32+c], w1);
    }
    for(int m=0;m<20;m++){
        double r=blockReduceD(a[m]);
        if(threadIdx.x==0) atomicAdd(&g_clacc[b][m/10][m%10],r);
    }
    __syncthreads();
    if(threadIdx.x<64 && sh64[threadIdx.x]!=0.f)
        atomicAdd(&g_ghist[b][threadIdx.x>>5][threadIdx.x&31],(double)sh64[threadIdx.x]);
    gridBarrier(128);
    if(blk==0 && threadIdx.x<4){
        int t = threadIdx.x;
        int bb=t>>1, k=t&1;
        double A[10];
        for(int i=0;i<10;i++) A[i]=vloadd(&g_clacc[bb][k][i]);
        double Ws = A[0] + 1e-8;
        double mu[3] = {A[1]/Ws, A[2]/Ws, A[3]/Ws};
        double Sx[3] = {A[1], A[2], A[3]};
        double Sxx[9] = {A[4],A[5],A[6], A[5],A[7],A[8], A[6],A[8],A[9]};
        double C[9];
        for(int i=0;i<3;i++) for(int j2=0;j2<3;j2++)
            C[i*3+j2] = (Sxx[i*3+j2] - mu[i]*Sx[j2] - mu[j2]*Sx[i] + A[0]*mu[i]*mu[j2])/Ws + ((i==j2)?1e-6:0.0);
        double I[9]; inv3(C, I);
        for(int i=0;i<9;i++) g_clinv[bb][k][i]=I[i];
        for(int i=0;i<3;i++) g_clmu[bb][k][i]=mu[i];
        for(int i=0;i<10;i++) g_clacc[bb][k][i]=0.0;
        double tot=0; for(int c=0;c<32;c++) tot += vloadd(&g_ghist[bb][k][c]);
        double cum=0;
        for(int c=0;c<32;c++){ cum += vloadd(&g_ghist[bb][k][c])/(tot+1e-8); g_gcdf[bb][k][c]=(float)cum; g_ghist[bb][k][c]=0.0; }
        if(k==0){ g_mm[bb][0]=0xFFFFFFFFu; g_mm[bb][1]=0u; }
    }
    gridBarrier(128);
    // DM for 9 pixels/thread
    for(int i=0;i<9;i++){
        int idx = blk*256+threadIdx.x + i*32768;
        int bb = idx/NPIX, p = idx%NPIX;
        float X0=g_Lp[idx], X1=g_E[idx], X2=g_S[idx];
        float ra0=g_Ra[(bb*2+0)*NPIX+p], ra1=g_Ra[(bb*2+1)*NPIX+p];
        float ssum = ra0+ra1+2e-8f;
        float DM=0.f;
        for(int kk=0;kk<2;kk++){
            float xm0=X0-(float)vloadd(&g_clmu[bb][kk][0]);
            float xm1=X1-(float)vloadd(&g_clmu[bb][kk][1]);
            float xm2=X2-(float)vloadd(&g_clmu[bb][kk][2]);
            float i0=(float)vloadd(&g_clinv[bb][kk][0]), i1=(float)vloadd(&g_clinv[bb][kk][1]);
            float i2=(float)vloadd(&g_clinv[bb][kk][2]), i4=(float)vloadd(&g_clinv[bb][kk][4]);
            float i5=(float)vloadd(&g_clinv[bb][kk][5]), i8=(float)vloadd(&g_clinv[bb][kk][8]);
            float q = xm0*xm0*i0 + xm1*xm1*i4 + xm2*xm2*i8
                    + 2.f*xm0*xm1*i1 + 2.f*xm0*xm2*i2 + 2.f*xm1*xm2*i5;
            float Dk = sqrtf(q + 1e-8f);
            float Rt = ((kk==0?ra0:ra1)+1e-8f)/ssum;
            DM += Rt*Dk;
        }
        g_DM[idx]=DM;
    }
    // boxH via shared rows: 1536 row jobs, 12 per block
    __shared__ float rowR[WW], rowL[WW];
    for(int j=blk; j<4*HH; j+=128){
        int bk = j/HH, y = j%HH;
        int bb = bk>>1;
        for(int i=threadIdx.x;i<WW;i+=256){
            rowR[i]=g_Ra[bk*NPIX + y*WW + i];
            rowL[i]=g_Lp[bb*NPIX + y*WW + i];
        }
        __syncthreads();
        for(int x=threadIdx.x;x<WW;x+=256){
            float s0=0.f,s1=0.f,s2=0.f;
            int lo2=max(x-7,0), hi2=min(x+7,WW-1);
            for(int xx=lo2;xx<=hi2;xx++){
                float r=rowR[xx], l=rowL[xx];
                s0+=r; s1+=r*l; s2+=r*l*l;
            }
            int p=y*WW+x;
            g_t0[bk*NPIX+p]=s0; g_t1[bk*NPIX+p]=s1; g_t2[bk*NPIX+p]=s2;
        }
        __syncthreads();
    }
    gridBarrier(128);
    // boxV: register-sliding per (plane-col, 24-row segment); 24576 active threads
    int tseg = blk*256 + threadIdx.x;
    if(tseg < 1536*16){
        int seg = tseg/1536, col = tseg%1536;
        int bk = col/WW, x = col%WW;
        int bb = bk>>1;
        int y0 = seg*GTY;
        float s0=0.f,s1=0.f,s2=0.f;
        for(int r=y0-7;r<=y0+6;r++){
            if(r<0||r>=HH) continue;
            int q=r*WW+x;
            s0+=g_t0[bk*NPIX+q]; s1+=g_t1[bk*NPIX+q]; s2+=g_t2[bk*NPIX+q];
        }
        for(int y=y0;y<y0+GTY;y++){
            int ra=y+7;
            if(ra<HH){ int q=ra*WW+x; s0+=g_t0[bk*NPIX+q]; s1+=g_t1[bk*NPIX+q]; s2+=g_t2[bk*NPIX+q]; }
            float cy = (float)(min(y+8,HH)-max(y-7,0));
            float cx = (float)(min(x+8,WW)-max(x-7,0));
            float c = cy*cx;
            float a0=s0/c, a1=s1/c, a2=s2/c;
            float den = a0 + 1e-8f;
            float mu = a1/den;
            float vb = fmaxf(a2/den - mu*mu, 1e-8f);
            int p=y*WW+x;
            g_lla[bk*NPIX+p] = fabsf(g_Lp[bb*NPIX+p]-mu)/(sqrtf(vb)+1e-8f);
            g_den[bk*NPIX+p] = a0;
            int rs=y-7;
            if(rs>=0){ int q=rs*WW+x; s0-=g_t0[bk*NPIX+q]; s1-=g_t1[bk*NPIX+q]; s2-=g_t2[bk*NPIX+q]; }
        }
    }
}

// fused GLD: tiled column histograms in shared (bin-prefix form)
__global__ void __launch_bounds__(128,8) kGLDTile(){
    int bk = blockIdx.z; int b=bk>>1, k=bk&1;
    int strip = blockIdx.x;            // 8 strips of 48 cols
    int y0 = blockIdx.y*GTY;           // 16 segs of 24 rows
    int warp = threadIdx.x>>5, lane = threadIdx.x&31;
    __shared__ float ch[62][32];
    const float* rk = g_Ra + bk*NPIX;
    const unsigned char* bi = g_idxb + b*NPIX;
    int xbase = strip*48 - 7;
    for(int i=threadIdx.x;i<62*32;i+=128) ((float*)ch)[i]=0.f;
    __syncthreads();
    for(int c=warp;c<62;c+=4){
        int x = xbase+c;
        if(x<0||x>=WW) continue;
        float P=0.f;
        for(int r=y0-7;r<=y0+6;r++){
            if(r<0||r>=HH) continue;
            float v=rk[r*WW+x]; int bn=bi[r*WW+x];
            if(lane>=bn) P+=v;
        }
        ch[c][lane]=P;
    }
    float gc = g_gcdf[b][k][lane];
    __syncthreads();
    for(int y=y0;y<y0+GTY;y++){
        int ra=y+7;
        if(ra<HH){
            for(int c=warp;c<62;c+=4){
                int x=xbase+c; if(x<0||x>=WW) continue;
                float v=rk[ra*WW+x]; int bn=bi[ra*WW+x];
                if(lane>=bn) ch[c][lane]+=v;
            }
        }
        __syncthreads();
        {
            int xo0 = warp*12;
            float S=0.f;
            #pragma unroll
            for(int c=0;c<14;c++) S += ch[xo0+c][lane];
            float cy = (float)(min(y+8,HH)-max(y-7,0));
            for(int j=0;j<12;j++){
                int xo = xo0+j;
                S += ch[xo+14][lane];
                int x = strip*48 + xo;
                float cx = (float)(min(x+8,WW)-max(x-7,0));
                float den = g_den[bk*NPIX + y*WW+x] + 1e-8f;
                float diff = fabsf(S/(cy*cx)/den - gc);
                for(int o=16;o;o>>=1) diff += __shfl_down_sync(0xffffffffu,diff,o);
                if(lane==0) g_gld[bk*NPIX + y*WW+x] = diff*(1.f/32.f);
                S -= ch[xo][lane];
            }
        }
        __syncthreads();
        int rs=y-7;
        if(rs>=0){
            for(int c=warp;c<62;c+=4){
                int x=xbase+c; if(x<0||x>=WW) continue;
                float v=rk[rs*WW+x]; int bn=bi[rs*WW+x];
                if(lane>=bn) ch[c][lane]-=v;
            }
        }
        __syncthreads();
    }
}

// LLA/GLD selects + gamma/La + La quantile selects + normalize + resets : 144 x 1024
__global__ void __launch_bounds__(1024,1) kFinalPhase(float* __restrict__ out){
    const int NB = 144;
    coopZero(NB);
    gridBarrier(NB);
    {   // 8 med+MAD jobs x 18 chunks
        int job = blockIdx.x/18, chunk = blockIdx.x%18;
        const int* jb = &g_seljobs[(10+job)*6];
        const float4* src = (const float4*)selSrc(jb[1], jb[2]);
        float med = coopSel(src,0.f,0,(unsigned)jb[3],job,0,chunk,18,NB);
        if(chunk==0&&threadIdx.x==0) g_sv[jb[4]]=med;
        float mad = coopSel(src,med,1,(unsigned)jb[3],job,3,chunk,18,NB);
        if(chunk==0&&threadIdx.x==0) g_sv[jb[5]]=mad;
    }
    gridBarrier(NB);
    // gamma + La (2 elems/thread)
    int gtid = blockIdx.x*1024 + threadIdx.x;
    #pragma unroll
    for(int h=0;h<2;h++){
        int idx = gtid + h*NPIX;
        int b = h, p = gtid;
        float gamma = 1.f;
        for(int k=0;k<2;k++){
            int s = b*2+k;
            float zl = (g_lla[s*NPIX+p]-vloadf(&g_sv[20+s]))/(vloadf(&g_sv[24+s])*1.4826f+1e-8f);
            float zg = (g_gld[s*NPIX+p]-vloadf(&g_sv[28+s]))/(vloadf(&g_sv[32+s])*1.4826f+1e-8f);
            gamma += g_Ra[s*NPIX+p]*(0.5f*softplusf(zl)+0.5f*softplusf(zg));
        }
        float mdE=g_sv[b*3+1], mdS=g_sv[b*3+2];
        float sdE=g_sv[6+b*3+1]*1.4826f+1e-8f, sdS=g_sv[6+b*3+2]*1.4826f+1e-8f;
        float dE=(g_E[idx]-mdE)/sdE-(float)g_esinv[b][3];
        float dS=(g_S[idx]-mdS)/sdS-(float)g_esinv[b][4];
        float d2 = dE*dE*(float)g_esinv[b][0] + 2.f*dE*dS*(float)g_esinv[b][1] + dS*dS*(float)g_esinv[b][2];
        float Rs = expf(-0.5f*d2);
        g_La[idx] = fmaxf(g_DM[idx]*gamma*(1.f-Rs), 0.f);
    }
    coopZero(NB);
    gridBarrier(NB);
    {   // La 1%/99% bracket selects: 4 jobs x 36 chunks
        int job = blockIdx.x/36, chunk = blockIdx.x%36;
        const int* jb = &g_seljobs[(18+job)*6];
        const float4* src = (const float4*)selSrc(jb[1], jb[2]);
        float v0 = coopSel(src,0.f,0,(unsigned)jb[3],job,0,chunk,36,NB);
        if(chunk==0&&threadIdx.x==0) g_sv[jb[4]]=v0;
        float v1 = coopSel(src,0.f,0,(unsigned)jb[3]+1u,job,3,chunk,36,NB);
        if(chunk==0&&threadIdx.x==0) g_sv[jb[5]]=v1;
    }
    gridBarrier(NB);
    #pragma unroll
    for(int h=0;h<2;h++){
        int idx = gtid + h*NPIX;
        int b = h;
        float q1 = vloadf(&g_sv[36+4*b]) + 0.55f*(vloadf(&g_sv[37+4*b])-vloadf(&g_sv[36+4*b]));
        float q9 = vloadf(&g_sv[38+4*b]) + 0.45f*(vloadf(&g_sv[39+4*b])-vloadf(&g_sv[38+4*b]));
        float v = (g_La[idx]-q1)/(q9-q1+1e-8f);
        out[BN + idx] = fminf(fmaxf(v,0.f),1.f);   // output #2
    }
    // resets for next replay
    if(blockIdx.x==0 && threadIdx.x<10) ((double*)g_reg)[threadIdx.x]=0.0;
}

// ======================= host =======================
extern "C" void kernel_launch(void* const* d_in, const int* in_sizes, int n_in,
                              void* d_out, int out_size){
    const float* lab   = (const float*)d_in[0];
    const float* arand = (const float*)d_in[1];
    float* out = (float*)d_out;

    kSobelE<<<dim3(24,24,BB),256>>>(lab);
    kLperp<<<1152,256>>>(lab,out);
    kSelA<<<144,1024>>>();
    kWhiten<<<128,256>>>(arand);
    kPhaseZEM<<<144,1024>>>();
    kClusterDM<<<128,256>>>();
    kGLDTile<<<dim3(8,16,4),128>>>();
    kFinalPhase<<<144,1024>>>(out);
}

// round 12
// speedup vs baseline: 1.4365x; 1.2477x over previous
#include <cuda_runtime.h>
#include <math.h>

#define HH 384
#define WW 384
#define NPIX (HH*WW)          // 147456
#define BB 2
#define BN (BB*NPIX)          // 294912
#define NDIR 128
#define GTY 24

// ======================= scratch buffers =======================
__device__ float g_E[BN];
__device__ float g_S[BN];
__device__ float g_Lp[BN];
__device__ float g_zb[BN];
__device__ float g_Ra[2*BN];     // [(b*2+k)*NPIX+n]
__device__ float g_DM[BN];
__device__ float g_t0[2*BN], g_t1[2*BN], g_t2[2*BN];
__device__ float g_lla[2*BN];
__device__ float g_den[2*BN];
__device__ float g_gld[2*BN];
__device__ float g_La[BN];
__device__ unsigned char g_idxb[BN];
__device__ unsigned g_jh[8*6*2048];     // cooperative select histograms

// ======================= small state =======================
__device__ float    g_sv[64];
__device__ unsigned g_mm[BB][2] = {{0xFFFFFFFFu,0u},{0xFFFFFFFFu,0u}};
__device__ double   g_reg[BB][5];
__device__ double   g_cacc[BB][9];
__device__ double   g_mean3[BB][3];
__device__ double   g_wwh[BB][9];
__device__ float    g_cdir[BB*NDIR*3];
__device__ float    g_cbest[BB][3];
__device__ double   g_dirm[BB][NDIR][4];
__device__ double   g_emacc2[9][BB][6];
__device__ double   g_clacc[BB][2][10];
__device__ double   g_clmu[BB][2][3];
__device__ double   g_clinv[BB][2][9];
__device__ double   g_ghist[BB][2][32];
__device__ float    g_gcdf[BB][2][32];
__device__ double   g_esinv[BB][6];

// grid-wide barrier (monotonic generation; arrive self-resets)
__device__ int g_barArrive = 0;
__device__ int g_barGen = 0;

static __device__ __forceinline__ void gridBarrier(int nb){
    __threadfence();
    __syncthreads();
    if(threadIdx.x==0){
        int gen = *(volatile int*)&g_barGen;
        if(atomicAdd(&g_barArrive,1)==nb-1){
            g_barArrive = 0;
            __threadfence();
            *(volatile int*)&g_barGen = gen+1;
        } else {
            while(*(volatile int*)&g_barGen == gen) { }
        }
    }
    __syncthreads();
}

static __device__ __forceinline__ double vloadd(const double* p){ return *(volatile const double*)p; }
static __device__ __forceinline__ float  vloadf(const float* p){ return *(volatile const float*)p; }

// ======================= helpers =======================
static __device__ __forceinline__ unsigned f2u(float f){
    unsigned u = __float_as_uint(f);
    return (u & 0x80000000u) ? ~u : (u | 0x80000000u);
}
static __device__ __forceinline__ float u2f(unsigned u){
    unsigned v = (u & 0x80000000u) ? (u & 0x7FFFFFFFu) : ~u;
    return __uint_as_float(v);
}
static __device__ __forceinline__ float softplusf(float x){
    float t = log1pf(expf(-fabsf(x)));
    return x >= 0.f ? x + t : t;
}
static __device__ double blockReduceD(double v){
    __shared__ double sh[32];
    int lane = threadIdx.x & 31, wid = threadIdx.x >> 5;
    for (int o=16;o;o>>=1) v += __shfl_down_sync(0xffffffffu, v, o);
    if (lane==0) sh[wid] = v;
    __syncthreads();
    int nw = (blockDim.x + 31) >> 5;
    v = (threadIdx.x < nw) ? sh[threadIdx.x] : 0.0;
    if (wid==0) for (int o=16;o;o>>=1) v += __shfl_down_sync(0xffffffffu, v, o);
    __syncthreads();
    return v;
}
// 3x3 symmetric Jacobi eigh with RELATIVE convergence (R11 fix: the old
// 1e-300 absolute threshold never fired -> always 40 serial double sweeps
// on one thread ~ 270us. Quadratic convergence: ~4-5 sweeps to 1e-14.)
static __device__ void eigh3(const double* A, double* e, double* V){
    double a[9]; for(int i=0;i<9;i++) a[i]=A[i];
    for(int i=0;i<9;i++) V[i] = (i%4==0)?1.0:0.0;
    double scale = fabs(A[0])+fabs(A[4])+fabs(A[8]) + 1e-300;
    for(int sweep=0; sweep<15; sweep++){
        double off = fabs(a[1])+fabs(a[2])+fabs(a[5]);
        if(off <= 1e-14*scale) break;
        for(int p=0;p<2;p++) for(int q=p+1;q<3;q++){
            double apq=a[p*3+q];
            if(fabs(apq) <= 1e-16*scale) continue;
            double app=a[p*3+p], aqq=a[q*3+q];
            double th=(aqq-app)/(2.0*apq);
            double t=(th>=0?1.0:-1.0)/(fabs(th)+sqrt(th*th+1.0));
            double c=1.0/sqrt(t*t+1.0), s=t*c;
            for(int i=0;i<3;i++){ double x=a[i*3+p],y=a[i*3+q]; a[i*3+p]=c*x-s*y; a[i*3+q]=s*x+c*y; }
            for(int i=0;i<3;i++){ double x=a[p*3+i],y=a[q*3+i]; a[p*3+i]=c*x-s*y; a[q*3+i]=s*x+c*y; }
            for(int i=0;i<3;i++){ double x=V[i*3+p],y=V[i*3+q]; V[i*3+p]=c*x-s*y; V[i*3+q]=s*x+c*y; }
        }
    }
    e[0]=a[0]; e[1]=a[4]; e[2]=a[8];
}
static __device__ void inv3(const double* m, double* inv){
    double a=m[0],b=m[1],c=m[2],d=m[3],e=m[4],f=m[5],g=m[6],h=m[7],i=m[8];
    double A=e*i-f*h, B=c*h-b*i, C=b*f-c*e;
    double D=f*g-d*i, E=a*i-c*g, F=c*d-a*f;
    double G=d*h-e*g, Hh=b*g-a*h, I=a*e-b*d;
    double det=a*A+b*D+c*G, id=1.0/det;
    inv[0]=A*id; inv[1]=B*id; inv[2]=C*id;
    inv[3]=D*id; inv[4]=E*id; inv[5]=F*id;
    inv[6]=G*id; inv[7]=Hh*id; inv[8]=I*id;
}

// ======================= cooperative radix select =======================
// jobs: {kind, type, b, rank, slotA, slotB}
__device__ const int g_seljobs[22*6] = {
 0,0,0,73727,0,6,   0,1,0,73727,1,7,   0,2,0,73727,2,8,
 0,0,1,73727,3,9,   0,1,1,73727,4,10,  0,2,1,73727,5,11,
 1,3,0,36863,12,13,  1,3,0,110591,14,15,  1,3,1,36863,16,17,  1,3,1,110591,18,19,
 0,4,0,73727,20,24,  0,5,0,73727,21,25,  0,4,1,73727,22,26,  0,5,1,73727,23,27,
 0,6,0,73727,28,32,  0,7,0,73727,29,33,  0,6,1,73727,30,34,  0,7,1,73727,31,35,
 1,8,0,1474,36,37,  1,8,0,145980,38,39,  1,8,1,1474,40,41,  1,8,1,145980,42,43
};

static __device__ const float* selSrc(int type, int b){
    switch(type){
        case 0: return g_Lp + b*NPIX;
        case 1: return g_E  + b*NPIX;
        case 2: return g_S  + b*NPIX;
        case 3: return g_zb + b*NPIX;
        case 4: return g_lla + (b*2+0)*NPIX;
        case 5: return g_lla + (b*2+1)*NPIX;
        case 6: return g_gld + (b*2+0)*NPIX;
        case 7: return g_gld + (b*2+1)*NPIX;
        default: return g_La + b*NPIX;
    }
}

static __device__ void coopZero(int nbTot){
    int total = 8*6*2048;
    for(int i=blockIdx.x*blockDim.x+threadIdx.x; i<total; i+=nbTot*blockDim.x)
        g_jh[i]=0u;
}

// 3-pass (11/11/10 bit) cooperative select across ncs blocks per job.
static __device__ float coopSel(const float4* __restrict__ src4, float ref, int useAbs, unsigned rank,
                                int jobLocal, int passBase, int chunk, int ncs, int nbTot){
    __shared__ unsigned sh[2048];
    __shared__ unsigned sres[2];
    unsigned pref=0, rk=rank;
    for(int pass=0; pass<3; pass++){
        unsigned* hist = g_jh + (jobLocal*6+passBase+pass)*2048;
        int nbin = (pass==2)?1024:2048;
        for(int i=threadIdx.x;i<nbin;i+=blockDim.x) sh[i]=0u;
        __syncthreads();
        int per = (NPIX/4)/ncs;
        int lo = chunk*per;
        for(int i=lo+threadIdx.x;i<lo+per;i+=blockDim.x){
            float4 v4 = src4[i];
            float vv[4]={v4.x,v4.y,v4.z,v4.w};
            #pragma unroll
            for(int c=0;c<4;c++){
                float v=vv[c]; if(useAbs) v=fabsf(v-ref);
                unsigned key=f2u(v);
                if(pass==0) atomicAdd(&sh[key>>21],1u);
                else if(pass==1){ if((key>>21)==(pref>>21)) atomicAdd(&sh[(key>>10)&2047u],1u); }
                else { if((key>>10)==(pref>>10)) atomicAdd(&sh[key&1023u],1u); }
            }
        }
        __syncthreads();
        for(int i=threadIdx.x;i<nbin;i+=blockDim.x) if(sh[i]) atomicAdd(&hist[i],sh[i]);
        gridBarrier(nbTot);
        if(threadIdx.x<32){
            int lane=threadIdx.x, perl=nbin>>5;
            unsigned s=0;
            for(int i=0;i<perl;i++) s+=hist[lane*perl+i];
            unsigned cum=s;
            #pragma unroll
            for(int o=1;o<32;o<<=1){ unsigned t=__shfl_up_sync(0xffffffffu,cum,o); if(lane>=o) cum+=t; }
            unsigned prev=cum-s;
            if(prev<=rk && rk<cum){
                unsigned rr=rk-prev; int bin=lane*perl;
                for(int i=0;i<perl;i++){ unsigned c=hist[lane*perl+i]; if(rr<c){ bin=lane*perl+i; break;} rr-=c; }
                sres[0]=(pass==0)? ((unsigned)bin<<21) : (pass==1)? (pref|((unsigned)bin<<10)) : (pref|(unsigned)bin);
                sres[1]=rr;
            }
        }
        __syncthreads();
        pref=sres[0]; rk=sres[1];
        __syncthreads();
    }
    return u2f(pref);
}

// ======================= pipeline kernels =======================
// fused Sobel + avg3 + regression accumulation, tiled in shared memory
__global__ void __launch_bounds__(256) kSobelE(const float* __restrict__ lab){
    __shared__ float sL[20][20];
    __shared__ float sP[18][18];
    int b = blockIdx.z;
    int x0 = blockIdx.x*16, y0 = blockIdx.y*16;
    int tid = threadIdx.x;
    int tx = tid & 15, ty = tid >> 4;
    const float* L = lab + (size_t)b*3*NPIX;
    for(int i=tid;i<400;i+=256){
        int jj=i/20, ii=i%20;
        int yy=y0-2+jj, xx=x0-2+ii;
        sL[jj][ii] = (yy>=0&&yy<HH&&xx>=0&&xx<WW) ? L[yy*WW+xx] : 0.f;
    }
    __syncthreads();
    for(int i=tid;i<324;i+=256){
        int jj=i/18, ii=i%18;
        int py=y0-1+jj, px=x0-1+ii;
        float v=0.f;
        if(py>=0&&py<HH&&px>=0&&px<WW){
            float l00=sL[jj][ii],   l01=sL[jj][ii+1],   l02=sL[jj][ii+2];
            float l10=sL[jj+1][ii],                     l12=sL[jj+1][ii+2];
            float l20=sL[jj+2][ii], l21=sL[jj+2][ii+1], l22=sL[jj+2][ii+2];
            float gx = -l00 + l02 - 2.f*l10 + 2.f*l12 - l20 + l22;
            float gy = -l00 - 2.f*l01 - l02 + l20 + 2.f*l21 + l22;
            v = gx*gx + gy*gy;
        }
        sP[jj][ii]=v;
    }
    __syncthreads();
    int y=y0+ty, x=x0+tx;
    int p = y*WW+x, idx = b*NPIX+p;
    float s = sP[ty][tx]  +sP[ty][tx+1]  +sP[ty][tx+2]
            + sP[ty+1][tx]+sP[ty+1][tx+1]+sP[ty+1][tx+2]
            + sP[ty+2][tx]+sP[ty+2][tx+1]+sP[ty+2][tx+2];
    float E = s/9.f;
    float av = L[NPIX+p], bv = L[2*NPIX+p];
    float S = sqrtf(av*av+bv*bv+1e-8f);
    g_E[idx]=E; g_S[idx]=S;
    double e=E, sv=S, l=L[p];
    double r;
    r=blockReduceD(e*e);  if(tid==0) atomicAdd(&g_reg[b][0],r);
    r=blockReduceD(e*sv); if(tid==0) atomicAdd(&g_reg[b][1],r);
    r=blockReduceD(sv*sv);if(tid==0) atomicAdd(&g_reg[b][2],r);
    r=blockReduceD(e*l);  if(tid==0) atomicAdd(&g_reg[b][3],r);
    r=blockReduceD(sv*l); if(tid==0) atomicAdd(&g_reg[b][4],r);
}

// L_perp (per-block inline 2x2 solve) + fused global min/max
__global__ void __launch_bounds__(256) kLperp(const float* __restrict__ lab, float* __restrict__ out){
    __shared__ float sb0, sb1;
    int idx = blockIdx.x*blockDim.x + threadIdx.x;
    int b = idx / NPIX, p = idx % NPIX;
    if(threadIdx.x==0){
        double ee=g_reg[b][0]+1e-6, es=g_reg[b][1], ss=g_reg[b][2]+1e-6;
        double el=g_reg[b][3], sl=g_reg[b][4];
        double det = ee*ss - es*es;
        sb0 = (float)((ss*el - es*sl)/det);
        sb1 = (float)((ee*sl - es*el)/det);
    }
    __syncthreads();
    float v = lab[(size_t)b*3*NPIX+p] - sb0*g_E[idx] - sb1*g_S[idx];
    g_Lp[idx] = v;
    out[idx] = v;   // output #1
    unsigned k = f2u(v);
    __shared__ unsigned smn[256], smx[256];
    smn[threadIdx.x]=k; smx[threadIdx.x]=k;
    __syncthreads();
    for(int o=128;o>0;o>>=1){
        if(threadIdx.x<o){ smn[threadIdx.x]=min(smn[threadIdx.x],smn[threadIdx.x+o]);
                           smx[threadIdx.x]=max(smx[threadIdx.x],smx[threadIdx.x+o]); }
        __syncthreads();
    }
    if(threadIdx.x==0){ atomicMin(&g_mm[b][0],smn[0]); atomicMax(&g_mm[b][1],smx[0]); }
}

// phase A: med+MAD of Lp,E,S for both batches; 6 jobs x 24 chunks = 144 blocks
__global__ void __launch_bounds__(1024,1) kSelA(){
    const int NB = 144;
    int job = blockIdx.x/24, chunk = blockIdx.x%24;
    coopZero(NB);
    gridBarrier(NB);
    const int* jb = &g_seljobs[job*6];
    const float4* src = (const float4*)selSrc(jb[1], jb[2]);
    float med = coopSel(src,0.f,0,(unsigned)jb[3],job,0,chunk,24,NB);
    if(chunk==0&&threadIdx.x==0) g_sv[jb[4]]=med;
    float mad = coopSel(src,med,1,(unsigned)jb[3],job,3,chunk,24,NB);
    if(chunk==0&&threadIdx.x==0) g_sv[jb[5]]=mad;
}

// cov-acc + eigh/ESinv/cdir + kurt-acc + parallel pick : ONE kernel, 128 blocks x 256
__global__ void __launch_bounds__(256) kWhiten(const float* __restrict__ arand){
    int blk = blockIdx.x;
    int b = blk>>6, chunk = blk&63;
    float md[3], sd[3];
    for(int f=0;f<3;f++){ md[f]=g_sv[b*3+f]; sd[f]=g_sv[6+b*3+f]*1.4826f+1e-8f; }
    int base = b*NPIX + chunk*2304;
    float z0[9], z1[9], z2[9];
    double a[9]={0,0,0,0,0,0,0,0,0};
    #pragma unroll
    for(int i=0;i<9;i++){
        int p = base + i*256 + threadIdx.x;
        float u0=(g_Lp[p]-md[0])/sd[0];
        float u1=(g_E [p]-md[1])/sd[1];
        float u2=(g_S [p]-md[2])/sd[2];
        z0[i]=u0; z1[i]=u1; z2[i]=u2;
        a[0]+=u0; a[1]+=u1; a[2]+=u2;
        a[3]+=(double)u0*u0; a[4]+=(double)u0*u1; a[5]+=(double)u0*u2;
        a[6]+=(double)u1*u1; a[7]+=(double)u1*u2; a[8]+=(double)u2*u2;
    }
    for(int m=0;m<9;m++){ double r=blockReduceD(a[m]); if(threadIdx.x==0) atomicAdd(&g_cacc[b][m],r); }
    gridBarrier(128);
    if(blk==0){
        int t = threadIdx.x;
        if(t<BB){
            int bb = t;
            double N = (double)NPIX;
            double mu[3]; for(int i=0;i<3;i++){ mu[i]=vloadd(&g_cacc[bb][i])/N; g_mean3[bb][i]=mu[i]; }
            double C[9];
            C[0]=vloadd(&g_cacc[bb][3])/N-mu[0]*mu[0]; C[1]=vloadd(&g_cacc[bb][4])/N-mu[0]*mu[1]; C[2]=vloadd(&g_cacc[bb][5])/N-mu[0]*mu[2];
            C[4]=vloadd(&g_cacc[bb][6])/N-mu[1]*mu[1]; C[5]=vloadd(&g_cacc[bb][7])/N-mu[1]*mu[2]; C[8]=vloadd(&g_cacc[bb][8])/N-mu[2]*mu[2];
            C[3]=C[1]; C[6]=C[2]; C[7]=C[5];
            {
                double c00=C[4]+1e-6, c01=C[5], c11=C[8]+1e-6;
                double det=c00*c11-c01*c01;
                g_esinv[bb][0]=c11/det; g_esinv[bb][1]=-c01/det; g_esinv[bb][2]=c00/det;
                g_esinv[bb][3]=mu[1]; g_esinv[bb][4]=mu[2];
            }
            for(int i=0;i<9;i++) C[i] = C[i] > 1e-8 ? C[i] : 1e-8;   // elementwise max (matches ref)
            double e[3], V[9];
            eigh3(C, e, V);
            for(int i=0;i<3;i++) for(int j=0;j<3;j++){
                double ssum=0; for(int k2=0;k2<3;k2++) ssum += V[i*3+k2]*(1.0/sqrt(e[k2]))*V[j*3+k2];
                g_wwh[bb][i*3+j]=ssum;
            }
            for(int i=0;i<9;i++) g_cacc[bb][i]=0.0;
        }
        __syncthreads();
        {
            int t2 = threadIdx.x;       // 256 threads = BB*NDIR
            int bb = t2 / NDIR, d = t2 % NDIR;
            float a0=arand[(bb*NDIR+d)*3+0], a1=arand[(bb*NDIR+d)*3+1], a2=arand[(bb*NDIR+d)*3+2];
            float nr = sqrtf(a0*a0+a1*a1+a2*a2) + 1e-12f;
            double an[3]={a0/nr,a1/nr,a2/nr};
            for(int jj=0;jj<3;jj++){
                double ssum=0; for(int i=0;i<3;i++) ssum += g_wwh[bb][jj*3+i]*an[i];
                g_cdir[(bb*NDIR+d)*3+jj]=(float)ssum;
            }
        }
    }
    gridBarrier(128);
    // kurt phase: reuse cached z arrays
    __shared__ float scd[NDIR*3];
    __shared__ float sacc[NDIR*4];
    for(int i=threadIdx.x;i<NDIR*3;i+=256) scd[i]=vloadf(&g_cdir[b*NDIR*3+i]);
    for(int i=threadIdx.x;i<NDIR*4;i+=256) sacc[i]=0.f;
    float mn0=(float)vloadd(&g_mean3[b][0]), mn1=(float)vloadd(&g_mean3[b][1]), mn2=(float)vloadd(&g_mean3[b][2]);
    #pragma unroll
    for(int i=0;i<9;i++){ z0[i]-=mn0; z1[i]-=mn1; z2[i]-=mn2; }
    __syncthreads();
    int lane = threadIdx.x & 31;
    for(int d=0;d<NDIR;d++){
        float c0=scd[d*3], c1=scd[d*3+1], c2=scd[d*3+2];
        float s1=0,s2=0,s3=0,s4=0;
        #pragma unroll
        for(int i=0;i<9;i++){
            float z=z0[i]*c0+z1[i]*c1+z2[i]*c2;
            float zz=z*z;
            s1+=z; s2+=zz; s3+=zz*z; s4+=zz*zz;
        }
        for(int o=16;o;o>>=1){
            s1+=__shfl_down_sync(0xffffffffu,s1,o); s2+=__shfl_down_sync(0xffffffffu,s2,o);
            s3+=__shfl_down_sync(0xffffffffu,s3,o); s4+=__shfl_down_sync(0xffffffffu,s4,o);
        }
        if(lane==0){
            atomicAdd(&sacc[d*4+0],s1); atomicAdd(&sacc[d*4+1],s2);
            atomicAdd(&sacc[d*4+2],s3); atomicAdd(&sacc[d*4+3],s4);
        }
    }
    __syncthreads();
    for(int i=threadIdx.x;i<NDIR*4;i+=256)
        atomicAdd(&((double*)g_dirm)[b*NDIR*4+i], (double)sacc[i]);
    gridBarrier(128);
    if(blk==0){
        __shared__ double skv[256];
        __shared__ int sdi[256];
        int t = threadIdx.x;
        int bb = t>>7, d = t&127;
        double N=(double)NPIX;
        double m1=vloadd(&g_dirm[bb][d][0])/N, s2=vloadd(&g_dirm[bb][d][1])/N;
        double s3=vloadd(&g_dirm[bb][d][2])/N, s4=vloadd(&g_dirm[bb][d][3])/N;
        double m2=(s2-m1*m1)+1e-12;
        double m4=s4-4.0*m1*s3+6.0*m1*m1*s2-3.0*m1*m1*m1*m1;
        skv[t]=fabs(m4/(m2*m2)-3.0); sdi[t]=d;
        __syncthreads();
        for(int o=64;o;o>>=1){
            if((t&127)<o){
                if(skv[t+o]>skv[t] || (skv[t+o]==skv[t] && sdi[t+o]<sdi[t])){ skv[t]=skv[t+o]; sdi[t]=sdi[t+o]; }
            }
            __syncthreads();
        }
        if((t&127)==0){
            int best=sdi[t];
            for(int j=0;j<3;j++) g_cbest[t>>7][j]=vloadf(&g_cdir[((t>>7)*NDIR+best)*3+j]);
        }
        __syncthreads();
        // reset dirm (1024 doubles)
        for(int i=t;i<BB*NDIR*4;i+=256) ((double*)g_dirm)[i]=0.0;
    }
}

// phase Z + EM fused: zb compute, quartile-bracket selects, 9 EM iters, Ra.  144 x 1024
__global__ void __launch_bounds__(1024,1) kPhaseZEM(){
    const int NB = 144;
    int gtid = blockIdx.x*1024 + threadIdx.x;     // < 147456
    // zb for both batches
    #pragma unroll
    for(int h=0;h<2;h++){
        int idx = gtid + h*NPIX;
        int b = h;
        float md0=g_sv[b*3+0], md1=g_sv[b*3+1], md2=g_sv[b*3+2];
        float sd0=g_sv[6+b*3+0]*1.4826f+1e-8f, sd1=g_sv[6+b*3+1]*1.4826f+1e-8f, sd2=g_sv[6+b*3+2]*1.4826f+1e-8f;
        float d0=(g_Lp[idx]-md0)/sd0-(float)g_mean3[b][0];
        float d1=(g_E [idx]-md1)/sd1-(float)g_mean3[b][1];
        float d2=(g_S [idx]-md2)/sd2-(float)g_mean3[b][2];
        g_zb[idx] = d0*g_cbest[b][0]+d1*g_cbest[b][1]+d2*g_cbest[b][2];
    }
    coopZero(NB);
    {   // zero EM accumulators for this replay
        double* acc = (double*)g_emacc2;
        int tot = 9*BB*6;
        for(int i=blockIdx.x*1024+threadIdx.x; i<tot; i+=NB*1024) acc[i]=0.0;
    }
    gridBarrier(NB);
    // quartile-bracket selects: 4 jobs x 36 chunks
    {
        int job = blockIdx.x/36, chunk = blockIdx.x%36;
        const int* jb = &g_seljobs[(6+job)*6];
        const float4* src = (const float4*)selSrc(jb[1], jb[2]);
        float v0 = coopSel(src,0.f,0,(unsigned)jb[3],job,0,chunk,36,NB);
        if(chunk==0&&threadIdx.x==0) g_sv[jb[4]]=v0;
        float v1 = coopSel(src,0.f,0,(unsigned)jb[3]+1u,job,3,chunk,36,NB);
        if(chunk==0&&threadIdx.x==0) g_sv[jb[5]]=v1;
    }
    gridBarrier(NB);
    // EM: blocks 0..71 -> batch0, 72..143 -> batch1; 2 elems per thread
    int b = blockIdx.x/72, sub = blockIdx.x%72;
    int baseRel = sub*2048 + threadIdx.x;
    float x0 = g_zb[b*NPIX + baseRel], x1 = g_zb[b*NPIX + baseRel + 1024];
    float q25 = vloadf(&g_sv[12+4*b]) + 0.75f*(vloadf(&g_sv[13+4*b])-vloadf(&g_sv[12+4*b]));
    float q75 = vloadf(&g_sv[14+4*b]) + 0.25f*(vloadf(&g_sv[15+4*b])-vloadf(&g_sv[14+4*b]));
    double mu0=q25, mu1=q75, var0=1.0, var1=1.0, pi0=0.5, pi1=0.5;
    for(int it=0; it<9; it++){
        float m0=(float)mu0, m1=(float)mu1;
        float v0=(float)var0+1e-6f, v1=(float)var1+1e-6f;
        float lw0=-0.5f*logf(v0)+logf((float)pi0+1e-8f);
        float lw1=-0.5f*logf(v1)+logf((float)pi1+1e-8f);
        float iv0=0.5f/v0, iv1=0.5f/v1;
        float a0=0,a1=0,a2=0,a3=0,a4=0,a5=0;
        #pragma unroll
        for(int i=0;i<2;i++){
            float xx = (i==0)?x0:x1;
            float lp0=-(xx-m0)*(xx-m0)*iv0+lw0;
            float lp1=-(xx-m1)*(xx-m1)*iv1+lw1;
            float R0=1.f/(1.f+expf(lp1-lp0));
            float R1=1.f/(1.f+expf(lp0-lp1));
            a0+=R0; a1+=R0*xx; a2+=R0*xx*xx;
            a3+=R1; a4+=R1*xx; a5+=R1*xx*xx;
        }
        double s[6]={a0,a1,a2,a3,a4,a5};
        for(int m=0;m<6;m++){
            double r=blockReduceD(s[m]);
            if(threadIdx.x==0) atomicAdd(&g_emacc2[it][b][m],r);
        }
        gridBarrier(NB);
        {
            double Sr0=vloadd(&g_emacc2[it][b][0]), Sx0=vloadd(&g_emacc2[it][b][1]), Sxx0=vloadd(&g_emacc2[it][b][2]);
            double Sr1=vloadd(&g_emacc2[it][b][3]), Sx1=vloadd(&g_emacc2[it][b][4]), Sxx1=vloadd(&g_emacc2[it][b][5]);
            double den0=Sr0+1e-8; mu0=Sx0/den0;
            var0=(Sxx0-2.0*mu0*Sx0+mu0*mu0*Sr0)/den0+1e-6; pi0=Sr0/(double)NPIX;
            double den1=Sr1+1e-8; mu1=Sx1/den1;
            var1=(Sxx1-2.0*mu1*Sx1+mu1*mu1*Sr1)/den1+1e-6; pi1=Sr1/(double)NPIX;
        }
    }
    {
        float m0=(float)mu0, m1=(float)mu1;
        float v0=(float)var0+1e-6f, v1=(float)var1+1e-6f;
        float lw0=-0.5f*logf(v0)+logf((float)pi0+1e-8f);
        float lw1=-0.5f*logf(v1)+logf((float)pi1+1e-8f);
        float iv0=0.5f/v0, iv1=0.5f/v1;
        #pragma unroll
        for(int i=0;i<2;i++){
            float xx = (i==0)?x0:x1;
            int p = baseRel + i*1024;          // batch-relative plane offset
            float lp0=-(xx-m0)*(xx-m0)*iv0+lw0;
            float lp1=-(xx-m1)*(xx-m1)*iv1+lw1;
            float R0=1.f/(1.f+expf(lp1-lp0));
            float R1=1.f/(1.f+expf(lp0-lp1));
            float r0=powf(R0,0.9f), r1=powf(R1,0.9f);
            float ssum=r0+r1+1e-8f;
            g_Ra[(b*2+0)*NPIX+p]=r0/ssum;
            g_Ra[(b*2+1)*NPIX+p]=r1/ssum;
        }
    }
}

// cluster moments + binidx + ghist -> inverses+gcdf -> DM + boxH(shared rows) -> boxV(sliding)
__global__ void __launch_bounds__(256) kClusterDM(){
    int blk = blockIdx.x;              // 128
    int b = blk>>6, chunk = blk&63;
    __shared__ float sh64[64];
    if(threadIdx.x<64) sh64[threadIdx.x]=0.f;
    __syncthreads();
    float mn = u2f(g_mm[b][0]), mx = u2f(g_mm[b][1]);
    float inv_rng = 1.f/(mx-mn+1e-8f);
    double a[20];
    for(int i=0;i<20;i++) a[i]=0.0;
    int lo = chunk*2304, hi = lo+2304;
    for(int p=lo+threadIdx.x;p<hi;p+=256){
        float w0=g_Ra[(b*2+0)*NPIX+p], w1=g_Ra[(b*2+1)*NPIX+p];
        float lpv=g_Lp[b*NPIX+p];
        double x0=lpv, x1=g_E[b*NPIX+p], x2=g_S[b*NPIX+p];
        a[0]+=w0; a[1]+=w0*x0; a[2]+=w0*x1; a[3]+=w0*x2;
        a[4]+=w0*x0*x0; a[5]+=w0*x0*x1; a[6]+=w0*x0*x2;
        a[7]+=w0*x1*x1; a[8]+=w0*x1*x2; a[9]+=w0*x2*x2;
        a[10]+=w1; a[11]+=w1*x0; a[12]+=w1*x1; a[13]+=w1*x2;
        a[14]+=w1*x0*x0; a[15]+=w1*x0*x1; a[16]+=w1*x0*x2;
        a[17]+=w1*x1*x1; a[18]+=w1*x1*x2; a[19]+=w1*x2*x2;
        float ln = (lpv-mn)*inv_rng;
        ln = fminf(fmaxf(ln,0.f),1.f);
        int c = (int)(ln*32.f); c = c<0?0:(c>31?31:c);
        g_idxb[b*NPIX+p] = (unsigned char)c;
        atomicAdd(&sh64[c],    w0);
        atomicAdd(&sh64[32+c], w1);
    }
    for(int m=0;m<20;m++){
        double r=blockReduceD(a[m]);
        if(threadIdx.x==0) atomicAdd(&g_clacc[b][m/10][m%10],r);
    }
    __syncthreads();
    if(threadIdx.x<64 && sh64[threadIdx.x]!=0.f)
        atomicAdd(&g_ghist[b][threadIdx.x>>5][threadIdx.x&31],(double)sh64[threadIdx.x]);
    gridBarrier(128);
    if(blk==0 && threadIdx.x<4){
        int t = threadIdx.x;
        int bb=t>>1, k=t&1;
        double A[10];
        for(int i=0;i<10;i++) A[i]=vloadd(&g_clacc[bb][k][i]);
        double Ws = A[0] + 1e-8;
        double mu[3] = {A[1]/Ws, A[2]/Ws, A[3]/Ws};
        double Sx[3] = {A[1], A[2], A[3]};
        double Sxx[9] = {A[4],A[5],A[6], A[5],A[7],A[8], A[6],A[8],A[9]};
        double C[9];
        for(int i=0;i<3;i++) for(int j2=0;j2<3;j2++)
            C[i*3+j2] = (Sxx[i*3+j2] - mu[i]*Sx[j2] - mu[j2]*Sx[i] + A[0]*mu[i]*mu[j2])/Ws + ((i==j2)?1e-6:0.0);
        double I[9]; inv3(C, I);
        for(int i=0;i<9;i++) g_clinv[bb][k][i]=I[i];
        for(int i=0;i<3;i++) g_clmu[bb][k][i]=mu[i];
        for(int i=0;i<10;i++) g_clacc[bb][k][i]=0.0;
        double tot=0; for(int c=0;c<32;c++) tot += vloadd(&g_ghist[bb][k][c]);
        double cum=0;
        for(int c=0;c<32;c++){ cum += vloadd(&g_ghist[bb][k][c])/(tot+1e-8); g_gcdf[bb][k][c]=(float)cum; g_ghist[bb][k][c]=0.0; }
        if(k==0){ g_mm[bb][0]=0xFFFFFFFFu; g_mm[bb][1]=0u; }
    }
    gridBarrier(128);
    // DM for 9 pixels/thread
    for(int i=0;i<9;i++){
        int idx = blk*256+threadIdx.x + i*32768;
        int bb = idx/NPIX, p = idx%NPIX;
        float X0=g_Lp[idx], X1=g_E[idx], X2=g_S[idx];
        float ra0=g_Ra[(bb*2+0)*NPIX+p], ra1=g_Ra[(bb*2+1)*NPIX+p];
        float ssum = ra0+ra1+2e-8f;
        float DM=0.f;
        for(int kk=0;kk<2;kk++){
            float xm0=X0-(float)vloadd(&g_clmu[bb][kk][0]);
            float xm1=X1-(float)vloadd(&g_clmu[bb][kk][1]);
            float xm2=X2-(float)vloadd(&g_clmu[bb][kk][2]);
            float i0=(float)vloadd(&g_clinv[bb][kk][0]), i1=(float)vloadd(&g_clinv[bb][kk][1]);
            float i2=(float)vloadd(&g_clinv[bb][kk][2]), i4=(float)vloadd(&g_clinv[bb][kk][4]);
            float i5=(float)vloadd(&g_clinv[bb][kk][5]), i8=(float)vloadd(&g_clinv[bb][kk][8]);
            float q = xm0*xm0*i0 + xm1*xm1*i4 + xm2*xm2*i8
                    + 2.f*xm0*xm1*i1 + 2.f*xm0*xm2*i2 + 2.f*xm1*xm2*i5;
            float Dk = sqrtf(q + 1e-8f);
            float Rt = ((kk==0?ra0:ra1)+1e-8f)/ssum;
            DM += Rt*Dk;
        }
        g_DM[idx]=DM;
    }
    // boxH via shared rows: 1536 row jobs, 12 per block
    __shared__ float rowR[WW], rowL[WW];
    for(int j=blk; j<4*HH; j+=128){
        int bk = j/HH, y = j%HH;
        int bb = bk>>1;
        for(int i=threadIdx.x;i<WW;i+=256){
            rowR[i]=g_Ra[bk*NPIX + y*WW + i];
            rowL[i]=g_Lp[bb*NPIX + y*WW + i];
        }
        __syncthreads();
        for(int x=threadIdx.x;x<WW;x+=256){
            float s0=0.f,s1=0.f,s2=0.f;
            int lo2=max(x-7,0), hi2=min(x+7,WW-1);
            for(int xx=lo2;xx<=hi2;xx++){
                float r=rowR[xx], l=rowL[xx];
                s0+=r; s1+=r*l; s2+=r*l*l;
            }
            int p=y*WW+x;
            g_t0[bk*NPIX+p]=s0; g_t1[bk*NPIX+p]=s1; g_t2[bk*NPIX+p]=s2;
        }
        __syncthreads();
    }
    gridBarrier(128);
    // boxV: register-sliding per (plane-col, 24-row segment); 24576 active threads
    int tseg = blk*256 + threadIdx.x;
    if(tseg < 1536*16){
        int seg = tseg/1536, col = tseg%1536;
        int bk = col/WW, x = col%WW;
        int bb = bk>>1;
        int y0 = seg*GTY;
        float s0=0.f,s1=0.f,s2=0.f;
        for(int r=y0-7;r<=y0+6;r++){
            if(r<0||r>=HH) continue;
            int q=r*WW+x;
            s0+=g_t0[bk*NPIX+q]; s1+=g_t1[bk*NPIX+q]; s2+=g_t2[bk*NPIX+q];
        }
        for(int y=y0;y<y0+GTY;y++){
            int ra=y+7;
            if(ra<HH){ int q=ra*WW+x; s0+=g_t0[bk*NPIX+q]; s1+=g_t1[bk*NPIX+q]; s2+=g_t2[bk*NPIX+q]; }
            float cy = (float)(min(y+8,HH)-max(y-7,0));
            float cx = (float)(min(x+8,WW)-max(x-7,0));
            float c = cy*cx;
            float a0=s0/c, a1=s1/c, a2=s2/c;
            float den = a0 + 1e-8f;
            float mu = a1/den;
            float vb = fmaxf(a2/den - mu*mu, 1e-8f);
            int p=y*WW+x;
            g_lla[bk*NPIX+p] = fabsf(g_Lp[bb*NPIX+p]-mu)/(sqrtf(vb)+1e-8f);
            g_den[bk*NPIX+p] = a0;
            int rs=y-7;
            if(rs>=0){ int q=rs*WW+x; s0-=g_t0[bk*NPIX+q]; s1-=g_t1[bk*NPIX+q]; s2-=g_t2[bk*NPIX+q]; }
        }
    }
}

// fused GLD: tiled column histograms in shared (bin-prefix form)
__global__ void __launch_bounds__(128,8) kGLDTile(){
    int bk = blockIdx.z; int b=bk>>1, k=bk&1;
    int strip = blockIdx.x;            // 8 strips of 48 cols
    int y0 = blockIdx.y*GTY;           // 16 segs of 24 rows
    int warp = threadIdx.x>>5, lane = threadIdx.x&31;
    __shared__ float ch[62][32];
    const float* rk = g_Ra + bk*NPIX;
    const unsigned char* bi = g_idxb + b*NPIX;
    int xbase = strip*48 - 7;
    for(int i=threadIdx.x;i<62*32;i+=128) ((float*)ch)[i]=0.f;
    __syncthreads();
    for(int c=warp;c<62;c+=4){
        int x = xbase+c;
        if(x<0||x>=WW) continue;
        float P=0.f;
        for(int r=y0-7;r<=y0+6;r++){
            if(r<0||r>=HH) continue;
            float v=rk[r*WW+x]; int bn=bi[r*WW+x];
            if(lane>=bn) P+=v;
        }
        ch[c][lane]=P;
    }
    float gc = g_gcdf[b][k][lane];
    __syncthreads();
    for(int y=y0;y<y0+GTY;y++){
        int ra=y+7;
        if(ra<HH){
            for(int c=warp;c<62;c+=4){
                int x=xbase+c; if(x<0||x>=WW) continue;
                float v=rk[ra*WW+x]; int bn=bi[ra*WW+x];
                if(lane>=bn) ch[c][lane]+=v;
            }
        }
        __syncthreads();
        {
            int xo0 = warp*12;
            float S=0.f;
            #pragma unroll
            for(int c=0;c<14;c++) S += ch[xo0+c][lane];
            float cy = (float)(min(y+8,HH)-max(y-7,0));
            for(int j=0;j<12;j++){
                int xo = xo0+j;
                S += ch[xo+14][lane];
                int x = strip*48 + xo;
                float cx = (float)(min(x+8,WW)-max(x-7,0));
                float den = g_den[bk*NPIX + y*WW+x] + 1e-8f;
                float diff = fabsf(S/(cy*cx)/den - gc);
                for(int o=16;o;o>>=1) diff += __shfl_down_sync(0xffffffffu,diff,o);
                if(lane==0) g_gld[bk*NPIX + y*WW+x] = diff*(1.f/32.f);
                S -= ch[xo][lane];
            }
        }
        __syncthreads();
        int rs=y-7;
        if(rs>=0){
            for(int c=warp;c<62;c+=4){
                int x=xbase+c; if(x<0||x>=WW) continue;
                float v=rk[rs*WW+x]; int bn=bi[rs*WW+x];
                if(lane>=bn) ch[c][lane]-=v;
            }
        }
        __syncthreads();
    }
}

// LLA/GLD selects + gamma/La + La quantile selects + normalize + resets : 144 x 1024
__global__ void __launch_bounds__(1024,1) kFinalPhase(float* __restrict__ out){
    const int NB = 144;
    coopZero(NB);
    gridBarrier(NB);
    {   // 8 med+MAD jobs x 18 chunks
        int job = blockIdx.x/18, chunk = blockIdx.x%18;
        const int* jb = &g_seljobs[(10+job)*6];
        const float4* src = (const float4*)selSrc(jb[1], jb[2]);
        float med = coopSel(src,0.f,0,(unsigned)jb[3],job,0,chunk,18,NB);
        if(chunk==0&&threadIdx.x==0) g_sv[jb[4]]=med;
        float mad = coopSel(src,med,1,(unsigned)jb[3],job,3,chunk,18,NB);
        if(chunk==0&&threadIdx.x==0) g_sv[jb[5]]=mad;
    }
    gridBarrier(NB);
    // gamma + La (2 elems/thread)
    int gtid = blockIdx.x*1024 + threadIdx.x;
    #pragma unroll
    for(int h=0;h<2;h++){
        int idx = gtid + h*NPIX;
        int b = h, p = gtid;
        float gamma = 1.f;
        for(int k=0;k<2;k++){
            int s = b*2+k;
            float zl = (g_lla[s*NPIX+p]-vloadf(&g_sv[20+s]))/(vloadf(&g_sv[24+s])*1.4826f+1e-8f);
            float zg = (g_gld[s*NPIX+p]-vloadf(&g_sv[28+s]))/(vloadf(&g_sv[32+s])*1.4826f+1e-8f);
            gamma += g_Ra[s*NPIX+p]*(0.5f*softplusf(zl)+0.5f*softplusf(zg));
        }
        float mdE=g_sv[b*3+1], mdS=g_sv[b*3+2];
        float sdE=g_sv[6+b*3+1]*1.4826f+1e-8f, sdS=g_sv[6+b*3+2]*1.4826f+1e-8f;
        float dE=(g_E[idx]-mdE)/sdE-(float)g_esinv[b][3];
        float dS=(g_S[idx]-mdS)/sdS-(float)g_esinv[b][4];
        float d2 = dE*dE*(float)g_esinv[b][0] + 2.f*dE*dS*(float)g_esinv[b][1] + dS*dS*(float)g_esinv[b][2];
        float Rs = expf(-0.5f*d2);
        g_La[idx] = fmaxf(g_DM[idx]*gamma*(1.f-Rs), 0.f);
    }
    coopZero(NB);
    gridBarrier(NB);
    {   // La 1%/99% bracket selects: 4 jobs x 36 chunks
        int job = blockIdx.x/36, chunk = blockIdx.x%36;
        const int* jb = &g_seljobs[(18+job)*6];
        const float4* src = (const float4*)selSrc(jb[1], jb[2]);
        float v0 = coopSel(src,0.f,0,(unsigned)jb[3],job,0,chunk,36,NB);
        if(chunk==0&&threadIdx.x==0) g_sv[jb[4]]=v0;
        float v1 = coopSel(src,0.f,0,(unsigned)jb[3]+1u,job,3,chunk,36,NB);
        if(chunk==0&&threadIdx.x==0) g_sv[jb[5]]=v1;
    }
    gridBarrier(NB);
    #pragma unroll
    for(int h=0;h<2;h++){
        int idx = gtid + h*NPIX;
        int b = h;
        float q1 = vloadf(&g_sv[36+4*b]) + 0.55f*(vloadf(&g_sv[37+4*b])-vloadf(&g_sv[36+4*b]));
        float q9 = vloadf(&g_sv[38+4*b]) + 0.45f*(vloadf(&g_sv[39+4*b])-vloadf(&g_sv[38+4*b]));
        float v = (g_La[idx]-q1)/(q9-q1+1e-8f);
        out[BN + idx] = fminf(fmaxf(v,0.f),1.f);   // output #2
    }
    // resets for next replay
    if(blockIdx.x==0 && threadIdx.x<10) ((double*)g_reg)[threadIdx.x]=0.0;
}

// ======================= host =======================
extern "C" void kernel_launch(void* const* d_in, const int* in_sizes, int n_in,
                              void* d_out, int out_size){
    const float* lab   = (const float*)d_in[0];
    const float* arand = (const float*)d_in[1];
    float* out = (float*)d_out;

    kSobelE<<<dim3(24,24,BB),256>>>(lab);
    kLperp<<<1152,256>>>(lab,out);
    kSelA<<<144,1024>>>();
    kWhiten<<<128,256>>>(arand);
    kPhaseZEM<<<144,1024>>>();
    kClusterDM<<<128,256>>>();
    kGLDTile<<<dim3(8,16,4),128>>>();
    kFinalPhase<<<144,1024>>>(out);
}

// round 13
// speedup vs baseline: 1.4843x; 1.0332x over previous
#include <cuda_runtime.h>
#include <math.h>

#define HH 384
#define WW 384
#define NPIX (HH*WW)          // 147456
#define BB 2
#define BN (BB*NPIX)          // 294912
#define NDIR 128
#define GTY 24

// ======================= scratch buffers =======================
__device__ float g_E[BN];
__device__ float g_S[BN];
__device__ float g_Lp[BN];
__device__ float g_zb[BN];
__device__ float g_Ra[2*BN];     // [(b*2+k)*NPIX+n]
__device__ float g_DM[BN];
__device__ float g_t0[2*BN], g_t1[2*BN], g_t2[2*BN];
__device__ float g_lla[2*BN];
__device__ float g_den[2*BN];
__device__ float g_gld[2*BN];
__device__ float g_La[BN];
__device__ unsigned char g_idxb[BN];
__device__ unsigned g_jh[8*6*2048];     // cooperative select histograms

// ======================= small state =======================
__device__ float    g_sv[64];
__device__ unsigned g_mm[BB][2] = {{0xFFFFFFFFu,0u},{0xFFFFFFFFu,0u}};
__device__ double   g_reg[BB][5];
__device__ double   g_cacc[BB][9];
__device__ double   g_mean3[BB][3];
__device__ double   g_wwh[BB][9];
__device__ float    g_cdir[BB*NDIR*3];
__device__ float    g_cbest[BB][3];
__device__ double   g_dirm[BB][NDIR][4];
__device__ double   g_emacc2[9][BB][6];
__device__ double   g_clacc[BB][2][10];
__device__ double   g_clmu[BB][2][3];
__device__ double   g_clinv[BB][2][9];
__device__ double   g_ghist[BB][2][32];
__device__ float    g_gcdf[BB][2][32];
__device__ double   g_esinv[BB][6];

// grid-wide barrier (monotonic generation; arrive self-resets)
__device__ int g_barArrive = 0;
__device__ int g_barGen = 0;

static __device__ __forceinline__ void gridBarrier(int nb){
    __threadfence();
    __syncthreads();
    if(threadIdx.x==0){
        int gen = *(volatile int*)&g_barGen;
        if(atomicAdd(&g_barArrive,1)==nb-1){
            g_barArrive = 0;
            __threadfence();
            *(volatile int*)&g_barGen = gen+1;
        } else {
            while(*(volatile int*)&g_barGen == gen) { }
        }
    }
    __syncthreads();
}

static __device__ __forceinline__ double vloadd(const double* p){ return *(volatile const double*)p; }
static __device__ __forceinline__ float  vloadf(const float* p){ return *(volatile const float*)p; }

// ======================= helpers =======================
static __device__ __forceinline__ unsigned f2u(float f){
    unsigned u = __float_as_uint(f);
    return (u & 0x80000000u) ? ~u : (u | 0x80000000u);
}
static __device__ __forceinline__ float u2f(unsigned u){
    unsigned v = (u & 0x80000000u) ? (u & 0x7FFFFFFFu) : ~u;
    return __uint_as_float(v);
}
static __device__ __forceinline__ float softplusf(float x){
    float t = log1pf(expf(-fabsf(x)));
    return x >= 0.f ? x + t : t;
}
static __device__ double blockReduceD(double v){
    __shared__ double sh[32];
    int lane = threadIdx.x & 31, wid = threadIdx.x >> 5;
    for (int o=16;o;o>>=1) v += __shfl_down_sync(0xffffffffu, v, o);
    if (lane==0) sh[wid] = v;
    __syncthreads();
    int nw = (blockDim.x + 31) >> 5;
    v = (threadIdx.x < nw) ? sh[threadIdx.x] : 0.0;
    if (wid==0) for (int o=16;o;o>>=1) v += __shfl_down_sync(0xffffffffu, v, o);
    __syncthreads();
    return v;
}
// 3x3 symmetric Jacobi eigh with RELATIVE convergence (~4-5 sweeps)
static __device__ void eigh3(const double* A, double* e, double* V){
    double a[9]; for(int i=0;i<9;i++) a[i]=A[i];
    for(int i=0;i<9;i++) V[i] = (i%4==0)?1.0:0.0;
    double scale = fabs(A[0])+fabs(A[4])+fabs(A[8]) + 1e-300;
    for(int sweep=0; sweep<15; sweep++){
        double off = fabs(a[1])+fabs(a[2])+fabs(a[5]);
        if(off <= 1e-14*scale) break;
        for(int p=0;p<2;p++) for(int q=p+1;q<3;q++){
            double apq=a[p*3+q];
            if(fabs(apq) <= 1e-16*scale) continue;
            double app=a[p*3+p], aqq=a[q*3+q];
            double th=(aqq-app)/(2.0*apq);
            double t=(th>=0?1.0:-1.0)/(fabs(th)+sqrt(th*th+1.0));
            double c=1.0/sqrt(t*t+1.0), s=t*c;
            for(int i=0;i<3;i++){ double x=a[i*3+p],y=a[i*3+q]; a[i*3+p]=c*x-s*y; a[i*3+q]=s*x+c*y; }
            for(int i=0;i<3;i++){ double x=a[p*3+i],y=a[q*3+i]; a[p*3+i]=c*x-s*y; a[q*3+i]=s*x+c*y; }
            for(int i=0;i<3;i++){ double x=V[i*3+p],y=V[i*3+q]; V[i*3+p]=c*x-s*y; V[i*3+q]=s*x+c*y; }
        }
    }
    e[0]=a[0]; e[1]=a[4]; e[2]=a[8];
}
static __device__ void inv3(const double* m, double* inv){
    double a=m[0],b=m[1],c=m[2],d=m[3],e=m[4],f=m[5],g=m[6],h=m[7],i=m[8];
    double A=e*i-f*h, B=c*h-b*i, C=b*f-c*e;
    double D=f*g-d*i, E=a*i-c*g, F=c*d-a*f;
    double G=d*h-e*g, Hh=b*g-a*h, I=a*e-b*d;
    double det=a*A+b*D+c*G, id=1.0/det;
    inv[0]=A*id; inv[1]=B*id; inv[2]=C*id;
    inv[3]=D*id; inv[4]=E*id; inv[5]=F*id;
    inv[6]=G*id; inv[7]=Hh*id; inv[8]=I*id;
}

// ======================= cooperative radix select =======================
// jobs: {kind, type, b, rank, slotA, slotB}
__device__ const int g_seljobs[22*6] = {
 0,0,0,73727,0,6,   0,1,0,73727,1,7,   0,2,0,73727,2,8,
 0,0,1,73727,3,9,   0,1,1,73727,4,10,  0,2,1,73727,5,11,
 1,3,0,36863,12,13,  1,3,0,110591,14,15,  1,3,1,36863,16,17,  1,3,1,110591,18,19,
 0,4,0,73727,20,24,  0,5,0,73727,21,25,  0,4,1,73727,22,26,  0,5,1,73727,23,27,
 0,6,0,73727,28,32,  0,7,0,73727,29,33,  0,6,1,73727,30,34,  0,7,1,73727,31,35,
 1,8,0,1474,36,37,  1,8,0,145980,38,39,  1,8,1,1474,40,41,  1,8,1,145980,42,43
};

static __device__ const float* selSrc(int type, int b){
    switch(type){
        case 0: return g_Lp + b*NPIX;
        case 1: return g_E  + b*NPIX;
        case 2: return g_S  + b*NPIX;
        case 3: return g_zb + b*NPIX;
        case 4: return g_lla + (b*2+0)*NPIX;
        case 5: return g_lla + (b*2+1)*NPIX;
        case 6: return g_gld + (b*2+0)*NPIX;
        case 7: return g_gld + (b*2+1)*NPIX;
        default: return g_La + b*NPIX;
    }
}

static __device__ void coopZero(int nbTot){
    int total = 8*6*2048;
    for(int i=blockIdx.x*blockDim.x+threadIdx.x; i<total; i+=nbTot*blockDim.x)
        g_jh[i]=0u;
}

// 3-pass (11/11/10 bit) cooperative select across ncs blocks per job.
static __device__ float coopSel(const float4* __restrict__ src4, float ref, int useAbs, unsigned rank,
                                int jobLocal, int passBase, int chunk, int ncs, int nbTot){
    __shared__ unsigned sh[2048];
    __shared__ unsigned sres[2];
    unsigned pref=0, rk=rank;
    for(int pass=0; pass<3; pass++){
        unsigned* hist = g_jh + (jobLocal*6+passBase+pass)*2048;
        int nbin = (pass==2)?1024:2048;
        for(int i=threadIdx.x;i<nbin;i+=blockDim.x) sh[i]=0u;
        __syncthreads();
        int per = (NPIX/4)/ncs;
        int lo = chunk*per;
        for(int i=lo+threadIdx.x;i<lo+per;i+=blockDim.x){
            float4 v4 = src4[i];
            float vv[4]={v4.x,v4.y,v4.z,v4.w};
            #pragma unroll
            for(int c=0;c<4;c++){
                float v=vv[c]; if(useAbs) v=fabsf(v-ref);
                unsigned key=f2u(v);
                if(pass==0) atomicAdd(&sh[key>>21],1u);
                else if(pass==1){ if((key>>21)==(pref>>21)) atomicAdd(&sh[(key>>10)&2047u],1u); }
                else { if((key>>10)==(pref>>10)) atomicAdd(&sh[key&1023u],1u); }
            }
        }
        __syncthreads();
        for(int i=threadIdx.x;i<nbin;i+=blockDim.x) if(sh[i]) atomicAdd(&hist[i],sh[i]);
        gridBarrier(nbTot);
        if(threadIdx.x<32){
            int lane=threadIdx.x, perl=nbin>>5;
            unsigned s=0;
            for(int i=0;i<perl;i++) s+=hist[lane*perl+i];
            unsigned cum=s;
            #pragma unroll
            for(int o=1;o<32;o<<=1){ unsigned t=__shfl_up_sync(0xffffffffu,cum,o); if(lane>=o) cum+=t; }
            unsigned prev=cum-s;
            if(prev<=rk && rk<cum){
                unsigned rr=rk-prev; int bin=lane*perl;
                for(int i=0;i<perl;i++){ unsigned c=hist[lane*perl+i]; if(rr<c){ bin=lane*perl+i; break;} rr-=c; }
                sres[0]=(pass==0)? ((unsigned)bin<<21) : (pass==1)? (pref|((unsigned)bin<<10)) : (pref|(unsigned)bin);
                sres[1]=rr;
            }
        }
        __syncthreads();
        pref=sres[0]; rk=sres[1];
        __syncthreads();
    }
    return u2f(pref);
}

// ======================= pipeline kernels =======================
// fused Sobel + avg3 + regression accumulation, tiled in shared memory
__global__ void __launch_bounds__(256) kSobelE(const float* __restrict__ lab){
    __shared__ float sL[20][20];
    __shared__ float sP[18][18];
    int b = blockIdx.z;
    int x0 = blockIdx.x*16, y0 = blockIdx.y*16;
    int tid = threadIdx.x;
    int tx = tid & 15, ty = tid >> 4;
    const float* L = lab + (size_t)b*3*NPIX;
    for(int i=tid;i<400;i+=256){
        int jj=i/20, ii=i%20;
        int yy=y0-2+jj, xx=x0-2+ii;
        sL[jj][ii] = (yy>=0&&yy<HH&&xx>=0&&xx<WW) ? L[yy*WW+xx] : 0.f;
    }
    __syncthreads();
    for(int i=tid;i<324;i+=256){
        int jj=i/18, ii=i%18;
        int py=y0-1+jj, px=x0-1+ii;
        float v=0.f;
        if(py>=0&&py<HH&&px>=0&&px<WW){
            float l00=sL[jj][ii],   l01=sL[jj][ii+1],   l02=sL[jj][ii+2];
            float l10=sL[jj+1][ii],                     l12=sL[jj+1][ii+2];
            float l20=sL[jj+2][ii], l21=sL[jj+2][ii+1], l22=sL[jj+2][ii+2];
            float gx = -l00 + l02 - 2.f*l10 + 2.f*l12 - l20 + l22;
            float gy = -l00 - 2.f*l01 - l02 + l20 + 2.f*l21 + l22;
            v = gx*gx + gy*gy;
        }
        sP[jj][ii]=v;
    }
    __syncthreads();
    int y=y0+ty, x=x0+tx;
    int p = y*WW+x, idx = b*NPIX+p;
    float s = sP[ty][tx]  +sP[ty][tx+1]  +sP[ty][tx+2]
            + sP[ty+1][tx]+sP[ty+1][tx+1]+sP[ty+1][tx+2]
            + sP[ty+2][tx]+sP[ty+2][tx+1]+sP[ty+2][tx+2];
    float E = s/9.f;
    float av = L[NPIX+p], bv = L[2*NPIX+p];
    float S = sqrtf(av*av+bv*bv+1e-8f);
    g_E[idx]=E; g_S[idx]=S;
    double e=E, sv=S, l=L[p];
    double r;
    r=blockReduceD(e*e);  if(tid==0) atomicAdd(&g_reg[b][0],r);
    r=blockReduceD(e*sv); if(tid==0) atomicAdd(&g_reg[b][1],r);
    r=blockReduceD(sv*sv);if(tid==0) atomicAdd(&g_reg[b][2],r);
    r=blockReduceD(e*l);  if(tid==0) atomicAdd(&g_reg[b][3],r);
    r=blockReduceD(sv*l); if(tid==0) atomicAdd(&g_reg[b][4],r);
}

// L_perp (per-block inline 2x2 solve) + fused global min/max
__global__ void __launch_bounds__(256) kLperp(const float* __restrict__ lab, float* __restrict__ out){
    __shared__ float sb0, sb1;
    int idx = blockIdx.x*blockDim.x + threadIdx.x;
    int b = idx / NPIX, p = idx % NPIX;
    if(threadIdx.x==0){
        double ee=g_reg[b][0]+1e-6, es=g_reg[b][1], ss=g_reg[b][2]+1e-6;
        double el=g_reg[b][3], sl=g_reg[b][4];
        double det = ee*ss - es*es;
        sb0 = (float)((ss*el - es*sl)/det);
        sb1 = (float)((ee*sl - es*el)/det);
    }
    __syncthreads();
    float v = lab[(size_t)b*3*NPIX+p] - sb0*g_E[idx] - sb1*g_S[idx];
    g_Lp[idx] = v;
    out[idx] = v;   // output #1
    unsigned k = f2u(v);
    __shared__ unsigned smn[256], smx[256];
    smn[threadIdx.x]=k; smx[threadIdx.x]=k;
    __syncthreads();
    for(int o=128;o>0;o>>=1){
        if(threadIdx.x<o){ smn[threadIdx.x]=min(smn[threadIdx.x],smn[threadIdx.x+o]);
                           smx[threadIdx.x]=max(smx[threadIdx.x],smx[threadIdx.x+o]); }
        __syncthreads();
    }
    if(threadIdx.x==0){ atomicMin(&g_mm[b][0],smn[0]); atomicMax(&g_mm[b][1],smx[0]); }
}

// phase A: med+MAD of Lp,E,S for both batches; 6 jobs x 24 chunks = 144 blocks
__global__ void __launch_bounds__(1024,1) kSelA(){
    const int NB = 144;
    int job = blockIdx.x/24, chunk = blockIdx.x%24;
    coopZero(NB);
    gridBarrier(NB);
    const int* jb = &g_seljobs[job*6];
    const float4* src = (const float4*)selSrc(jb[1], jb[2]);
    float med = coopSel(src,0.f,0,(unsigned)jb[3],job,0,chunk,24,NB);
    if(chunk==0&&threadIdx.x==0) g_sv[jb[4]]=med;
    float mad = coopSel(src,med,1,(unsigned)jb[3],job,3,chunk,24,NB);
    if(chunk==0&&threadIdx.x==0) g_sv[jb[5]]=mad;
}

// cov-acc + eigh/ESinv/cdir + kurt-acc + parallel pick : ONE kernel, 288 blocks x 256
// (R12: 128->288 blocks, 4 elems/thread; launch_bounds(256,2) guarantees co-residency)
__global__ void __launch_bounds__(256,2) kWhiten(const float* __restrict__ arand){
    const int NBW = 288;
    int blk = blockIdx.x;
    int b = blk/144, chunk = blk%144;
    float md[3], sd[3];
    for(int f=0;f<3;f++){ md[f]=g_sv[b*3+f]; sd[f]=g_sv[6+b*3+f]*1.4826f+1e-8f; }
    int base = b*NPIX + chunk*1024;
    float z0[4], z1[4], z2[4];
    double a[9]={0,0,0,0,0,0,0,0,0};
    #pragma unroll
    for(int i=0;i<4;i++){
        int p = base + i*256 + threadIdx.x;
        float u0=(g_Lp[p]-md[0])/sd[0];
        float u1=(g_E [p]-md[1])/sd[1];
        float u2=(g_S [p]-md[2])/sd[2];
        z0[i]=u0; z1[i]=u1; z2[i]=u2;
        a[0]+=u0; a[1]+=u1; a[2]+=u2;
        a[3]+=(double)u0*u0; a[4]+=(double)u0*u1; a[5]+=(double)u0*u2;
        a[6]+=(double)u1*u1; a[7]+=(double)u1*u2; a[8]+=(double)u2*u2;
    }
    for(int m=0;m<9;m++){ double r=blockReduceD(a[m]); if(threadIdx.x==0) atomicAdd(&g_cacc[b][m],r); }
    gridBarrier(NBW);
    if(blk==0){
        int t = threadIdx.x;
        if(t<BB){
            int bb = t;
            double N = (double)NPIX;
            double mu[3]; for(int i=0;i<3;i++){ mu[i]=vloadd(&g_cacc[bb][i])/N; g_mean3[bb][i]=mu[i]; }
            double C[9];
            C[0]=vloadd(&g_cacc[bb][3])/N-mu[0]*mu[0]; C[1]=vloadd(&g_cacc[bb][4])/N-mu[0]*mu[1]; C[2]=vloadd(&g_cacc[bb][5])/N-mu[0]*mu[2];
            C[4]=vloadd(&g_cacc[bb][6])/N-mu[1]*mu[1]; C[5]=vloadd(&g_cacc[bb][7])/N-mu[1]*mu[2]; C[8]=vloadd(&g_cacc[bb][8])/N-mu[2]*mu[2];
            C[3]=C[1]; C[6]=C[2]; C[7]=C[5];
            {
                double c00=C[4]+1e-6, c01=C[5], c11=C[8]+1e-6;
                double det=c00*c11-c01*c01;
                g_esinv[bb][0]=c11/det; g_esinv[bb][1]=-c01/det; g_esinv[bb][2]=c00/det;
                g_esinv[bb][3]=mu[1]; g_esinv[bb][4]=mu[2];
            }
            for(int i=0;i<9;i++) C[i] = C[i] > 1e-8 ? C[i] : 1e-8;   // elementwise max (matches ref)
            double e[3], V[9];
            eigh3(C, e, V);
            for(int i=0;i<3;i++) for(int j=0;j<3;j++){
                double ssum=0; for(int k2=0;k2<3;k2++) ssum += V[i*3+k2]*(1.0/sqrt(e[k2]))*V[j*3+k2];
                g_wwh[bb][i*3+j]=ssum;
            }
            for(int i=0;i<9;i++) g_cacc[bb][i]=0.0;
        }
        __syncthreads();
        {
            int t2 = threadIdx.x;       // 256 threads = BB*NDIR
            int bb = t2 / NDIR, d = t2 % NDIR;
            float a0=arand[(bb*NDIR+d)*3+0], a1=arand[(bb*NDIR+d)*3+1], a2=arand[(bb*NDIR+d)*3+2];
            float nr = sqrtf(a0*a0+a1*a1+a2*a2) + 1e-12f;
            double an[3]={a0/nr,a1/nr,a2/nr};
            for(int jj=0;jj<3;jj++){
                double ssum=0; for(int i=0;i<3;i++) ssum += g_wwh[bb][jj*3+i]*an[i];
                g_cdir[(bb*NDIR+d)*3+jj]=(float)ssum;
            }
        }
    }
    gridBarrier(NBW);
    // kurt phase: reuse cached z arrays
    __shared__ float scd[NDIR*3];
    __shared__ float sacc[NDIR*4];
    for(int i=threadIdx.x;i<NDIR*3;i+=256) scd[i]=vloadf(&g_cdir[b*NDIR*3+i]);
    for(int i=threadIdx.x;i<NDIR*4;i+=256) sacc[i]=0.f;
    float mn0=(float)vloadd(&g_mean3[b][0]), mn1=(float)vloadd(&g_mean3[b][1]), mn2=(float)vloadd(&g_mean3[b][2]);
    #pragma unroll
    for(int i=0;i<4;i++){ z0[i]-=mn0; z1[i]-=mn1; z2[i]-=mn2; }
    __syncthreads();
    int lane = threadIdx.x & 31;
    for(int d=0;d<NDIR;d++){
        float c0=scd[d*3], c1=scd[d*3+1], c2=scd[d*3+2];
        float s1=0,s2=0,s3=0,s4=0;
        #pragma unroll
        for(int i=0;i<4;i++){
            float z=z0[i]*c0+z1[i]*c1+z2[i]*c2;
            float zz=z*z;
            s1+=z; s2+=zz; s3+=zz*z; s4+=zz*zz;
        }
        for(int o=16;o;o>>=1){
            s1+=__shfl_down_sync(0xffffffffu,s1,o); s2+=__shfl_down_sync(0xffffffffu,s2,o);
            s3+=__shfl_down_sync(0xffffffffu,s3,o); s4+=__shfl_down_sync(0xffffffffu,s4,o);
        }
        if(lane==0){
            atomicAdd(&sacc[d*4+0],s1); atomicAdd(&sacc[d*4+1],s2);
            atomicAdd(&sacc[d*4+2],s3); atomicAdd(&sacc[d*4+3],s4);
        }
    }
    __syncthreads();
    for(int i=threadIdx.x;i<NDIR*4;i+=256)
        atomicAdd(&((double*)g_dirm)[b*NDIR*4+i], (double)sacc[i]);
    gridBarrier(NBW);
    if(blk==0){
        __shared__ double skv[256];
        __shared__ int sdi[256];
        int t = threadIdx.x;
        int bb = t>>7, d = t&127;
        double N=(double)NPIX;
        double m1=vloadd(&g_dirm[bb][d][0])/N, s2=vloadd(&g_dirm[bb][d][1])/N;
        double s3=vloadd(&g_dirm[bb][d][2])/N, s4=vloadd(&g_dirm[bb][d][3])/N;
        double m2=(s2-m1*m1)+1e-12;
        double m4=s4-4.0*m1*s3+6.0*m1*m1*s2-3.0*m1*m1*m1*m1;
        skv[t]=fabs(m4/(m2*m2)-3.0); sdi[t]=d;
        __syncthreads();
        for(int o=64;o;o>>=1){
            if((t&127)<o){
                if(skv[t+o]>skv[t] || (skv[t+o]==skv[t] && sdi[t+o]<sdi[t])){ skv[t]=skv[t+o]; sdi[t]=sdi[t+o]; }
            }
            __syncthreads();
        }
        if((t&127)==0){
            int best=sdi[t];
            for(int j=0;j<3;j++) g_cbest[t>>7][j]=vloadf(&g_cdir[((t>>7)*NDIR+best)*3+j]);
        }
        __syncthreads();
        // reset dirm (1024 doubles)
        for(int i=t;i<BB*NDIR*4;i+=256) ((double*)g_dirm)[i]=0.0;
    }
}

// phase Z + EM fused: zb compute, SPLIT bracket selects (8 parallel single selects), 9 EM iters, Ra.
__global__ void __launch_bounds__(1024,1) kPhaseZEM(){
    const int NB = 144;
    int gtid = blockIdx.x*1024 + threadIdx.x;     // < 147456
    // zb for both batches
    #pragma unroll
    for(int h=0;h<2;h++){
        int idx = gtid + h*NPIX;
        int b = h;
        float md0=g_sv[b*3+0], md1=g_sv[b*3+1], md2=g_sv[b*3+2];
        float sd0=g_sv[6+b*3+0]*1.4826f+1e-8f, sd1=g_sv[6+b*3+1]*1.4826f+1e-8f, sd2=g_sv[6+b*3+2]*1.4826f+1e-8f;
        float d0=(g_Lp[idx]-md0)/sd0-(float)g_mean3[b][0];
        float d1=(g_E [idx]-md1)/sd1-(float)g_mean3[b][1];
        float d2=(g_S [idx]-md2)/sd2-(float)g_mean3[b][2];
        g_zb[idx] = d0*g_cbest[b][0]+d1*g_cbest[b][1]+d2*g_cbest[b][2];
    }
    coopZero(NB);
    {   // zero EM accumulators for this replay
        double* acc = (double*)g_emacc2;
        int tot = 9*BB*6;
        for(int i=blockIdx.x*1024+threadIdx.x; i<tot; i+=NB*1024) acc[i]=0.0;
    }
    gridBarrier(NB);
    // SPLIT quartile-bracket selects: 8 single-select jobs x 18 chunks (3 passes total)
    {
        int job = blockIdx.x/18, chunk = blockIdx.x%18;
        int pair = job>>1, which = job&1;
        const int* jb = &g_seljobs[(6+pair)*6];
        const float4* src = (const float4*)selSrc(jb[1], jb[2]);
        float v = coopSel(src,0.f,0,(unsigned)(jb[3]+which),job,0,chunk,18,NB);
        if(chunk==0&&threadIdx.x==0) g_sv[jb[4+which]]=v;
    }
    gridBarrier(NB);
    // EM: blocks 0..71 -> batch0, 72..143 -> batch1; 2 elems per thread (batch-relative indexing)
    int b = blockIdx.x/72, sub = blockIdx.x%72;
    int baseRel = sub*2048 + threadIdx.x;
    float x0 = g_zb[b*NPIX + baseRel], x1 = g_zb[b*NPIX + baseRel + 1024];
    float q25 = vloadf(&g_sv[12+4*b]) + 0.75f*(vloadf(&g_sv[13+4*b])-vloadf(&g_sv[12+4*b]));
    float q75 = vloadf(&g_sv[14+4*b]) + 0.25f*(vloadf(&g_sv[15+4*b])-vloadf(&g_sv[14+4*b]));
    double mu0=q25, mu1=q75, var0=1.0, var1=1.0, pi0=0.5, pi1=0.5;
    for(int it=0; it<9; it++){
        float m0=(float)mu0, m1=(float)mu1;
        float v0=(float)var0+1e-6f, v1=(float)var1+1e-6f;
        float lw0=-0.5f*logf(v0)+logf((float)pi0+1e-8f);
        float lw1=-0.5f*logf(v1)+logf((float)pi1+1e-8f);
        float iv0=0.5f/v0, iv1=0.5f/v1;
        float a0=0,a1=0,a2=0,a3=0,a4=0,a5=0;
        #pragma unroll
        for(int i=0;i<2;i++){
            float xx = (i==0)?x0:x1;
            float lp0=-(xx-m0)*(xx-m0)*iv0+lw0;
            float lp1=-(xx-m1)*(xx-m1)*iv1+lw1;
            float R0=1.f/(1.f+expf(lp1-lp0));
            float R1=1.f/(1.f+expf(lp0-lp1));
            a0+=R0; a1+=R0*xx; a2+=R0*xx*xx;
            a3+=R1; a4+=R1*xx; a5+=R1*xx*xx;
        }
        double s[6]={a0,a1,a2,a3,a4,a5};
        for(int m=0;m<6;m++){
            double r=blockReduceD(s[m]);
            if(threadIdx.x==0) atomicAdd(&g_emacc2[it][b][m],r);
        }
        gridBarrier(NB);
        {
            double Sr0=vloadd(&g_emacc2[it][b][0]), Sx0=vloadd(&g_emacc2[it][b][1]), Sxx0=vloadd(&g_emacc2[it][b][2]);
            double Sr1=vloadd(&g_emacc2[it][b][3]), Sx1=vloadd(&g_emacc2[it][b][4]), Sxx1=vloadd(&g_emacc2[it][b][5]);
            double den0=Sr0+1e-8; mu0=Sx0/den0;
            var0=(Sxx0-2.0*mu0*Sx0+mu0*mu0*Sr0)/den0+1e-6; pi0=Sr0/(double)NPIX;
            double den1=Sr1+1e-8; mu1=Sx1/den1;
            var1=(Sxx1-2.0*mu1*Sx1+mu1*mu1*Sr1)/den1+1e-6; pi1=Sr1/(double)NPIX;
        }
    }
    {
        float m0=(float)mu0, m1=(float)mu1;
        float v0=(float)var0+1e-6f, v1=(float)var1+1e-6f;
        float lw0=-0.5f*logf(v0)+logf((float)pi0+1e-8f);
        float lw1=-0.5f*logf(v1)+logf((float)pi1+1e-8f);
        float iv0=0.5f/v0, iv1=0.5f/v1;
        #pragma unroll
        for(int i=0;i<2;i++){
            float xx = (i==0)?x0:x1;
            int p = baseRel + i*1024;          // batch-relative plane offset
            float lp0=-(xx-m0)*(xx-m0)*iv0+lw0;
            float lp1=-(xx-m1)*(xx-m1)*iv1+lw1;
            float R0=1.f/(1.f+expf(lp1-lp0));
            float R1=1.f/(1.f+expf(lp0-lp1));
            float r0=powf(R0,0.9f), r1=powf(R1,0.9f);
            float ssum=r0+r1+1e-8f;
            g_Ra[(b*2+0)*NPIX+p]=r0/ssum;
            g_Ra[(b*2+1)*NPIX+p]=r1/ssum;
        }
    }
}

// cluster moments + binidx + ghist -> inverses+gcdf -> DM + boxH(shared rows) -> boxV(sliding)
__global__ void __launch_bounds__(256) kClusterDM(){
    int blk = blockIdx.x;              // 128
    int b = blk>>6, chunk = blk&63;
    __shared__ float sh64[64];
    if(threadIdx.x<64) sh64[threadIdx.x]=0.f;
    __syncthreads();
    float mn = u2f(g_mm[b][0]), mx = u2f(g_mm[b][1]);
    float inv_rng = 1.f/(mx-mn+1e-8f);
    double a[20];
    for(int i=0;i<20;i++) a[i]=0.0;
    int lo = chunk*2304, hi = lo+2304;
    for(int p=lo+threadIdx.x;p<hi;p+=256){
        float w0=g_Ra[(b*2+0)*NPIX+p], w1=g_Ra[(b*2+1)*NPIX+p];
        float lpv=g_Lp[b*NPIX+p];
        double x0=lpv, x1=g_E[b*NPIX+p], x2=g_S[b*NPIX+p];
        a[0]+=w0; a[1]+=w0*x0; a[2]+=w0*x1; a[3]+=w0*x2;
        a[4]+=w0*x0*x0; a[5]+=w0*x0*x1; a[6]+=w0*x0*x2;
        a[7]+=w0*x1*x1; a[8]+=w0*x1*x2; a[9]+=w0*x2*x2;
        a[10]+=w1; a[11]+=w1*x0; a[12]+=w1*x1; a[13]+=w1*x2;
        a[14]+=w1*x0*x0; a[15]+=w1*x0*x1; a[16]+=w1*x0*x2;
        a[17]+=w1*x1*x1; a[18]+=w1*x1*x2; a[19]+=w1*x2*x2;
        float ln = (lpv-mn)*inv_rng;
        ln = fminf(fmaxf(ln,0.f),1.f);
        int c = (int)(ln*32.f); c = c<0?0:(c>31?31:c);
        g_idxb[b*NPIX+p] = (unsigned char)c;
        atomicAdd(&sh64[c],    w0);
        atomicAdd(&sh64[32+c], w1);
    }
    for(int m=0;m<20;m++){
        double r=blockReduceD(a[m]);
        if(threadIdx.x==0) atomicAdd(&g_clacc[b][m/10][m%10],r);
    }
    __syncthreads();
    if(threadIdx.x<64 && sh64[threadIdx.x]!=0.f)
        atomicAdd(&g_ghist[b][threadIdx.x>>5][threadIdx.x&31],(double)sh64[threadIdx.x]);
    gridBarrier(128);
    if(blk==0 && threadIdx.x<4){
        int t = threadIdx.x;
        int bb=t>>1, k=t&1;
        double A[10];
        for(int i=0;i<10;i++) A[i]=vloadd(&g_clacc[bb][k][i]);
        double Ws = A[0] + 1e-8;
        double mu[3] = {A[1]/Ws, A[2]/Ws, A[3]/Ws};
        double Sx[3] = {A[1], A[2], A[3]};
        double Sxx[9] = {A[4],A[5],A[6], A[5],A[7],A[8], A[6],A[8],A[9]};
        double C[9];
        for(int i=0;i<3;i++) for(int j2=0;j2<3;j2++)
            C[i*3+j2] = (Sxx[i*3+j2] - mu[i]*Sx[j2] - mu[j2]*Sx[i] + A[0]*mu[i]*mu[j2])/Ws + ((i==j2)?1e-6:0.0);
        double I[9]; inv3(C, I);
        for(int i=0;i<9;i++) g_clinv[bb][k][i]=I[i];
        for(int i=0;i<3;i++) g_clmu[bb][k][i]=mu[i];
        for(int i=0;i<10;i++) g_clacc[bb][k][i]=0.0;
        double tot=0; for(int c=0;c<32;c++) tot += vloadd(&g_ghist[bb][k][c]);
        double cum=0;
        for(int c=0;c<32;c++){ cum += vloadd(&g_ghist[bb][k][c])/(tot+1e-8); g_gcdf[bb][k][c]=(float)cum; g_ghist[bb][k][c]=0.0; }
        if(k==0){ g_mm[bb][0]=0xFFFFFFFFu; g_mm[bb][1]=0u; }
    }
    gridBarrier(128);
    // DM for 9 pixels/thread
    for(int i=0;i<9;i++){
        int idx = blk*256+threadIdx.x + i*32768;
        int bb = idx/NPIX, p = idx%NPIX;
        float X0=g_Lp[idx], X1=g_E[idx], X2=g_S[idx];
        float ra0=g_Ra[(bb*2+0)*NPIX+p], ra1=g_Ra[(bb*2+1)*NPIX+p];
        float ssum = ra0+ra1+2e-8f;
        float DM=0.f;
        for(int kk=0;kk<2;kk++){
            float xm0=X0-(float)vloadd(&g_clmu[bb][kk][0]);
            float xm1=X1-(float)vloadd(&g_clmu[bb][kk][1]);
            float xm2=X2-(float)vloadd(&g_clmu[bb][kk][2]);
            float i0=(float)vloadd(&g_clinv[bb][kk][0]), i1=(float)vloadd(&g_clinv[bb][kk][1]);
            float i2=(float)vloadd(&g_clinv[bb][kk][2]), i4=(float)vloadd(&g_clinv[bb][kk][4]);
            float i5=(float)vloadd(&g_clinv[bb][kk][5]), i8=(float)vloadd(&g_clinv[bb][kk][8]);
            float q = xm0*xm0*i0 + xm1*xm1*i4 + xm2*xm2*i8
                    + 2.f*xm0*xm1*i1 + 2.f*xm0*xm2*i2 + 2.f*xm1*xm2*i5;
            float Dk = sqrtf(q + 1e-8f);
            float Rt = ((kk==0?ra0:ra1)+1e-8f)/ssum;
            DM += Rt*Dk;
        }
        g_DM[idx]=DM;
    }
    // boxH via shared rows: 1536 row jobs, 12 per block
    __shared__ float rowR[WW], rowL[WW];
    for(int j=blk; j<4*HH; j+=128){
        int bk = j/HH, y = j%HH;
        int bb = bk>>1;
        for(int i=threadIdx.x;i<WW;i+=256){
            rowR[i]=g_Ra[bk*NPIX + y*WW + i];
            rowL[i]=g_Lp[bb*NPIX + y*WW + i];
        }
        __syncthreads();
        for(int x=threadIdx.x;x<WW;x+=256){
            float s0=0.f,s1=0.f,s2=0.f;
            int lo2=max(x-7,0), hi2=min(x+7,WW-1);
            for(int xx=lo2;xx<=hi2;xx++){
                float r=rowR[xx], l=rowL[xx];
                s0+=r; s1+=r*l; s2+=r*l*l;
            }
            int p=y*WW+x;
            g_t0[bk*NPIX+p]=s0; g_t1[bk*NPIX+p]=s1; g_t2[bk*NPIX+p]=s2;
        }
        __syncthreads();
    }
    gridBarrier(128);
    // boxV: register-sliding per (plane-col, 24-row segment); 24576 active threads
    int tseg = blk*256 + threadIdx.x;
    if(tseg < 1536*16){
        int seg = tseg/1536, col = tseg%1536;
        int bk = col/WW, x = col%WW;
        int bb = bk>>1;
        int y0 = seg*GTY;
        float s0=0.f,s1=0.f,s2=0.f;
        for(int r=y0-7;r<=y0+6;r++){
            if(r<0||r>=HH) continue;
            int q=r*WW+x;
            s0+=g_t0[bk*NPIX+q]; s1+=g_t1[bk*NPIX+q]; s2+=g_t2[bk*NPIX+q];
        }
        for(int y=y0;y<y0+GTY;y++){
            int ra=y+7;
            if(ra<HH){ int q=ra*WW+x; s0+=g_t0[bk*NPIX+q]; s1+=g_t1[bk*NPIX+q]; s2+=g_t2[bk*NPIX+q]; }
            float cy = (float)(min(y+8,HH)-max(y-7,0));
            float cx = (float)(min(x+8,WW)-max(x-7,0));
            float c = cy*cx;
            float a0=s0/c, a1=s1/c, a2=s2/c;
            float den = a0 + 1e-8f;
            float mu = a1/den;
            float vb = fmaxf(a2/den - mu*mu, 1e-8f);
            int p=y*WW+x;
            g_lla[bk*NPIX+p] = fabsf(g_Lp[bb*NPIX+p]-mu)/(sqrtf(vb)+1e-8f);
            g_den[bk*NPIX+p] = a0;
            int rs=y-7;
            if(rs>=0){ int q=rs*WW+x; s0-=g_t0[bk*NPIX+q]; s1-=g_t1[bk*NPIX+q]; s2-=g_t2[bk*NPIX+q]; }
        }
    }
}

// fused GLD: tiled column histograms in shared (bin-prefix form)
__global__ void __launch_bounds__(128,8) kGLDTile(){
    int bk = blockIdx.z; int b=bk>>1, k=bk&1;
    int strip = blockIdx.x;            // 8 strips of 48 cols
    int y0 = blockIdx.y*GTY;           // 16 segs of 24 rows
    int warp = threadIdx.x>>5, lane = threadIdx.x&31;
    __shared__ float ch[62][32];
    const float* rk = g_Ra + bk*NPIX;
    const unsigned char* bi = g_idxb + b*NPIX;
    int xbase = strip*48 - 7;
    for(int i=threadIdx.x;i<62*32;i+=128) ((float*)ch)[i]=0.f;
    __syncthreads();
    for(int c=warp;c<62;c+=4){
        int x = xbase+c;
        if(x<0||x>=WW) continue;
        float P=0.f;
        for(int r=y0-7;r<=y0+6;r++){
            if(r<0||r>=HH) continue;
            float v=rk[r*WW+x]; int bn=bi[r*WW+x];
            if(lane>=bn) P+=v;
        }
        ch[c][lane]=P;
    }
    float gc = g_gcdf[b][k][lane];
    __syncthreads();
    for(int y=y0;y<y0+GTY;y++){
        int ra=y+7;
        if(ra<HH){
            for(int c=warp;c<62;c+=4){
                int x=xbase+c; if(x<0||x>=WW) continue;
                float v=rk[ra*WW+x]; int bn=bi[ra*WW+x];
                if(lane>=bn) ch[c][lane]+=v;
            }
        }
        __syncthreads();
        {
            int xo0 = warp*12;
            float S=0.f;
            #pragma unroll
            for(int c=0;c<14;c++) S += ch[xo0+c][lane];
            float cy = (float)(min(y+8,HH)-max(y-7,0));
            for(int j=0;j<12;j++){
                int xo = xo0+j;
                S += ch[xo+14][lane];
                int x = strip*48 + xo;
                float cx = (float)(min(x+8,WW)-max(x-7,0));
                float den = g_den[bk*NPIX + y*WW+x] + 1e-8f;
                float diff = fabsf(S/(cy*cx)/den - gc);
                for(int o=16;o;o>>=1) diff += __shfl_down_sync(0xffffffffu,diff,o);
                if(lane==0) g_gld[bk*NPIX + y*WW+x] = diff*(1.f/32.f);
                S -= ch[xo][lane];
            }
        }
        __syncthreads();
        int rs=y-7;
        if(rs>=0){
            for(int c=warp;c<62;c+=4){
                int x=xbase+c; if(x<0||x>=WW) continue;
                float v=rk[rs*WW+x]; int bn=bi[rs*WW+x];
                if(lane>=bn) ch[c][lane]-=v;
            }
        }
        __syncthreads();
    }
}

// LLA/GLD selects + gamma/La + SPLIT La quantile selects + normalize + resets : 144 x 1024
__global__ void __launch_bounds__(1024,1) kFinalPhase(float* __restrict__ out){
    const int NB = 144;
    coopZero(NB);
    gridBarrier(NB);
    {   // 8 med+MAD jobs x 18 chunks
        int job = blockIdx.x/18, chunk = blockIdx.x%18;
        const int* jb = &g_seljobs[(10+job)*6];
        const float4* src = (const float4*)selSrc(jb[1], jb[2]);
        float med = coopSel(src,0.f,0,(unsigned)jb[3],job,0,chunk,18,NB);
        if(chunk==0&&threadIdx.x==0) g_sv[jb[4]]=med;
        float mad = coopSel(src,med,1,(unsigned)jb[3],job,3,chunk,18,NB);
        if(chunk==0&&threadIdx.x==0) g_sv[jb[5]]=mad;
    }
    gridBarrier(NB);
    // gamma + La (2 elems/thread)
    int gtid = blockIdx.x*1024 + threadIdx.x;
    #pragma unroll
    for(int h=0;h<2;h++){
        int idx = gtid + h*NPIX;
        int b = h, p = gtid;
        float gamma = 1.f;
        for(int k=0;k<2;k++){
            int s = b*2+k;
            float zl = (g_lla[s*NPIX+p]-vloadf(&g_sv[20+s]))/(vloadf(&g_sv[24+s])*1.4826f+1e-8f);
            float zg = (g_gld[s*NPIX+p]-vloadf(&g_sv[28+s]))/(vloadf(&g_sv[32+s])*1.4826f+1e-8f);
            gamma += g_Ra[s*NPIX+p]*(0.5f*softplusf(zl)+0.5f*softplusf(zg));
        }
        float mdE=g_sv[b*3+1], mdS=g_sv[b*3+2];
        float sdE=g_sv[6+b*3+1]*1.4826f+1e-8f, sdS=g_sv[6+b*3+2]*1.4826f+1e-8f;
        float dE=(g_E[idx]-mdE)/sdE-(float)g_esinv[b][3];
        float dS=(g_S[idx]-mdS)/sdS-(float)g_esinv[b][4];
        float d2 = dE*dE*(float)g_esinv[b][0] + 2.f*dE*dS*(float)g_esinv[b][1] + dS*dS*(float)g_esinv[b][2];
        float Rs = expf(-0.5f*d2);
        g_La[idx] = fmaxf(g_DM[idx]*gamma*(1.f-Rs), 0.f);
    }
    coopZero(NB);
    gridBarrier(NB);
    {   // SPLIT La 1%/99% bracket selects: 8 single-select jobs x 18 chunks (3 passes)
        int job = blockIdx.x/18, chunk = blockIdx.x%18;
        int pair = job>>1, which = job&1;
        const int* jb = &g_seljobs[(18+pair)*6];
        const float4* src = (const float4*)selSrc(jb[1], jb[2]);
        float v = coopSel(src,0.f,0,(unsigned)(jb[3]+which),job,0,chunk,18,NB);
        if(chunk==0&&threadIdx.x==0) g_sv[jb[4+which]]=v;
    }
    gridBarrier(NB);
    #pragma unroll
    for(int h=0;h<2;h++){
        int idx = gtid + h*NPIX;
        int b = h;
        float q1 = vloadf(&g_sv[36+4*b]) + 0.55f*(vloadf(&g_sv[37+4*b])-vloadf(&g_sv[36+4*b]));
        float q9 = vloadf(&g_sv[38+4*b]) + 0.45f*(vloadf(&g_sv[39+4*b])-vloadf(&g_sv[38+4*b]));
        float v = (g_La[idx]-q1)/(q9-q1+1e-8f);
        out[BN + idx] = fminf(fmaxf(v,0.f),1.f);   // output #2
    }
    // resets for next replay
    if(blockIdx.x==0 && threadIdx.x<10) ((double*)g_reg)[threadIdx.x]=0.0;
}

// ======================= host =======================
extern "C" void kernel_launch(void* const* d_in, const int* in_sizes, int n_in,
                              void* d_out, int out_size){
    const float* lab   = (const float*)d_in[0];
    const float* arand = (const float*)d_in[1];
    float* out = (float*)d_out;

    kSobelE<<<dim3(24,24,BB),256>>>(lab);
    kLperp<<<1152,256>>>(lab,out);
    kSelA<<<144,1024>>>();
    kWhiten<<<288,256>>>(arand);
    kPhaseZEM<<<144,1024>>>();
    kClusterDM<<<128,256>>>();
    kGLDTile<<<dim3(8,16,4),128>>>();
    kFinalPhase<<<144,1024>>>(out);
}

// round 14
// speedup vs baseline: 1.5271x; 1.0289x over previous
#include <cuda_runtime.h>
#include <math.h>

#define HH 384
#define WW 384
#define NPIX (HH*WW)          // 147456
#define BB 2
#define BN (BB*NPIX)          // 294912
#define NDIR 128
#define GTY 24

// ======================= scratch buffers =======================
__device__ float g_E[BN];
__device__ float g_S[BN];
__device__ float g_Lp[BN];
__device__ float g_zb[BN];
__device__ float g_Ra[2*BN];     // [(b*2+k)*NPIX+n]
__device__ float g_DM[BN];
__device__ float g_t0[2*BN], g_t1[2*BN], g_t2[2*BN];
__device__ float g_lla[2*BN];
__device__ float g_den[2*BN];
__device__ float g_gld[2*BN];
__device__ float g_La[BN];
__device__ unsigned char g_idxb[BN];
__device__ unsigned g_jh[8*6*2048];     // cooperative select histograms

// ======================= small state =======================
__device__ float    g_sv[64];
__device__ unsigned g_mm[BB][2] = {{0xFFFFFFFFu,0u},{0xFFFFFFFFu,0u}};
__device__ double   g_reg[BB][5];
__device__ double   g_cacc[BB][9];
__device__ double   g_mean3[BB][3];
__device__ double   g_wwh[BB][9];
__device__ float    g_cdir[BB*NDIR*3];
__device__ float    g_cbest[BB][3];
__device__ double   g_dirm[BB][NDIR][4];
__device__ double   g_emacc2[9][BB][6];
__device__ double   g_clacc[BB][2][10];
__device__ double   g_clmu[BB][2][3];
__device__ double   g_clinv[BB][2][9];
__device__ double   g_ghist[BB][2][32];
__device__ float    g_gcdf[BB][2][32];
__device__ double   g_esinv[BB][6];

// grid-wide barrier (monotonic generation; arrive self-resets)
__device__ int g_barArrive = 0;
__device__ int g_barGen = 0;

static __device__ __forceinline__ void gridBarrier(int nb){
    __threadfence();
    __syncthreads();
    if(threadIdx.x==0){
        int gen = *(volatile int*)&g_barGen;
        if(atomicAdd(&g_barArrive,1)==nb-1){
            g_barArrive = 0;
            __threadfence();
            *(volatile int*)&g_barGen = gen+1;
        } else {
            while(*(volatile int*)&g_barGen == gen) { }
        }
    }
    __syncthreads();
}

static __device__ __forceinline__ double vloadd(const double* p){ return *(volatile const double*)p; }
static __device__ __forceinline__ float  vloadf(const float* p){ return *(volatile const float*)p; }

// ======================= helpers =======================
static __device__ __forceinline__ unsigned f2u(float f){
    unsigned u = __float_as_uint(f);
    return (u & 0x80000000u) ? ~u : (u | 0x80000000u);
}
static __device__ __forceinline__ float u2f(unsigned u){
    unsigned v = (u & 0x80000000u) ? (u & 0x7FFFFFFFu) : ~u;
    return __uint_as_float(v);
}
static __device__ __forceinline__ float softplusf(float x){
    float t = log1pf(expf(-fabsf(x)));
    return x >= 0.f ? x + t : t;
}
static __device__ double blockReduceD(double v){
    __shared__ double sh[32];
    int lane = threadIdx.x & 31, wid = threadIdx.x >> 5;
    for (int o=16;o;o>>=1) v += __shfl_down_sync(0xffffffffu, v, o);
    if (lane==0) sh[wid] = v;
    __syncthreads();
    int nw = (blockDim.x + 31) >> 5;
    v = (threadIdx.x < nw) ? sh[threadIdx.x] : 0.0;
    if (wid==0) for (int o=16;o;o>>=1) v += __shfl_down_sync(0xffffffffu, v, o);
    __syncthreads();
    return v;
}
// 3x3 symmetric Jacobi eigh with RELATIVE convergence (~4-5 sweeps)
static __device__ void eigh3(const double* A, double* e, double* V){
    double a[9]; for(int i=0;i<9;i++) a[i]=A[i];
    for(int i=0;i<9;i++) V[i] = (i%4==0)?1.0:0.0;
    double scale = fabs(A[0])+fabs(A[4])+fabs(A[8]) + 1e-300;
    for(int sweep=0; sweep<15; sweep++){
        double off = fabs(a[1])+fabs(a[2])+fabs(a[5]);
        if(off <= 1e-14*scale) break;
        for(int p=0;p<2;p++) for(int q=p+1;q<3;q++){
            double apq=a[p*3+q];
            if(fabs(apq) <= 1e-16*scale) continue;
            double app=a[p*3+p], aqq=a[q*3+q];
            double th=(aqq-app)/(2.0*apq);
            double t=(th>=0?1.0:-1.0)/(fabs(th)+sqrt(th*th+1.0));
            double c=1.0/sqrt(t*t+1.0), s=t*c;
            for(int i=0;i<3;i++){ double x=a[i*3+p],y=a[i*3+q]; a[i*3+p]=c*x-s*y; a[i*3+q]=s*x+c*y; }
            for(int i=0;i<3;i++){ double x=a[p*3+i],y=a[q*3+i]; a[p*3+i]=c*x-s*y; a[q*3+i]=s*x+c*y; }
            for(int i=0;i<3;i++){ double x=V[i*3+p],y=V[i*3+q]; V[i*3+p]=c*x-s*y; V[i*3+q]=s*x+c*y; }
        }
    }
    e[0]=a[0]; e[1]=a[4]; e[2]=a[8];
}
static __device__ void inv3(const double* m, double* inv){
    double a=m[0],b=m[1],c=m[2],d=m[3],e=m[4],f=m[5],g=m[6],h=m[7],i=m[8];
    double A=e*i-f*h, B=c*h-b*i, C=b*f-c*e;
    double D=f*g-d*i, E=a*i-c*g, F=c*d-a*f;
    double G=d*h-e*g, Hh=b*g-a*h, I=a*e-b*d;
    double det=a*A+b*D+c*G, id=1.0/det;
    inv[0]=A*id; inv[1]=B*id; inv[2]=C*id;
    inv[3]=D*id; inv[4]=E*id; inv[5]=F*id;
    inv[6]=G*id; inv[7]=Hh*id; inv[8]=I*id;
}

// ======================= cooperative radix select =======================
// jobs: {kind, type, b, rank, slotA, slotB}
__device__ const int g_seljobs[22*6] = {
 0,0,0,73727,0,6,   0,1,0,73727,1,7,   0,2,0,73727,2,8,
 0,0,1,73727,3,9,   0,1,1,73727,4,10,  0,2,1,73727,5,11,
 1,3,0,36863,12,13,  1,3,0,110591,14,15,  1,3,1,36863,16,17,  1,3,1,110591,18,19,
 0,4,0,73727,20,24,  0,5,0,73727,21,25,  0,4,1,73727,22,26,  0,5,1,73727,23,27,
 0,6,0,73727,28,32,  0,7,0,73727,29,33,  0,6,1,73727,30,34,  0,7,1,73727,31,35,
 1,8,0,1474,36,37,  1,8,0,145980,38,39,  1,8,1,1474,40,41,  1,8,1,145980,42,43
};

static __device__ const float* selSrc(int type, int b){
    switch(type){
        case 0: return g_Lp + b*NPIX;
        case 1: return g_E  + b*NPIX;
        case 2: return g_S  + b*NPIX;
        case 3: return g_zb + b*NPIX;
        case 4: return g_lla + (b*2+0)*NPIX;
        case 5: return g_lla + (b*2+1)*NPIX;
        case 6: return g_gld + (b*2+0)*NPIX;
        case 7: return g_gld + (b*2+1)*NPIX;
        default: return g_La + b*NPIX;
    }
}

static __device__ void coopZero(int nbTot){
    int total = 8*6*2048;
    for(int i=blockIdx.x*blockDim.x+threadIdx.x; i<total; i+=nbTot*blockDim.x)
        g_jh[i]=0u;
}

// 3-pass (11/11/10 bit) cooperative select across ncs blocks per job.
static __device__ float coopSel(const float4* __restrict__ src4, float ref, int useAbs, unsigned rank,
                                int jobLocal, int passBase, int chunk, int ncs, int nbTot){
    __shared__ unsigned sh[2048];
    __shared__ unsigned sres[2];
    unsigned pref=0, rk=rank;
    for(int pass=0; pass<3; pass++){
        unsigned* hist = g_jh + (jobLocal*6+passBase+pass)*2048;
        int nbin = (pass==2)?1024:2048;
        for(int i=threadIdx.x;i<nbin;i+=blockDim.x) sh[i]=0u;
        __syncthreads();
        int per = (NPIX/4)/ncs;
        int lo = chunk*per;
        for(int i=lo+threadIdx.x;i<lo+per;i+=blockDim.x){
            float4 v4 = src4[i];
            float vv[4]={v4.x,v4.y,v4.z,v4.w};
            #pragma unroll
            for(int c=0;c<4;c++){
                float v=vv[c]; if(useAbs) v=fabsf(v-ref);
                unsigned key=f2u(v);
                if(pass==0) atomicAdd(&sh[key>>21],1u);
                else if(pass==1){ if((key>>21)==(pref>>21)) atomicAdd(&sh[(key>>10)&2047u],1u); }
                else { if((key>>10)==(pref>>10)) atomicAdd(&sh[key&1023u],1u); }
            }
        }
        __syncthreads();
        for(int i=threadIdx.x;i<nbin;i+=blockDim.x) if(sh[i]) atomicAdd(&hist[i],sh[i]);
        gridBarrier(nbTot);
        if(threadIdx.x<32){
            int lane=threadIdx.x, perl=nbin>>5;
            unsigned s=0;
            for(int i=0;i<perl;i++) s+=hist[lane*perl+i];
            unsigned cum=s;
            #pragma unroll
            for(int o=1;o<32;o<<=1){ unsigned t=__shfl_up_sync(0xffffffffu,cum,o); if(lane>=o) cum+=t; }
            unsigned prev=cum-s;
            if(prev<=rk && rk<cum){
                unsigned rr=rk-prev; int bin=lane*perl;
                for(int i=0;i<perl;i++){ unsigned c=hist[lane*perl+i]; if(rr<c){ bin=lane*perl+i; break;} rr-=c; }
                sres[0]=(pass==0)? ((unsigned)bin<<21) : (pass==1)? (pref|((unsigned)bin<<10)) : (pref|(unsigned)bin);
                sres[1]=rr;
            }
        }
        __syncthreads();
        pref=sres[0]; rk=sres[1];
        __syncthreads();
    }
    return u2f(pref);
}

// ======================= pipeline kernels =======================
// fused Sobel + avg3 + regression accumulation, tiled in shared memory
__global__ void __launch_bounds__(256) kSobelE(const float* __restrict__ lab){
    __shared__ float sL[20][20];
    __shared__ float sP[18][18];
    int b = blockIdx.z;
    int x0 = blockIdx.x*16, y0 = blockIdx.y*16;
    int tid = threadIdx.x;
    int tx = tid & 15, ty = tid >> 4;
    const float* L = lab + (size_t)b*3*NPIX;
    for(int i=tid;i<400;i+=256){
        int jj=i/20, ii=i%20;
        int yy=y0-2+jj, xx=x0-2+ii;
        sL[jj][ii] = (yy>=0&&yy<HH&&xx>=0&&xx<WW) ? L[yy*WW+xx] : 0.f;
    }
    __syncthreads();
    for(int i=tid;i<324;i+=256){
        int jj=i/18, ii=i%18;
        int py=y0-1+jj, px=x0-1+ii;
        float v=0.f;
        if(py>=0&&py<HH&&px>=0&&px<WW){
            float l00=sL[jj][ii],   l01=sL[jj][ii+1],   l02=sL[jj][ii+2];
            float l10=sL[jj+1][ii],                     l12=sL[jj+1][ii+2];
            float l20=sL[jj+2][ii], l21=sL[jj+2][ii+1], l22=sL[jj+2][ii+2];
            float gx = -l00 + l02 - 2.f*l10 + 2.f*l12 - l20 + l22;
            float gy = -l00 - 2.f*l01 - l02 + l20 + 2.f*l21 + l22;
            v = gx*gx + gy*gy;
        }
        sP[jj][ii]=v;
    }
    __syncthreads();
    int y=y0+ty, x=x0+tx;
    int p = y*WW+x, idx = b*NPIX+p;
    float s = sP[ty][tx]  +sP[ty][tx+1]  +sP[ty][tx+2]
            + sP[ty+1][tx]+sP[ty+1][tx+1]+sP[ty+1][tx+2]
            + sP[ty+2][tx]+sP[ty+2][tx+1]+sP[ty+2][tx+2];
    float E = s/9.f;
    float av = L[NPIX+p], bv = L[2*NPIX+p];
    float S = sqrtf(av*av+bv*bv+1e-8f);
    g_E[idx]=E; g_S[idx]=S;
    double e=E, sv=S, l=L[p];
    double r;
    r=blockReduceD(e*e);  if(tid==0) atomicAdd(&g_reg[b][0],r);
    r=blockReduceD(e*sv); if(tid==0) atomicAdd(&g_reg[b][1],r);
    r=blockReduceD(sv*sv);if(tid==0) atomicAdd(&g_reg[b][2],r);
    r=blockReduceD(e*l);  if(tid==0) atomicAdd(&g_reg[b][3],r);
    r=blockReduceD(sv*l); if(tid==0) atomicAdd(&g_reg[b][4],r);
}

// fused: 2x2 solve + L_perp + minmax (prologue), then phase-A med+MAD selects.
// 144 blocks x 1024 = NPIX threads exactly; each thread handles both batches.
__global__ void __launch_bounds__(1024,1) kSelALperp(const float* __restrict__ lab, float* __restrict__ out){
    const int NB = 144;
    __shared__ float sb[4];     // beta0/1 per batch
    if(threadIdx.x<2){
        int b=threadIdx.x;
        double ee=g_reg[b][0]+1e-6, es=g_reg[b][1], ss=g_reg[b][2]+1e-6;
        double el=g_reg[b][3], sl=g_reg[b][4];
        double det = ee*ss - es*es;
        sb[b*2+0] = (float)((ss*el - es*sl)/det);
        sb[b*2+1] = (float)((ee*sl - es*el)/det);
    }
    __syncthreads();
    int gtid = blockIdx.x*1024 + threadIdx.x;      // pixel p, < NPIX
    float v0 = lab[gtid] - sb[0]*g_E[gtid] - sb[1]*g_S[gtid];
    g_Lp[gtid]=v0; out[gtid]=v0;                   // output #1, batch 0
    int idx1 = NPIX + gtid;
    float v1 = lab[(size_t)3*NPIX + gtid] - sb[2]*g_E[idx1] - sb[3]*g_S[idx1];
    g_Lp[idx1]=v1; out[idx1]=v1;                   // output #1, batch 1
    // warp min/max per batch -> global atomics
    unsigned mn0=f2u(v0), mx0=mn0, mn1=f2u(v1), mx1=mn1;
    #pragma unroll
    for(int o=16;o;o>>=1){
        mn0=min(mn0,__shfl_down_sync(0xffffffffu,mn0,o));
        mx0=max(mx0,__shfl_down_sync(0xffffffffu,mx0,o));
        mn1=min(mn1,__shfl_down_sync(0xffffffffu,mn1,o));
        mx1=max(mx1,__shfl_down_sync(0xffffffffu,mx1,o));
    }
    if((threadIdx.x&31)==0){
        atomicMin(&g_mm[0][0],mn0); atomicMax(&g_mm[0][1],mx0);
        atomicMin(&g_mm[1][0],mn1); atomicMax(&g_mm[1][1],mx1);
    }
    coopZero(NB);
    gridBarrier(NB);
    // phase A: med+MAD of Lp,E,S for both batches; 6 jobs x 24 chunks
    int job = blockIdx.x/24, chunk = blockIdx.x%24;
    const int* jb = &g_seljobs[job*6];
    const float4* src = (const float4*)selSrc(jb[1], jb[2]);
    float med = coopSel(src,0.f,0,(unsigned)jb[3],job,0,chunk,24,NB);
    if(chunk==0&&threadIdx.x==0) g_sv[jb[4]]=med;
    float mad = coopSel(src,med,1,(unsigned)jb[3],job,3,chunk,24,NB);
    if(chunk==0&&threadIdx.x==0) g_sv[jb[5]]=mad;
}

// cov-acc + eigh/ESinv/cdir + kurt-acc (thread-per-direction via shared z) + pick
__global__ void __launch_bounds__(256,2) kWhiten(const float* __restrict__ arand){
    const int NBW = 288;
    int blk = blockIdx.x;
    int b = blk/144, chunk = blk%144;
    float md[3], sd[3];
    for(int f=0;f<3;f++){ md[f]=g_sv[b*3+f]; sd[f]=g_sv[6+b*3+f]*1.4826f+1e-8f; }
    int base = b*NPIX + chunk*1024;
    float z0[4], z1[4], z2[4];
    double a[9]={0,0,0,0,0,0,0,0,0};
    #pragma unroll
    for(int i=0;i<4;i++){
        int p = base + i*256 + threadIdx.x;
        float u0=(g_Lp[p]-md[0])/sd[0];
        float u1=(g_E [p]-md[1])/sd[1];
        float u2=(g_S [p]-md[2])/sd[2];
        z0[i]=u0; z1[i]=u1; z2[i]=u2;
        a[0]+=u0; a[1]+=u1; a[2]+=u2;
        a[3]+=(double)u0*u0; a[4]+=(double)u0*u1; a[5]+=(double)u0*u2;
        a[6]+=(double)u1*u1; a[7]+=(double)u1*u2; a[8]+=(double)u2*u2;
    }
    for(int m=0;m<9;m++){ double r=blockReduceD(a[m]); if(threadIdx.x==0) atomicAdd(&g_cacc[b][m],r); }
    gridBarrier(NBW);
    if(blk==0){
        int t = threadIdx.x;
        if(t<BB){
            int bb = t;
            double N = (double)NPIX;
            double mu[3]; for(int i=0;i<3;i++){ mu[i]=vloadd(&g_cacc[bb][i])/N; g_mean3[bb][i]=mu[i]; }
            double C[9];
            C[0]=vloadd(&g_cacc[bb][3])/N-mu[0]*mu[0]; C[1]=vloadd(&g_cacc[bb][4])/N-mu[0]*mu[1]; C[2]=vloadd(&g_cacc[bb][5])/N-mu[0]*mu[2];
            C[4]=vloadd(&g_cacc[bb][6])/N-mu[1]*mu[1]; C[5]=vloadd(&g_cacc[bb][7])/N-mu[1]*mu[2]; C[8]=vloadd(&g_cacc[bb][8])/N-mu[2]*mu[2];
            C[3]=C[1]; C[6]=C[2]; C[7]=C[5];
            {
                double c00=C[4]+1e-6, c01=C[5], c11=C[8]+1e-6;
                double det=c00*c11-c01*c01;
                g_esinv[bb][0]=c11/det; g_esinv[bb][1]=-c01/det; g_esinv[bb][2]=c00/det;
                g_esinv[bb][3]=mu[1]; g_esinv[bb][4]=mu[2];
            }
            for(int i=0;i<9;i++) C[i] = C[i] > 1e-8 ? C[i] : 1e-8;   // elementwise max (matches ref)
            double e[3], V[9];
            eigh3(C, e, V);
            for(int i=0;i<3;i++) for(int j=0;j<3;j++){
                double ssum=0; for(int k2=0;k2<3;k2++) ssum += V[i*3+k2]*(1.0/sqrt(e[k2]))*V[j*3+k2];
                g_wwh[bb][i*3+j]=ssum;
            }
            for(int i=0;i<9;i++) g_cacc[bb][i]=0.0;
        }
        __syncthreads();
        {
            int t2 = threadIdx.x;       // 256 threads = BB*NDIR
            int bb = t2 / NDIR, d = t2 % NDIR;
            float a0=arand[(bb*NDIR+d)*3+0], a1=arand[(bb*NDIR+d)*3+1], a2=arand[(bb*NDIR+d)*3+2];
            float nr = sqrtf(a0*a0+a1*a1+a2*a2) + 1e-12f;
            double an[3]={a0/nr,a1/nr,a2/nr};
            for(int jj=0;jj<3;jj++){
                double ssum=0; for(int i=0;i<3;i++) ssum += g_wwh[bb][jj*3+i]*an[i];
                g_cdir[(bb*NDIR+d)*3+jj]=(float)ssum;
            }
        }
    }
    gridBarrier(NBW);
    // kurt phase: stage z in shared, ONE DIRECTION PER THREAD-PAIR (no shuffle chains)
    __shared__ float scd[NDIR*3];
    __shared__ float sacc[NDIR*4];
    __shared__ float sZ[3][1024];
    for(int i=threadIdx.x;i<NDIR*3;i+=256) scd[i]=vloadf(&g_cdir[b*NDIR*3+i]);
    float mn0=(float)vloadd(&g_mean3[b][0]), mn1=(float)vloadd(&g_mean3[b][1]), mn2=(float)vloadd(&g_mean3[b][2]);
    #pragma unroll
    for(int i=0;i<4;i++){
        sZ[0][i*256+threadIdx.x]=z0[i]-mn0;
        sZ[1][i*256+threadIdx.x]=z1[i]-mn1;
        sZ[2][i*256+threadIdx.x]=z2[i]-mn2;
    }
    __syncthreads();
    {
        int d = threadIdx.x>>1, half = threadIdx.x&1;
        float c0=scd[d*3], c1=scd[d*3+1], c2=scd[d*3+2];
        float s1=0,s2=0,s3=0,s4=0;
        int e0 = half*512;
        #pragma unroll 4
        for(int e=0;e<512;e++){
            float z = sZ[0][e0+e]*c0 + sZ[1][e0+e]*c1 + sZ[2][e0+e]*c2;
            float zz=z*z;
            s1+=z; s2+=zz; s3+=zz*z; s4+=zz*zz;
        }
        s1 += __shfl_down_sync(0xffffffffu,s1,1);
        s2 += __shfl_down_sync(0xffffffffu,s2,1);
        s3 += __shfl_down_sync(0xffffffffu,s3,1);
        s4 += __shfl_down_sync(0xffffffffu,s4,1);
        if(half==0){
            sacc[d*4+0]=s1; sacc[d*4+1]=s2; sacc[d*4+2]=s3; sacc[d*4+3]=s4;
        }
    }
    __syncthreads();
    for(int i=threadIdx.x;i<NDIR*4;i+=256)
        atomicAdd(&((double*)g_dirm)[b*NDIR*4+i], (double)sacc[i]);
    gridBarrier(NBW);
    if(blk==0){
        __shared__ double skv[256];
        __shared__ int sdi[256];
        int t = threadIdx.x;
        int bb = t>>7, d = t&127;
        double N=(double)NPIX;
        double m1=vloadd(&g_dirm[bb][d][0])/N, s2=vloadd(&g_dirm[bb][d][1])/N;
        double s3=vloadd(&g_dirm[bb][d][2])/N, s4=vloadd(&g_dirm[bb][d][3])/N;
        double m2=(s2-m1*m1)+1e-12;
        double m4=s4-4.0*m1*s3+6.0*m1*m1*s2-3.0*m1*m1*m1*m1;
        skv[t]=fabs(m4/(m2*m2)-3.0); sdi[t]=d;
        __syncthreads();
        for(int o=64;o;o>>=1){
            if((t&127)<o){
                if(skv[t+o]>skv[t] || (skv[t+o]==skv[t] && sdi[t+o]<sdi[t])){ skv[t]=skv[t+o]; sdi[t]=sdi[t+o]; }
            }
            __syncthreads();
        }
        if((t&127)==0){
            int best=sdi[t];
            for(int j=0;j<3;j++) g_cbest[t>>7][j]=vloadf(&g_cdir[((t>>7)*NDIR+best)*3+j]);
        }
        __syncthreads();
        for(int i=t;i<BB*NDIR*4;i+=256) ((double*)g_dirm)[i]=0.0;
    }
}

// phase Z + EM fused: zb compute, SPLIT bracket selects, 9 EM iters, Ra.
__global__ void __launch_bounds__(1024,1) kPhaseZEM(){
    const int NB = 144;
    int gtid = blockIdx.x*1024 + threadIdx.x;     // < 147456
    #pragma unroll
    for(int h=0;h<2;h++){
        int idx = gtid + h*NPIX;
        int b = h;
        float md0=g_sv[b*3+0], md1=g_sv[b*3+1], md2=g_sv[b*3+2];
        float sd0=g_sv[6+b*3+0]*1.4826f+1e-8f, sd1=g_sv[6+b*3+1]*1.4826f+1e-8f, sd2=g_sv[6+b*3+2]*1.4826f+1e-8f;
        float d0=(g_Lp[idx]-md0)/sd0-(float)g_mean3[b][0];
        float d1=(g_E [idx]-md1)/sd1-(float)g_mean3[b][1];
        float d2=(g_S [idx]-md2)/sd2-(float)g_mean3[b][2];
        g_zb[idx] = d0*g_cbest[b][0]+d1*g_cbest[b][1]+d2*g_cbest[b][2];
    }
    coopZero(NB);
    {
        double* acc = (double*)g_emacc2;
        int tot = 9*BB*6;
        for(int i=blockIdx.x*1024+threadIdx.x; i<tot; i+=NB*1024) acc[i]=0.0;
    }
    gridBarrier(NB);
    // SPLIT quartile-bracket selects: 8 single-select jobs x 18 chunks (3 passes)
    {
        int job = blockIdx.x/18, chunk = blockIdx.x%18;
        int pair = job>>1, which = job&1;
        const int* jb = &g_seljobs[(6+pair)*6];
        const float4* src = (const float4*)selSrc(jb[1], jb[2]);
        float v = coopSel(src,0.f,0,(unsigned)(jb[3]+which),job,0,chunk,18,NB);
        if(chunk==0&&threadIdx.x==0) g_sv[jb[4+which]]=v;
    }
    gridBarrier(NB);
    // EM: blocks 0..71 -> batch0, 72..143 -> batch1; 2 elems per thread (batch-relative)
    int b = blockIdx.x/72, sub = blockIdx.x%72;
    int baseRel = sub*2048 + threadIdx.x;
    float x0 = g_zb[b*NPIX + baseRel], x1 = g_zb[b*NPIX + baseRel + 1024];
    float q25 = vloadf(&g_sv[12+4*b]) + 0.75f*(vloadf(&g_sv[13+4*b])-vloadf(&g_sv[12+4*b]));
    float q75 = vloadf(&g_sv[14+4*b]) + 0.25f*(vloadf(&g_sv[15+4*b])-vloadf(&g_sv[14+4*b]));
    double mu0=q25, mu1=q75, var0=1.0, var1=1.0, pi0=0.5, pi1=0.5;
    for(int it=0; it<9; it++){
        float m0=(float)mu0, m1=(float)mu1;
        float v0=(float)var0+1e-6f, v1=(float)var1+1e-6f;
        float lw0=-0.5f*logf(v0)+logf((float)pi0+1e-8f);
        float lw1=-0.5f*logf(v1)+logf((float)pi1+1e-8f);
        float iv0=0.5f/v0, iv1=0.5f/v1;
        float a0=0,a1=0,a2=0,a3=0,a4=0,a5=0;
        #pragma unroll
        for(int i=0;i<2;i++){
            float xx = (i==0)?x0:x1;
            float lp0=-(xx-m0)*(xx-m0)*iv0+lw0;
            float lp1=-(xx-m1)*(xx-m1)*iv1+lw1;
            float R0=1.f/(1.f+expf(lp1-lp0));
            float R1=1.f/(1.f+expf(lp0-lp1));
            a0+=R0; a1+=R0*xx; a2+=R0*xx*xx;
            a3+=R1; a4+=R1*xx; a5+=R1*xx*xx;
        }
        double s[6]={a0,a1,a2,a3,a4,a5};
        for(int m=0;m<6;m++){
            double r=blockReduceD(s[m]);
            if(threadIdx.x==0) atomicAdd(&g_emacc2[it][b][m],r);
        }
        gridBarrier(NB);
        {
            double Sr0=vloadd(&g_emacc2[it][b][0]), Sx0=vloadd(&g_emacc2[it][b][1]), Sxx0=vloadd(&g_emacc2[it][b][2]);
            double Sr1=vloadd(&g_emacc2[it][b][3]), Sx1=vloadd(&g_emacc2[it][b][4]), Sxx1=vloadd(&g_emacc2[it][b][5]);
            double den0=Sr0+1e-8; mu0=Sx0/den0;
            var0=(Sxx0-2.0*mu0*Sx0+mu0*mu0*Sr0)/den0+1e-6; pi0=Sr0/(double)NPIX;
            double den1=Sr1+1e-8; mu1=Sx1/den1;
            var1=(Sxx1-2.0*mu1*Sx1+mu1*mu1*Sr1)/den1+1e-6; pi1=Sr1/(double)NPIX;
        }
    }
    {
        float m0=(float)mu0, m1=(float)mu1;
        float v0=(float)var0+1e-6f, v1=(float)var1+1e-6f;
        float lw0=-0.5f*logf(v0)+logf((float)pi0+1e-8f);
        float lw1=-0.5f*logf(v1)+logf((float)pi1+1e-8f);
        float iv0=0.5f/v0, iv1=0.5f/v1;
        #pragma unroll
        for(int i=0;i<2;i++){
            float xx = (i==0)?x0:x1;
            int p = baseRel + i*1024;
            float lp0=-(xx-m0)*(xx-m0)*iv0+lw0;
            float lp1=-(xx-m1)*(xx-m1)*iv1+lw1;
            float R0=1.f/(1.f+expf(lp1-lp0));
            float R1=1.f/(1.f+expf(lp0-lp1));
            float r0=powf(R0,0.9f), r1=powf(R1,0.9f);
            float ssum=r0+r1+1e-8f;
            g_Ra[(b*2+0)*NPIX+p]=r0/ssum;
            g_Ra[(b*2+1)*NPIX+p]=r1/ssum;
        }
    }
}

// cluster moments + binidx + ghist -> inverses+gcdf -> DM + boxH(shared rows) -> boxV(sliding)
// R13: widened 128 -> 256 blocks, launch_bounds(256,2)
__global__ void __launch_bounds__(256,2) kClusterDM(){
    const int NBC = 256;
    int blk = blockIdx.x;
    int b = blk>>7, chunk = blk&127;
    __shared__ float sh64[64];
    if(threadIdx.x<64) sh64[threadIdx.x]=0.f;
    __syncthreads();
    float mn = u2f(g_mm[b][0]), mx = u2f(g_mm[b][1]);
    float inv_rng = 1.f/(mx-mn+1e-8f);
    double a[20];
    for(int i=0;i<20;i++) a[i]=0.0;
    int lo = chunk*1152, hi = lo+1152;
    for(int p=lo+threadIdx.x;p<hi;p+=256){
        float w0=g_Ra[(b*2+0)*NPIX+p], w1=g_Ra[(b*2+1)*NPIX+p];
        float lpv=g_Lp[b*NPIX+p];
        double x0=lpv, x1=g_E[b*NPIX+p], x2=g_S[b*NPIX+p];
        a[0]+=w0; a[1]+=w0*x0; a[2]+=w0*x1; a[3]+=w0*x2;
        a[4]+=w0*x0*x0; a[5]+=w0*x0*x1; a[6]+=w0*x0*x2;
        a[7]+=w0*x1*x1; a[8]+=w0*x1*x2; a[9]+=w0*x2*x2;
        a[10]+=w1; a[11]+=w1*x0; a[12]+=w1*x1; a[13]+=w1*x2;
        a[14]+=w1*x0*x0; a[15]+=w1*x0*x1; a[16]+=w1*x0*x2;
        a[17]+=w1*x1*x1; a[18]+=w1*x1*x2; a[19]+=w1*x2*x2;
        float ln = (lpv-mn)*inv_rng;
        ln = fminf(fmaxf(ln,0.f),1.f);
        int c = (int)(ln*32.f); c = c<0?0:(c>31?31:c);
        g_idxb[b*NPIX+p] = (unsigned char)c;
        atomicAdd(&sh64[c],    w0);
        atomicAdd(&sh64[32+c], w1);
    }
    for(int m=0;m<20;m++){
        double r=blockReduceD(a[m]);
        if(threadIdx.x==0) atomicAdd(&g_clacc[b][m/10][m%10],r);
    }
    __syncthreads();
    if(threadIdx.x<64 && sh64[threadIdx.x]!=0.f)
        atomicAdd(&g_ghist[b][threadIdx.x>>5][threadIdx.x&31],(double)sh64[threadIdx.x]);
    gridBarrier(NBC);
    if(blk==0 && threadIdx.x<4){
        int t = threadIdx.x;
        int bb=t>>1, k=t&1;
        double A[10];
        for(int i=0;i<10;i++) A[i]=vloadd(&g_clacc[bb][k][i]);
        double Ws = A[0] + 1e-8;
        double mu[3] = {A[1]/Ws, A[2]/Ws, A[3]/Ws};
        double Sx[3] = {A[1], A[2], A[3]};
        double Sxx[9] = {A[4],A[5],A[6], A[5],A[7],A[8], A[6],A[8],A[9]};
        double C[9];
        for(int i=0;i<3;i++) for(int j2=0;j2<3;j2++)
            C[i*3+j2] = (Sxx[i*3+j2] - mu[i]*Sx[j2] - mu[j2]*Sx[i] + A[0]*mu[i]*mu[j2])/Ws + ((i==j2)?1e-6:0.0);
        double I[9]; inv3(C, I);
        for(int i=0;i<9;i++) g_clinv[bb][k][i]=I[i];
        for(int i=0;i<3;i++) g_clmu[bb][k][i]=mu[i];
        for(int i=0;i<10;i++) g_clacc[bb][k][i]=0.0;
        double tot=0; for(int c=0;c<32;c++) tot += vloadd(&g_ghist[bb][k][c]);
        double cum=0;
        for(int c=0;c<32;c++){ cum += vloadd(&g_ghist[bb][k][c])/(tot+1e-8); g_gcdf[bb][k][c]=(float)cum; g_ghist[bb][k][c]=0.0; }
        if(k==0){ g_mm[bb][0]=0xFFFFFFFFu; g_mm[bb][1]=0u; }
    }
    gridBarrier(NBC);
    // DM: strided over BN
    for(int idx=blk*256+threadIdx.x; idx<BN; idx+=NBC*256){
        int bb = idx/NPIX, p = idx%NPIX;
        float X0=g_Lp[idx], X1=g_E[idx], X2=g_S[idx];
        float ra0=g_Ra[(bb*2+0)*NPIX+p], ra1=g_Ra[(bb*2+1)*NPIX+p];
        float ssum = ra0+ra1+2e-8f;
        float DM=0.f;
        for(int kk=0;kk<2;kk++){
            float xm0=X0-(float)vloadd(&g_clmu[bb][kk][0]);
            float xm1=X1-(float)vloadd(&g_clmu[bb][kk][1]);
            float xm2=X2-(float)vloadd(&g_clmu[bb][kk][2]);
            float i0=(float)vloadd(&g_clinv[bb][kk][0]), i1=(float)vloadd(&g_clinv[bb][kk][1]);
            float i2=(float)vloadd(&g_clinv[bb][kk][2]), i4=(float)vloadd(&g_clinv[bb][kk][4]);
            float i5=(float)vloadd(&g_clinv[bb][kk][5]), i8=(float)vloadd(&g_clinv[bb][kk][8]);
            float q = xm0*xm0*i0 + xm1*xm1*i4 + xm2*xm2*i8
                    + 2.f*xm0*xm1*i1 + 2.f*xm0*xm2*i2 + 2.f*xm1*xm2*i5;
            float Dk = sqrtf(q + 1e-8f);
            float Rt = ((kk==0?ra0:ra1)+1e-8f)/ssum;
            DM += Rt*Dk;
        }
        g_DM[idx]=DM;
    }
    // boxH via shared rows: 1536 row jobs, 6 per block
    __shared__ float rowR[WW], rowL[WW];
    for(int j=blk; j<4*HH; j+=NBC){
        int bk = j/HH, y = j%HH;
        int bb = bk>>1;
        for(int i=threadIdx.x;i<WW;i+=256){
            rowR[i]=g_Ra[bk*NPIX + y*WW + i];
            rowL[i]=g_Lp[bb*NPIX + y*WW + i];
        }
        __syncthreads();
        for(int x=threadIdx.x;x<WW;x+=256){
            float s0=0.f,s1=0.f,s2=0.f;
            int lo2=max(x-7,0), hi2=min(x+7,WW-1);
            for(int xx=lo2;xx<=hi2;xx++){
                float r=rowR[xx], l=rowL[xx];
                s0+=r; s1+=r*l; s2+=r*l*l;
            }
            int p=y*WW+x;
            g_t0[bk*NPIX+p]=s0; g_t1[bk*NPIX+p]=s1; g_t2[bk*NPIX+p]=s2;
        }
        __syncthreads();
    }
    gridBarrier(NBC);
    // boxV: register-sliding per (plane-col, 24-row segment); 24576 active threads
    int tseg = blk*256 + threadIdx.x;
    if(tseg < 1536*16){
        int seg = tseg/1536, col = tseg%1536;
        int bk = col/WW, x = col%WW;
        int bb = bk>>1;
        int y0 = seg*GTY;
        float s0=0.f,s1=0.f,s2=0.f;
        for(int r=y0-7;r<=y0+6;r++){
            if(r<0||r>=HH) continue;
            int q=r*WW+x;
            s0+=g_t0[bk*NPIX+q]; s1+=g_t1[bk*NPIX+q]; s2+=g_t2[bk*NPIX+q];
        }
        for(int y=y0;y<y0+GTY;y++){
            int ra=y+7;
            if(ra<HH){ int q=ra*WW+x; s0+=g_t0[bk*NPIX+q]; s1+=g_t1[bk*NPIX+q]; s2+=g_t2[bk*NPIX+q]; }
            float cy = (float)(min(y+8,HH)-max(y-7,0));
            float cx = (float)(min(x+8,WW)-max(x-7,0));
            float c = cy*cx;
            float a0=s0/c, a1=s1/c, a2=s2/c;
            float den = a0 + 1e-8f;
            float mu = a1/den;
            float vb = fmaxf(a2/den - mu*mu, 1e-8f);
            int p=y*WW+x;
            g_lla[bk*NPIX+p] = fabsf(g_Lp[bb*NPIX+p]-mu)/(sqrtf(vb)+1e-8f);
            g_den[bk*NPIX+p] = a0;
            int rs=y-7;
            if(rs>=0){ int q=rs*WW+x; s0-=g_t0[bk*NPIX+q]; s1-=g_t1[bk*NPIX+q]; s2-=g_t2[bk*NPIX+q]; }
        }
    }
}

// fused GLD: tiled column histograms in shared (bin-prefix form)
__global__ void __launch_bounds__(128,8) kGLDTile(){
    int bk = blockIdx.z; int b=bk>>1, k=bk&1;
    int strip = blockIdx.x;            // 8 strips of 48 cols
    int y0 = blockIdx.y*GTY;           // 16 segs of 24 rows
    int warp = threadIdx.x>>5, lane = threadIdx.x&31;
    __shared__ float ch[62][32];
    const float* rk = g_Ra + bk*NPIX;
    const unsigned char* bi = g_idxb + b*NPIX;
    int xbase = strip*48 - 7;
    for(int i=threadIdx.x;i<62*32;i+=128) ((float*)ch)[i]=0.f;
    __syncthreads();
    for(int c=warp;c<62;c+=4){
        int x = xbase+c;
        if(x<0||x>=WW) continue;
        float P=0.f;
        for(int r=y0-7;r<=y0+6;r++){
            if(r<0||r>=HH) continue;
            float v=rk[r*WW+x]; int bn=bi[r*WW+x];
            if(lane>=bn) P+=v;
        }
        ch[c][lane]=P;
    }
    float gc = g_gcdf[b][k][lane];
    __syncthreads();
    for(int y=y0;y<y0+GTY;y++){
        int ra=y+7;
        if(ra<HH){
            for(int c=warp;c<62;c+=4){
                int x=xbase+c; if(x<0||x>=WW) continue;
                float v=rk[ra*WW+x]; int bn=bi[ra*WW+x];
                if(lane>=bn) ch[c][lane]+=v;
            }
        }
        __syncthreads();
        {
            int xo0 = warp*12;
            float S=0.f;
            #pragma unroll
            for(int c=0;c<14;c++) S += ch[xo0+c][lane];
            float cy = (float)(min(y+8,HH)-max(y-7,0));
            for(int j=0;j<12;j++){
                int xo = xo0+j;
                S += ch[xo+14][lane];
                int x = strip*48 + xo;
                float cx = (float)(min(x+8,WW)-max(x-7,0));
                float den = g_den[bk*NPIX + y*WW+x] + 1e-8f;
                float diff = fabsf(S/(cy*cx)/den - gc);
                for(int o=16;o;o>>=1) diff += __shfl_down_sync(0xffffffffu,diff,o);
                if(lane==0) g_gld[bk*NPIX + y*WW+x] = diff*(1.f/32.f);
                S -= ch[xo][lane];
            }
        }
        __syncthreads();
        int rs=y-7;
        if(rs>=0){
            for(int c=warp;c<62;c+=4){
                int x=xbase+c; if(x<0||x>=WW) continue;
                float v=rk[rs*WW+x]; int bn=bi[rs*WW+x];
                if(lane>=bn) ch[c][lane]-=v;
            }
        }
        __syncthreads();
    }
}

// LLA/GLD selects + gamma/La + SPLIT La quantile selects + normalize + resets : 144 x 1024
__global__ void __launch_bounds__(1024,1) kFinalPhase(float* __restrict__ out){
    const int NB = 144;
    coopZero(NB);
    gridBarrier(NB);
    {   // 8 med+MAD jobs x 18 chunks
        int job = blockIdx.x/18, chunk = blockIdx.x%18;
        const int* jb = &g_seljobs[(10+job)*6];
        const float4* src = (const float4*)selSrc(jb[1], jb[2]);
        float med = coopSel(src,0.f,0,(unsigned)jb[3],job,0,chunk,18,NB);
        if(chunk==0&&threadIdx.x==0) g_sv[jb[4]]=med;
        float mad = coopSel(src,med,1,(unsigned)jb[3],job,3,chunk,18,NB);
        if(chunk==0&&threadIdx.x==0) g_sv[jb[5]]=mad;
    }
    gridBarrier(NB);
    int gtid = blockIdx.x*1024 + threadIdx.x;
    #pragma unroll
    for(int h=0;h<2;h++){
        int idx = gtid + h*NPIX;
        int b = h, p = gtid;
        float gamma = 1.f;
        for(int k=0;k<2;k++){
            int s = b*2+k;
            float zl = (g_lla[s*NPIX+p]-vloadf(&g_sv[20+s]))/(vloadf(&g_sv[24+s])*1.4826f+1e-8f);
            float zg = (g_gld[s*NPIX+p]-vloadf(&g_sv[28+s]))/(vloadf(&g_sv[32+s])*1.4826f+1e-8f);
            gamma += g_Ra[s*NPIX+p]*(0.5f*softplusf(zl)+0.5f*softplusf(zg));
        }
        float mdE=g_sv[b*3+1], mdS=g_sv[b*3+2];
        float sdE=g_sv[6+b*3+1]*1.4826f+1e-8f, sdS=g_sv[6+b*3+2]*1.4826f+1e-8f;
        float dE=(g_E[idx]-mdE)/sdE-(float)g_esinv[b][3];
        float dS=(g_S[idx]-mdS)/sdS-(float)g_esinv[b][4];
        float d2 = dE*dE*(float)g_esinv[b][0] + 2.f*dE*dS*(float)g_esinv[b][1] + dS*dS*(float)g_esinv[b][2];
        float Rs = expf(-0.5f*d2);
        g_La[idx] = fmaxf(g_DM[idx]*gamma*(1.f-Rs), 0.f);
    }
    coopZero(NB);
    gridBarrier(NB);
    {   // SPLIT La 1%/99% bracket selects: 8 single-select jobs x 18 chunks
        int job = blockIdx.x/18, chunk = blockIdx.x%18;
        int pair = job>>1, which = job&1;
        const int* jb = &g_seljobs[(18+pair)*6];
        const float4* src = (const float4*)selSrc(jb[1], jb[2]);
        float v = coopSel(src,0.f,0,(unsigned)(jb[3]+which),job,0,chunk,18,NB);
        if(chunk==0&&threadIdx.x==0) g_sv[jb[4+which]]=v;
    }
    gridBarrier(NB);
    #pragma unroll
    for(int h=0;h<2;h++){
        int idx = gtid + h*NPIX;
        int b = h;
        float q1 = vloadf(&g_sv[36+4*b]) + 0.55f*(vloadf(&g_sv[37+4*b])-vloadf(&g_sv[36+4*b]));
        float q9 = vloadf(&g_sv[38+4*b]) + 0.45f*(vloadf(&g_sv[39+4*b])-vloadf(&g_sv[38+4*b]));
        float v = (g_La[idx]-q1)/(q9-q1+1e-8f);
        out[BN + idx] = fminf(fmaxf(v,0.f),1.f);   // output #2
    }
    // resets for next replay
    if(blockIdx.x==0 && threadIdx.x<10) ((double*)g_reg)[threadIdx.x]=0.0;
}

// ======================= host =======================
extern "C" void kernel_launch(void* const* d_in, const int* in_sizes, int n_in,
                              void* d_out, int out_size){
    const float* lab   = (const float*)d_in[0];
    const float* arand = (const float*)d_in[1];
    float* out = (float*)d_out;

    kSobelE<<<dim3(24,24,BB),256>>>(lab);
    kSelALperp<<<144,1024>>>(lab,out);
    kWhiten<<<288,256>>>(arand);
    kPhaseZEM<<<144,1024>>>();
    kClusterDM<<<256,256>>>();
    kGLDTile<<<dim3(8,16,4),128>>>();
    kFinalPhase<<<144,1024>>>(out);
}